// round 8
// baseline (speedup 1.0000x reference)
#include <cuda_runtime.h>
#include <cuda_bf16.h>
#include <cstdint>
#include <math.h>

// Problem constants (fixed by the dataset)
#define NS 100000
#define NE 100000
#define EDG 1600000
#define D 256
#define H 8
#define HD 32
#define FEAT 64
#define DFF 512

#define SCAN_B 1024
#define NBLK ((NS + SCAN_B - 1) / SCAN_B)   // 98
#define KPAD 40                              // bf16 elems per smem row (80B, 16B-aligned)

// ---------------- device scratch (no allocations allowed) ----------------
__device__ float g_z[(size_t)NE * D];
__device__ float g_df[(size_t)NS * D];
__device__ float g_h[(size_t)NS * D];
__device__ float g_x[(size_t)NS * D];
__device__ float g_xn[(size_t)NS * D];
__device__ float g_t[(size_t)NS * DFF];
__device__ float g_Wz[D * D];
__device__ float g_Wd[FEAT * D];
__device__ int   g_counts[NS];
__device__ int   g_offsets[NS + 1];
__device__ int   g_cursor[NS];
__device__ int   g_csr_src[EDG];
__device__ int   g_bsum[NBLK];

// ---------------- small helpers ----------------
__device__ __forceinline__ float gelu_fast(float x) {
    const float c = 0.7978845608028654f;
    float u = c * (x + 0.044715f * x * x * x);
    float e = __expf(2.0f * u);
    float th = 1.0f - 2.0f / (e + 1.0f);
    return 0.5f * x * (1.0f + th);
}

__device__ __forceinline__ uint32_t smem_u32(const void* p) {
    uint32_t a;
    asm("{ .reg .u64 t; cvta.to.shared.u64 t, %1; cvt.u32.u64 %0, t; }" : "=r"(a) : "l"(p));
    return a;
}

__device__ __forceinline__ void ldm_x4(uint32_t* r, uint32_t addr) {
    asm volatile("ldmatrix.sync.aligned.m8n8.x4.shared.b16 {%0,%1,%2,%3}, [%4];"
                 : "=r"(r[0]), "=r"(r[1]), "=r"(r[2]), "=r"(r[3]) : "r"(addr));
}

__device__ __forceinline__ void mma_bf16(float* c, const uint32_t* a, const uint32_t* b) {
    asm volatile(
        "mma.sync.aligned.m16n8k16.row.col.f32.bf16.bf16.f32 "
        "{%0,%1,%2,%3}, {%4,%5,%6,%7}, {%8,%9}, {%0,%1,%2,%3};"
        : "+f"(c[0]), "+f"(c[1]), "+f"(c[2]), "+f"(c[3])
        : "r"(a[0]), "r"(a[1]), "r"(a[2]), "r"(a[3]), "r"(b[0]), "r"(b[1]));
}

__device__ __forceinline__ void split_bf16(float x, __nv_bfloat16& hi, __nv_bfloat16& lo) {
    hi = __float2bfloat16_rn(x);
    lo = __float2bfloat16_rn(x - __bfloat162float(hi));
}

// ---------------- weight repack: (H, K, HD) -> [K, H*HD] ----------------
__global__ void repack_w(const float* __restrict__ w, float* __restrict__ out, int K) {
    int idx = blockIdx.x * blockDim.x + threadIdx.x;
    if (idx >= K * 256) return;
    int k = idx >> 8;
    int n = idx & 255;
    out[idx] = w[(n >> 5) * (K * 32) + k * 32 + (n & 31)];
}

// ================= tensor-core GEMM via mma.sync (bf16 3-product split) =================
// C[M, ldc] (tile 128x128/CTA) = act(A @ B + bias) + res.
// Fragments loaded ONCE per k16 step and reused across the 3 passes
// (Ah*Bh, Al*Bh, then Bl overwrites Bh regs for Ah*Bl) — cuts ldmatrix traffic 33%.
template <int ACT, bool BIAS, bool RES>
__global__ void __launch_bounds__(256, 2) mma_gemm(
    const float* __restrict__ A0, int lda0,
    const float* __restrict__ A1, int lda1, int ksplit,
    const float* __restrict__ B, int ldb,
    const float* __restrict__ bias,
    const float* __restrict__ res, int ldr,
    float* __restrict__ C, int ldc,
    int M, int K)
{
    __shared__ __nv_bfloat16 Ah[128 * KPAD];
    __shared__ __nv_bfloat16 Al[128 * KPAD];
    __shared__ __nv_bfloat16 Bh[128 * KPAD];
    __shared__ __nv_bfloat16 Bl[128 * KPAD];

    int t = threadIdx.x;
    int lane = t & 31, wid = t >> 5;
    int m0 = blockIdx.y * 128;
    int n0 = blockIdx.x * 128;
    int wm = wid & 3;    // 4 M-groups of 32 rows
    int wn = wid >> 2;   // 2 N-groups of 64 cols

    float acc[2][8][4];
#pragma unroll
    for (int i = 0; i < 2; i++)
#pragma unroll
        for (int j = 0; j < 8; j++)
#pragma unroll
            for (int q = 0; q < 4; q++) acc[i][j][q] = 0.0f;

    uint32_t sAh = smem_u32(Ah), sAl = smem_u32(Al);
    uint32_t sBh = smem_u32(Bh), sBl = smem_u32(Bl);

    // lane-fixed fragment offsets (bytes), k16-step adds ks*32
    uint32_t a_off = (uint32_t)(((wm * 32 + (lane & 15)) * KPAD + (lane >> 4) * 8) * 2);
    uint32_t b_off = (uint32_t)(((wn * 64 + (lane & 7) + (lane >> 4) * 8) * KPAD
                                 + ((lane >> 3) & 1) * 8) * 2);

    // A-load mapping: 2 threads per row, 16 k each
    int a_row = t >> 1;
    int a_kb  = (t & 1) * 16;
    bool a_ok = (m0 + a_row) < M;

    for (int k0 = 0; k0 < K; k0 += 32) {
        __syncthreads();
        // ---- A tile [128 m x 32 k] -> bf16 hi/lo ----
        {
            const float* Asrc; int lda, koff;
            if (k0 < ksplit) { Asrc = A0; lda = lda0; koff = k0; }
            else             { Asrc = A1; lda = lda1; koff = k0 - ksplit; }
            const float* ap = Asrc + (size_t)(m0 + a_row) * lda + koff + a_kb;
            int base = a_row * KPAD + a_kb;
#pragma unroll
            for (int i = 0; i < 4; i++) {
                float4 v = a_ok ? *(const float4*)(ap + i * 4)
                                : make_float4(0.f, 0.f, 0.f, 0.f);
                __nv_bfloat16 h, l;
                split_bf16(v.x, h, l); Ah[base + i*4 + 0] = h; Al[base + i*4 + 0] = l;
                split_bf16(v.y, h, l); Ah[base + i*4 + 1] = h; Al[base + i*4 + 1] = l;
                split_bf16(v.z, h, l); Ah[base + i*4 + 2] = h; Al[base + i*4 + 2] = l;
                split_bf16(v.w, h, l); Ah[base + i*4 + 3] = h; Al[base + i*4 + 3] = l;
            }
        }
        // ---- B tile: Bs[n][k] <- B[k0+k][n0+n], coalesced over n ----
        {
            int n = t & 127;
            int kk0 = t >> 7;  // 0 or 1
#pragma unroll
            for (int it = 0; it < 16; it++) {
                int k = kk0 + it * 2;
                float v = B[(size_t)(k0 + k) * ldb + n0 + n];
                __nv_bfloat16 h, l;
                split_bf16(v, h, l);
                Bh[n * KPAD + k] = h;
                Bl[n * KPAD + k] = l;
            }
        }
        __syncthreads();

        // ---- fragments loaded once; 3 passes reuse them ----
#pragma unroll
        for (int ks = 0; ks < 2; ks++) {
            uint32_t koffb = (uint32_t)(ks * 32);
            uint32_t a_hi[2][4], a_lo[2][4], b[4][4];
            ldm_x4(a_hi[0], sAh + a_off + koffb);
            ldm_x4(a_hi[1], sAh + a_off + koffb + 16 * KPAD * 2);
            ldm_x4(a_lo[0], sAl + a_off + koffb);
            ldm_x4(a_lo[1], sAl + a_off + koffb + 16 * KPAD * 2);
#pragma unroll
            for (int ni2 = 0; ni2 < 4; ni2++)
                ldm_x4(b[ni2], sBh + b_off + koffb + ni2 * 16 * KPAD * 2);

            // pass 1: Ah * Bh
#pragma unroll
            for (int mi = 0; mi < 2; mi++)
#pragma unroll
                for (int ni = 0; ni < 8; ni++)
                    mma_bf16(acc[mi][ni], a_hi[mi], &b[ni >> 1][(ni & 1) * 2]);
            // pass 2: Al * Bh
#pragma unroll
            for (int mi = 0; mi < 2; mi++)
#pragma unroll
                for (int ni = 0; ni < 8; ni++)
                    mma_bf16(acc[mi][ni], a_lo[mi], &b[ni >> 1][(ni & 1) * 2]);
            // reload b regs with Bl, pass 3: Ah * Bl
#pragma unroll
            for (int ni2 = 0; ni2 < 4; ni2++)
                ldm_x4(b[ni2], sBl + b_off + koffb + ni2 * 16 * KPAD * 2);
#pragma unroll
            for (int mi = 0; mi < 2; mi++)
#pragma unroll
                for (int ni = 0; ni < 8; ni++)
                    mma_bf16(acc[mi][ni], a_hi[mi], &b[ni >> 1][(ni & 1) * 2]);
        }
    }

    // ---- epilogue ----
#pragma unroll
    for (int mi = 0; mi < 2; mi++) {
#pragma unroll
        for (int ni = 0; ni < 8; ni++) {
            int cc = n0 + wn * 64 + ni * 8 + (lane & 3) * 2;
#pragma unroll
            for (int hh = 0; hh < 2; hh++) {
                int m = m0 + wm * 32 + mi * 16 + (lane >> 2) + hh * 8;
                if (m >= M) continue;
                float v0 = acc[mi][ni][hh * 2 + 0];
                float v1 = acc[mi][ni][hh * 2 + 1];
                if (BIAS) { v0 += bias[cc]; v1 += bias[cc + 1]; }
                if (ACT == 1) { v0 = gelu_fast(v0); v1 = gelu_fast(v1); }
                if (RES) {
                    const float* rp = res + (size_t)m * ldr + cc;
                    v0 += rp[0]; v1 += rp[1];
                }
                *(float2*)(C + (size_t)m * ldc + cc) = make_float2(v0, v1);
            }
        }
    }
}

// ---------------- CSR build ----------------
__global__ void zero_counts() {
    int i = blockIdx.x * blockDim.x + threadIdx.x;
    if (i < NS) g_counts[i] = 0;
}
__global__ void hist_kernel(const int* __restrict__ edge_dst) {
    int i = blockIdx.x * blockDim.x + threadIdx.x;
    if (i < EDG) atomicAdd(&g_counts[edge_dst[i]], 1);
}
__global__ void __launch_bounds__(SCAN_B) scan_pass1() {
    __shared__ int ws[32];
    int b = blockIdx.x, t = threadIdx.x;
    int i = b * SCAN_B + t;
    int v = (i < NS) ? g_counts[i] : 0;
#pragma unroll
    for (int o = 16; o; o >>= 1) v += __shfl_xor_sync(0xFFFFFFFFu, v, o);
    if ((t & 31) == 0) ws[t >> 5] = v;
    __syncthreads();
    if (t < 32) {
        int x = ws[t];
#pragma unroll
        for (int o = 16; o; o >>= 1) x += __shfl_xor_sync(0xFFFFFFFFu, x, o);
        if (t == 0) g_bsum[b] = x;
    }
}
__global__ void scan_pass2() {
    __shared__ int sh[128];
    int t = threadIdx.x;
    int orig = (t < NBLK) ? g_bsum[t] : 0;
    sh[t] = orig;
    __syncthreads();
    for (int o = 1; o < 128; o <<= 1) {
        int v = (t >= o) ? sh[t - o] : 0;
        __syncthreads();
        sh[t] += v;
        __syncthreads();
    }
    if (t < NBLK) g_bsum[t] = sh[t] - orig;
}
__global__ void __launch_bounds__(SCAN_B) scan_pass3() {
    __shared__ int ws[32];
    int b = blockIdx.x, t = threadIdx.x;
    int lane = t & 31, w = t >> 5;
    int i = b * SCAN_B + t;
    int v = (i < NS) ? g_counts[i] : 0;
    int x = v;
#pragma unroll
    for (int o = 1; o < 32; o <<= 1) {
        int y = __shfl_up_sync(0xFFFFFFFFu, x, o);
        if (lane >= o) x += y;
    }
    if (lane == 31) ws[w] = x;
    __syncthreads();
    if (w == 0) {
        int sv = ws[lane];
#pragma unroll
        for (int o = 1; o < 32; o <<= 1) {
            int y = __shfl_up_sync(0xFFFFFFFFu, sv, o);
            if (lane >= o) sv += y;
        }
        ws[lane] = sv;
    }
    __syncthreads();
    int incl = x + (w > 0 ? ws[w - 1] : 0) + g_bsum[b];
    if (i < NS) {
        g_offsets[i + 1] = incl;
        g_cursor[i] = incl - v;
    }
    if (b == 0 && t == 0) g_offsets[0] = 0;
}
__global__ void scatter_kernel(const int* __restrict__ edge_src,
                               const int* __restrict__ edge_dst) {
    int i = blockIdx.x * blockDim.x + threadIdx.x;
    if (i >= EDG) return;
    int dst = edge_dst[i];
    int pos = atomicAdd(&g_cursor[dst], 1);
    g_csr_src[pos] = edge_src[i];
}

// ---------------- attention: warp per dst, lane = (head, quarter) (R4 winner) ----------------
__global__ void __launch_bounds__(256) attn_kernel() {
    int gw = (blockIdx.x * blockDim.x + threadIdx.x) >> 5;
    if (gw >= NS) return;
    int lane = threadIdx.x & 31;
    int off = (lane >> 2) * 32 + (lane & 3) * 8;

    int beg = g_offsets[gw];
    int end = g_offsets[gw + 1];

    const float* dfp = g_df + (size_t)gw * 256 + off;
    float4 d0 = *(const float4*)(dfp);
    float4 d1 = *(const float4*)(dfp + 4);

    float m = -1e30f, den = 0.0f;
    float4 a0 = make_float4(0.f, 0.f, 0.f, 0.f);
    float4 a1 = make_float4(0.f, 0.f, 0.f, 0.f);

    int e = beg;
    for (; e + 2 <= end; e += 2) {
        int s0 = __ldg(&g_csr_src[e]);
        int s1 = __ldg(&g_csr_src[e + 1]);
        const float* zp0 = g_z + (size_t)s0 * 256 + off;
        const float* zp1 = g_z + (size_t)s1 * 256 + off;
        float4 x0 = __ldg((const float4*)zp0);
        float4 x1 = __ldg((const float4*)(zp0 + 4));
        float4 y0 = __ldg((const float4*)zp1);
        float4 y1 = __ldg((const float4*)(zp1 + 4));

        float sa = x0.x * d0.x + x0.y * d0.y + x0.z * d0.z + x0.w * d0.w
                 + x1.x * d1.x + x1.y * d1.y + x1.z * d1.z + x1.w * d1.w;
        float sb = y0.x * d0.x + y0.y * d0.y + y0.z * d0.z + y0.w * d0.w
                 + y1.x * d1.x + y1.y * d1.y + y1.z * d1.z + y1.w * d1.w;
        sa += __shfl_xor_sync(0xFFFFFFFFu, sa, 1);
        sb += __shfl_xor_sync(0xFFFFFFFFu, sb, 1);
        sa += __shfl_xor_sync(0xFFFFFFFFu, sa, 2);
        sb += __shfl_xor_sync(0xFFFFFFFFu, sb, 2);

        {
            float mn = fmaxf(m, sa);
            float sc = __expf(m - mn);
            float w  = __expf(sa - mn);
            den = den * sc + w;
            a0.x = a0.x * sc + w * x0.x; a0.y = a0.y * sc + w * x0.y;
            a0.z = a0.z * sc + w * x0.z; a0.w = a0.w * sc + w * x0.w;
            a1.x = a1.x * sc + w * x1.x; a1.y = a1.y * sc + w * x1.y;
            a1.z = a1.z * sc + w * x1.z; a1.w = a1.w * sc + w * x1.w;
            m = mn;
        }
        {
            float mn = fmaxf(m, sb);
            float sc = __expf(m - mn);
            float w  = __expf(sb - mn);
            den = den * sc + w;
            a0.x = a0.x * sc + w * y0.x; a0.y = a0.y * sc + w * y0.y;
            a0.z = a0.z * sc + w * y0.z; a0.w = a0.w * sc + w * y0.w;
            a1.x = a1.x * sc + w * y1.x; a1.y = a1.y * sc + w * y1.y;
            a1.z = a1.z * sc + w * y1.z; a1.w = a1.w * sc + w * y1.w;
            m = mn;
        }
    }
    for (; e < end; e++) {
        int s0 = __ldg(&g_csr_src[e]);
        const float* zp0 = g_z + (size_t)s0 * 256 + off;
        float4 x0 = __ldg((const float4*)zp0);
        float4 x1 = __ldg((const float4*)(zp0 + 4));
        float sa = x0.x * d0.x + x0.y * d0.y + x0.z * d0.z + x0.w * d0.w
                 + x1.x * d1.x + x1.y * d1.y + x1.z * d1.z + x1.w * d1.w;
        sa += __shfl_xor_sync(0xFFFFFFFFu, sa, 1);
        sa += __shfl_xor_sync(0xFFFFFFFFu, sa, 2);
        float mn = fmaxf(m, sa);
        float sc = __expf(m - mn);
        float w  = __expf(sa - mn);
        den = den * sc + w;
        a0.x = a0.x * sc + w * x0.x; a0.y = a0.y * sc + w * x0.y;
        a0.z = a0.z * sc + w * x0.z; a0.w = a0.w * sc + w * x0.w;
        a1.x = a1.x * sc + w * x1.x; a1.y = a1.y * sc + w * x1.y;
        a1.z = a1.z * sc + w * x1.z; a1.w = a1.w * sc + w * x1.w;
        m = mn;
    }

    float inv = 1.0f / den;
    float v[8];
    v[0] = a0.x * inv; v[1] = a0.y * inv; v[2] = a0.z * inv; v[3] = a0.w * inv;
    v[4] = a1.x * inv; v[5] = a1.y * inv; v[6] = a1.z * inv; v[7] = a1.w * inv;
#pragma unroll
    for (int i = 0; i < 8; i++)
        v[i] = (v[i] > 0.0f) ? v[i] : expm1f(v[i]);  // ELU(alpha=1)

    float* hp = g_h + (size_t)gw * 256 + off;
    *(float4*)(hp)     = make_float4(v[0], v[1], v[2], v[3]);
    *(float4*)(hp + 4) = make_float4(v[4], v[5], v[6], v[7]);
}

// ---------------- layernorm: one warp per row ----------------
__global__ void ln_kernel(const float* __restrict__ x,
                          const float* __restrict__ gam,
                          const float* __restrict__ bet,
                          float* __restrict__ y) {
    int row = (blockIdx.x * blockDim.x + threadIdx.x) >> 5;
    if (row >= NS) return;
    int lane = threadIdx.x & 31;
    const float* xp = x + (size_t)row * 256;
    float v[8];
    float s = 0.0f, s2 = 0.0f;
#pragma unroll
    for (int r = 0; r < 8; r++) {
        v[r] = xp[r * 32 + lane];
        s += v[r];
        s2 += v[r] * v[r];
    }
#pragma unroll
    for (int off = 16; off > 0; off >>= 1) {
        s  += __shfl_xor_sync(0xFFFFFFFFu, s, off);
        s2 += __shfl_xor_sync(0xFFFFFFFFu, s2, off);
    }
    float mean = s * (1.0f / 256.0f);
    float var = s2 * (1.0f / 256.0f) - mean * mean;
    float inv = rsqrtf(var + 1e-6f);
    float* yp = y + (size_t)row * 256;
#pragma unroll
    for (int r = 0; r < 8; r++) {
        int c = r * 32 + lane;
        yp[c] = (v[r] - mean) * inv * gam[c] + bet[c];
    }
}

// ---------------- launch ----------------
extern "C" void kernel_launch(void* const* d_in, const int* in_sizes, int n_in,
                              void* d_out, int out_size) {
    const float* s_in      = (const float*)d_in[0];
    const float* e_in      = (const float*)d_in[1];
    const float* dst_feat  = (const float*)d_in[2];
    const float* fc_w      = (const float*)d_in[3];
    const float* dstfeat_w = (const float*)d_in[4];
    const float* proj_w    = (const float*)d_in[5];
    const float* proj_b    = (const float*)d_in[6];
    const float* ln_g      = (const float*)d_in[7];
    const float* ln_b      = (const float*)d_in[8];
    const float* w1        = (const float*)d_in[9];
    const float* b1        = (const float*)d_in[10];
    const float* w2        = (const float*)d_in[11];
    const float* b2        = (const float*)d_in[12];
    const int*   edge_src  = (const int*)d_in[13];
    const int*   edge_dst  = (const int*)d_in[14];
    float* out = (float*)d_out;

    float *zp, *dfp, *hp, *xp, *xnp, *tp, *wzp, *wdp;
    cudaGetSymbolAddress((void**)&zp,  g_z);
    cudaGetSymbolAddress((void**)&dfp, g_df);
    cudaGetSymbolAddress((void**)&hp,  g_h);
    cudaGetSymbolAddress((void**)&xp,  g_x);
    cudaGetSymbolAddress((void**)&xnp, g_xn);
    cudaGetSymbolAddress((void**)&tp,  g_t);
    cudaGetSymbolAddress((void**)&wzp, g_Wz);
    cudaGetSymbolAddress((void**)&wdp, g_Wd);

    const int TB = 256;
    const int MB = (NS + 127) / 128;  // 782

    // 1) repack per-head weights into plain [K, 256] matrices
    repack_w<<<(D * 256 + TB - 1) / TB, TB>>>(fc_w, wzp, D);
    repack_w<<<(FEAT * 256 + TB - 1) / TB, TB>>>(dstfeat_w, wdp, FEAT);

    // 2) z = e @ Wz  [NE,256]
    mma_gemm<0, false, false><<<dim3(2, MB), TB>>>(
        e_in, D, e_in, D, D, wzp, 256, nullptr, nullptr, 0, zp, 256, NE, 256);

    // 3) df = dst_feat @ Wd  [NS,256]
    mma_gemm<0, false, false><<<dim3(2, MB), TB>>>(
        dst_feat, FEAT, dst_feat, FEAT, FEAT, wdp, 256, nullptr, nullptr, 0, dfp, 256, NS, 64);

    // 4) CSR build by dst (parallel decoupled scan)
    zero_counts<<<(NS + TB - 1) / TB, TB>>>();
    hist_kernel<<<(EDG + TB - 1) / TB, TB>>>(edge_dst);
    scan_pass1<<<NBLK, SCAN_B>>>();
    scan_pass2<<<1, 128>>>();
    scan_pass3<<<NBLK, SCAN_B>>>();
    scatter_kernel<<<(EDG + TB - 1) / TB, TB>>>(edge_src, edge_dst);

    // 5) attention + ELU -> g_h
    attn_kernel<<<(NS * 32 + TB - 1) / TB, TB>>>();

    // 6) proj: [h | s] @ proj_w + b -> g_x
    mma_gemm<0, true, false><<<dim3(2, MB), TB>>>(
        hp, 256, s_in, 256, 256, proj_w, 256, proj_b, nullptr, 0, xp, 256, NS, 512);

    // 7) layernorm -> g_xn
    ln_kernel<<<(NS * 32 + TB - 1) / TB, TB>>>(xp, ln_g, ln_b, xnp);

    // 8) ffn1: gelu(xn @ w1 + b1) -> g_t
    mma_gemm<1, true, false><<<dim3(4, MB), TB>>>(
        xnp, 256, xnp, 256, 256, w1, 512, b1, nullptr, 0, tp, 512, NS, 256);

    // 9) ffn2: g_t @ w2 + b2 + g_x -> out
    mma_gemm<0, true, true><<<dim3(2, MB), TB>>>(
        tp, DFF, tp, DFF, DFF, w2, 256, b2, xp, 256, out, 256, NS, 512);
}

// round 9
// speedup vs baseline: 1.2734x; 1.2734x over previous
#include <cuda_runtime.h>
#include <cuda_bf16.h>
#include <cstdint>
#include <math.h>

// Problem constants (fixed by the dataset)
#define NS 100000
#define NE 100000
#define EDG 1600000
#define D 256
#define H 8
#define HD 32
#define FEAT 64
#define DFF 512

#define SCAN_B 1024
#define NBLK ((NS + SCAN_B - 1) / SCAN_B)   // 98

// smem tile geometry: 32 bf16 of k per row, padded to 40 (80 B)
#define KP 40
#define ROWB 80
#define MATB (128 * ROWB)     // 10240 B per matrix
#define STAGEB (4 * MATB)     // 40960 B per stage (Ah, Al, Bh, Bl)
#define GEMM_SMEM (2 * STAGEB)

typedef __nv_bfloat16 bf16;

// ---------------- device scratch (no allocations allowed) ----------------
__device__ float g_z[(size_t)NE * D];
__device__ float g_df[(size_t)NS * D];
__device__ float g_x[(size_t)NS * D];
// bf16 split activations
__device__ bf16 g_eh[(size_t)NE * D],   g_el[(size_t)NE * D];
__device__ bf16 g_fh[(size_t)NS * FEAT], g_fl[(size_t)NS * FEAT];
__device__ bf16 g_sh[(size_t)NS * D],   g_sl[(size_t)NS * D];
__device__ bf16 g_hh[(size_t)NS * D],   g_hl[(size_t)NS * D];
__device__ bf16 g_xnh[(size_t)NS * D],  g_xnl[(size_t)NS * D];
__device__ bf16 g_th[(size_t)NS * DFF], g_tl[(size_t)NS * DFF];
// bf16 split transposed weights: Wt[n][k]
__device__ bf16 g_wzh[256 * 256], g_wzl[256 * 256];
__device__ bf16 g_wdh[256 * 64],  g_wdl[256 * 64];
__device__ bf16 g_pwh[256 * 512], g_pwl[256 * 512];
__device__ bf16 g_w1h[512 * 256], g_w1l[512 * 256];
__device__ bf16 g_w2h[256 * 512], g_w2l[256 * 512];
// CSR
__device__ int g_counts[NS];
__device__ int g_offsets[NS + 1];
__device__ int g_cursor[NS];
__device__ int g_csr_src[EDG];
__device__ int g_bsum[NBLK];

// ---------------- small helpers ----------------
__device__ __forceinline__ float gelu_fast(float x) {
    const float c = 0.7978845608028654f;
    float u = c * (x + 0.044715f * x * x * x);
    float e = __expf(2.0f * u);
    float th = 1.0f - 2.0f / (e + 1.0f);
    return 0.5f * x * (1.0f + th);
}
__device__ __forceinline__ uint32_t smem_u32(const void* p) {
    uint32_t a;
    asm("{ .reg .u64 t; cvta.to.shared.u64 t, %1; cvt.u32.u64 %0, t; }" : "=r"(a) : "l"(p));
    return a;
}
__device__ __forceinline__ void ldm_x4(uint32_t* r, uint32_t addr) {
    asm volatile("ldmatrix.sync.aligned.m8n8.x4.shared.b16 {%0,%1,%2,%3}, [%4];"
                 : "=r"(r[0]), "=r"(r[1]), "=r"(r[2]), "=r"(r[3]) : "r"(addr));
}
__device__ __forceinline__ void mma_bf16(float* c, const uint32_t* a, const uint32_t* b) {
    asm volatile(
        "mma.sync.aligned.m16n8k16.row.col.f32.bf16.bf16.f32 "
        "{%0,%1,%2,%3}, {%4,%5,%6,%7}, {%8,%9}, {%0,%1,%2,%3};"
        : "+f"(c[0]), "+f"(c[1]), "+f"(c[2]), "+f"(c[3])
        : "r"(a[0]), "r"(a[1]), "r"(a[2]), "r"(a[3]), "r"(b[0]), "r"(b[1]));
}
__device__ __forceinline__ void split_bf16(float x, bf16& hi, bf16& lo) {
    hi = __float2bfloat16_rn(x);
    lo = __float2bfloat16_rn(x - __bfloat162float(hi));
}
__device__ __forceinline__ uint32_t pk2(bf16 a, bf16 b) {
    __nv_bfloat162 t(a, b);
    return *(uint32_t*)&t;
}
__device__ __forceinline__ void cpa16(uint32_t dst, const void* src, bool pred) {
    int sz = pred ? 16 : 0;
    asm volatile("cp.async.cg.shared.global [%0], [%1], 16, %2;"
                 :: "r"(dst), "l"(src), "r"(sz) : "memory");
}

// ---------------- conversion kernels ----------------
// elementwise fp32 -> bf16 hi/lo (n multiple of 4)
__global__ void act_split(const float* __restrict__ in, bf16* __restrict__ hi,
                          bf16* __restrict__ lo, int n) {
    int i = 4 * (blockIdx.x * blockDim.x + threadIdx.x);
    if (i >= n) return;
    float4 v = *(const float4*)(in + i);
    bf16 h0, l0, h1, l1, h2, l2, h3, l3;
    split_bf16(v.x, h0, l0); split_bf16(v.y, h1, l1);
    split_bf16(v.z, h2, l2); split_bf16(v.w, h3, l3);
    *(uint2*)(hi + i) = make_uint2(pk2(h0, h1), pk2(h2, h3));
    *(uint2*)(lo + i) = make_uint2(pk2(l0, l1), pk2(l2, l3));
}
// W[K][N] row-major -> Wt_hi/lo [N][K]
__global__ void wsplit_t(const float* __restrict__ w, bf16* __restrict__ hi,
                         bf16* __restrict__ lo, int K, int N) {
    int idx = blockIdx.x * blockDim.x + threadIdx.x;
    if (idx >= K * N) return;
    int k = idx / N, n = idx % N;
    bf16 h, l;
    split_bf16(w[idx], h, l);
    hi[(size_t)n * K + k] = h;
    lo[(size_t)n * K + k] = l;
}
// per-head weight (H, K, HD) -> Wt_hi/lo [256 n][K k]
__global__ void repack_split(const float* __restrict__ w, bf16* __restrict__ hi,
                             bf16* __restrict__ lo, int K) {
    int idx = blockIdx.x * blockDim.x + threadIdx.x;
    if (idx >= K * 256) return;
    int n = idx / K, k = idx % K;
    bf16 h, l;
    split_bf16(w[(n >> 5) * (K * 32) + k * 32 + (n & 31)], h, l);
    hi[idx] = h;
    lo[idx] = l;
}

// ================= cp.async double-buffered bf16 split GEMM =================
// C (128x128 tile) = act(A @ B^T_stored + bias) + res, A pre-split bf16 hi/lo,
// B stored transposed-split Bt[n][k]. A rows: k < ksplit from pair0 else pair1.
template <int ACT, bool BIAS, bool RES, bool OSPLIT>
__global__ void __launch_bounds__(256, 2) mma_gemm(
    const bf16* __restrict__ Ah0, const bf16* __restrict__ Al0, int lda0,
    const bf16* __restrict__ Ah1, const bf16* __restrict__ Al1, int lda1, int ksplit,
    const bf16* __restrict__ Bh, const bf16* __restrict__ Bl, int ldbk,
    const float* __restrict__ bias,
    const float* __restrict__ res, int ldr,
    float* __restrict__ C, bf16* __restrict__ Ch, bf16* __restrict__ Cl, int ldc,
    int M, int K)
{
    extern __shared__ char dsm[];
    uint32_t sb = smem_u32(dsm);

    int t = threadIdx.x;
    int lane = t & 31, wid = t >> 5;
    int m0 = blockIdx.y * 128;
    int n0 = blockIdx.x * 128;
    int wm = wid & 3;
    int wn = wid >> 2;

    float acc[2][8][4];
#pragma unroll
    for (int i = 0; i < 2; i++)
#pragma unroll
        for (int j = 0; j < 8; j++)
#pragma unroll
            for (int q = 0; q < 4; q++) acc[i][j][q] = 0.0f;

    // fragment offsets (bytes within a matrix)
    uint32_t a_off = (uint32_t)(((wm * 32 + (lane & 15)) * KP + (lane >> 4) * 8) * 2);
    uint32_t b_off = (uint32_t)(((wn * 64 + (lane & 7) + (lane >> 4) * 8) * KP
                                 + ((lane >> 3) & 1) * 8) * 2);

    // prefetch mapping: thread -> row t>>1, chunks c0, c0+1 (16B each)
    int p_row = t >> 1;
    int p_c0 = (t & 1) * 2;
    bool a_ok = (m0 + p_row) < M;
    const int KT = K >> 5;

    // issue one stage of copies
    auto prefetch = [&](int stage, int k0) {
        const bf16 *AhS, *AlS; int lda, koff;
        if (k0 < ksplit) { AhS = Ah0; AlS = Al0; lda = lda0; koff = k0; }
        else             { AhS = Ah1; AlS = Al1; lda = lda1; koff = k0 - ksplit; }
        const bf16* pah = AhS + (size_t)(m0 + p_row) * lda + koff;
        const bf16* pal = AlS + (size_t)(m0 + p_row) * lda + koff;
        const bf16* pbh = Bh + (size_t)(n0 + p_row) * ldbk + k0;
        const bf16* pbl = Bl + (size_t)(n0 + p_row) * ldbk + k0;
        uint32_t base = sb + stage * STAGEB + p_row * ROWB;
#pragma unroll
        for (int ci = 0; ci < 2; ci++) {
            int c = p_c0 + ci;
            cpa16(base + c * 16,            pah + c * 8, a_ok);
            cpa16(base + MATB + c * 16,     pal + c * 8, a_ok);
            cpa16(base + 2 * MATB + c * 16, pbh + c * 8, true);
            cpa16(base + 3 * MATB + c * 16, pbl + c * 8, true);
        }
        asm volatile("cp.async.commit_group;" ::: "memory");
    };

    prefetch(0, 0);

    for (int kt = 0; kt < KT; kt++) {
        if (kt + 1 < KT) {
            prefetch((kt + 1) & 1, (kt + 1) * 32);
            asm volatile("cp.async.wait_group 1;" ::: "memory");
        } else {
            asm volatile("cp.async.wait_group 0;" ::: "memory");
        }
        __syncthreads();

        uint32_t s0 = sb + (kt & 1) * STAGEB;
        uint32_t sAh = s0, sAl = s0 + MATB, sBh = s0 + 2 * MATB, sBl = s0 + 3 * MATB;

#pragma unroll
        for (int ks = 0; ks < 2; ks++) {
            uint32_t koffb = (uint32_t)(ks * 32);
            uint32_t a_hi[2][4], a_lo[2][4], b[4][4];
            ldm_x4(a_hi[0], sAh + a_off + koffb);
            ldm_x4(a_hi[1], sAh + a_off + koffb + 16 * KP * 2);
            ldm_x4(a_lo[0], sAl + a_off + koffb);
            ldm_x4(a_lo[1], sAl + a_off + koffb + 16 * KP * 2);
#pragma unroll
            for (int ni2 = 0; ni2 < 4; ni2++)
                ldm_x4(b[ni2], sBh + b_off + koffb + ni2 * 16 * KP * 2);
            // pass 1: Ah * Bh
#pragma unroll
            for (int mi = 0; mi < 2; mi++)
#pragma unroll
                for (int ni = 0; ni < 8; ni++)
                    mma_bf16(acc[mi][ni], a_hi[mi], &b[ni >> 1][(ni & 1) * 2]);
            // pass 2: Al * Bh
#pragma unroll
            for (int mi = 0; mi < 2; mi++)
#pragma unroll
                for (int ni = 0; ni < 8; ni++)
                    mma_bf16(acc[mi][ni], a_lo[mi], &b[ni >> 1][(ni & 1) * 2]);
            // pass 3: Ah * Bl
#pragma unroll
            for (int ni2 = 0; ni2 < 4; ni2++)
                ldm_x4(b[ni2], sBl + b_off + koffb + ni2 * 16 * KP * 2);
#pragma unroll
            for (int mi = 0; mi < 2; mi++)
#pragma unroll
                for (int ni = 0; ni < 8; ni++)
                    mma_bf16(acc[mi][ni], a_hi[mi], &b[ni >> 1][(ni & 1) * 2]);
        }
        __syncthreads();
    }

    // ---- epilogue ----
#pragma unroll
    for (int mi = 0; mi < 2; mi++) {
#pragma unroll
        for (int ni = 0; ni < 8; ni++) {
            int cc = n0 + wn * 64 + ni * 8 + (lane & 3) * 2;
#pragma unroll
            for (int hh = 0; hh < 2; hh++) {
                int m = m0 + wm * 32 + mi * 16 + (lane >> 2) + hh * 8;
                if (m >= M) continue;
                float v0 = acc[mi][ni][hh * 2 + 0];
                float v1 = acc[mi][ni][hh * 2 + 1];
                if (BIAS) { v0 += bias[cc]; v1 += bias[cc + 1]; }
                if (ACT == 1) { v0 = gelu_fast(v0); v1 = gelu_fast(v1); }
                if (RES) {
                    const float* rp = res + (size_t)m * ldr + cc;
                    v0 += rp[0]; v1 += rp[1];
                }
                if (OSPLIT) {
                    bf16 h0, l0, h1, l1;
                    split_bf16(v0, h0, l0);
                    split_bf16(v1, h1, l1);
                    *(uint32_t*)(Ch + (size_t)m * ldc + cc) = pk2(h0, h1);
                    *(uint32_t*)(Cl + (size_t)m * ldc + cc) = pk2(l0, l1);
                } else {
                    *(float2*)(C + (size_t)m * ldc + cc) = make_float2(v0, v1);
                }
            }
        }
    }
}

// ---------------- CSR build ----------------
__global__ void zero_counts() {
    int i = blockIdx.x * blockDim.x + threadIdx.x;
    if (i < NS) g_counts[i] = 0;
}
__global__ void hist_kernel(const int* __restrict__ edge_dst) {
    int i = blockIdx.x * blockDim.x + threadIdx.x;
    if (i < EDG) atomicAdd(&g_counts[edge_dst[i]], 1);
}
__global__ void __launch_bounds__(SCAN_B) scan_pass1() {
    __shared__ int ws[32];
    int b = blockIdx.x, t = threadIdx.x;
    int i = b * SCAN_B + t;
    int v = (i < NS) ? g_counts[i] : 0;
#pragma unroll
    for (int o = 16; o; o >>= 1) v += __shfl_xor_sync(0xFFFFFFFFu, v, o);
    if ((t & 31) == 0) ws[t >> 5] = v;
    __syncthreads();
    if (t < 32) {
        int x = ws[t];
#pragma unroll
        for (int o = 16; o; o >>= 1) x += __shfl_xor_sync(0xFFFFFFFFu, x, o);
        if (t == 0) g_bsum[b] = x;
    }
}
__global__ void scan_pass2() {
    __shared__ int sh[128];
    int t = threadIdx.x;
    int orig = (t < NBLK) ? g_bsum[t] : 0;
    sh[t] = orig;
    __syncthreads();
    for (int o = 1; o < 128; o <<= 1) {
        int v = (t >= o) ? sh[t - o] : 0;
        __syncthreads();
        sh[t] += v;
        __syncthreads();
    }
    if (t < NBLK) g_bsum[t] = sh[t] - orig;
}
__global__ void __launch_bounds__(SCAN_B) scan_pass3() {
    __shared__ int ws[32];
    int b = blockIdx.x, t = threadIdx.x;
    int lane = t & 31, w = t >> 5;
    int i = b * SCAN_B + t;
    int v = (i < NS) ? g_counts[i] : 0;
    int x = v;
#pragma unroll
    for (int o = 1; o < 32; o <<= 1) {
        int y = __shfl_up_sync(0xFFFFFFFFu, x, o);
        if (lane >= o) x += y;
    }
    if (lane == 31) ws[w] = x;
    __syncthreads();
    if (w == 0) {
        int sv = ws[lane];
#pragma unroll
        for (int o = 1; o < 32; o <<= 1) {
            int y = __shfl_up_sync(0xFFFFFFFFu, sv, o);
            if (lane >= o) sv += y;
        }
        ws[lane] = sv;
    }
    __syncthreads();
    int incl = x + (w > 0 ? ws[w - 1] : 0) + g_bsum[b];
    if (i < NS) {
        g_offsets[i + 1] = incl;
        g_cursor[i] = incl - v;
    }
    if (b == 0 && t == 0) g_offsets[0] = 0;
}
__global__ void scatter_kernel(const int* __restrict__ edge_src,
                               const int* __restrict__ edge_dst) {
    int i = blockIdx.x * blockDim.x + threadIdx.x;
    if (i >= EDG) return;
    int dst = edge_dst[i];
    int pos = atomicAdd(&g_cursor[dst], 1);
    g_csr_src[pos] = edge_src[i];
}

// ---------------- attention: warp per dst, lane = (head, quarter) ----------------
// R4-winning core; epilogue emits split bf16 h for the proj GEMM.
__global__ void __launch_bounds__(256) attn_kernel() {
    int gw = (blockIdx.x * blockDim.x + threadIdx.x) >> 5;
    if (gw >= NS) return;
    int lane = threadIdx.x & 31;
    int off = (lane >> 2) * 32 + (lane & 3) * 8;

    int beg = g_offsets[gw];
    int end = g_offsets[gw + 1];

    const float* dfp = g_df + (size_t)gw * 256 + off;
    float4 d0 = *(const float4*)(dfp);
    float4 d1 = *(const float4*)(dfp + 4);

    float m = -1e30f, den = 0.0f;
    float4 a0 = make_float4(0.f, 0.f, 0.f, 0.f);
    float4 a1 = make_float4(0.f, 0.f, 0.f, 0.f);

    int e = beg;
    for (; e + 2 <= end; e += 2) {
        int s0 = __ldg(&g_csr_src[e]);
        int s1 = __ldg(&g_csr_src[e + 1]);
        const float* zp0 = g_z + (size_t)s0 * 256 + off;
        const float* zp1 = g_z + (size_t)s1 * 256 + off;
        float4 x0 = __ldg((const float4*)zp0);
        float4 x1 = __ldg((const float4*)(zp0 + 4));
        float4 y0 = __ldg((const float4*)zp1);
        float4 y1 = __ldg((const float4*)(zp1 + 4));

        float sa = x0.x * d0.x + x0.y * d0.y + x0.z * d0.z + x0.w * d0.w
                 + x1.x * d1.x + x1.y * d1.y + x1.z * d1.z + x1.w * d1.w;
        float sb = y0.x * d0.x + y0.y * d0.y + y0.z * d0.z + y0.w * d0.w
                 + y1.x * d1.x + y1.y * d1.y + y1.z * d1.z + y1.w * d1.w;
        sa += __shfl_xor_sync(0xFFFFFFFFu, sa, 1);
        sb += __shfl_xor_sync(0xFFFFFFFFu, sb, 1);
        sa += __shfl_xor_sync(0xFFFFFFFFu, sa, 2);
        sb += __shfl_xor_sync(0xFFFFFFFFu, sb, 2);

        {
            float mn = fmaxf(m, sa);
            float sc = __expf(m - mn);
            float w  = __expf(sa - mn);
            den = den * sc + w;
            a0.x = a0.x * sc + w * x0.x; a0.y = a0.y * sc + w * x0.y;
            a0.z = a0.z * sc + w * x0.z; a0.w = a0.w * sc + w * x0.w;
            a1.x = a1.x * sc + w * x1.x; a1.y = a1.y * sc + w * x1.y;
            a1.z = a1.z * sc + w * x1.z; a1.w = a1.w * sc + w * x1.w;
            m = mn;
        }
        {
            float mn = fmaxf(m, sb);
            float sc = __expf(m - mn);
            float w  = __expf(sb - mn);
            den = den * sc + w;
            a0.x = a0.x * sc + w * y0.x; a0.y = a0.y * sc + w * y0.y;
            a0.z = a0.z * sc + w * y0.z; a0.w = a0.w * sc + w * y0.w;
            a1.x = a1.x * sc + w * y1.x; a1.y = a1.y * sc + w * y1.y;
            a1.z = a1.z * sc + w * y1.z; a1.w = a1.w * sc + w * y1.w;
            m = mn;
        }
    }
    for (; e < end; e++) {
        int s0 = __ldg(&g_csr_src[e]);
        const float* zp0 = g_z + (size_t)s0 * 256 + off;
        float4 x0 = __ldg((const float4*)zp0);
        float4 x1 = __ldg((const float4*)(zp0 + 4));
        float sa = x0.x * d0.x + x0.y * d0.y + x0.z * d0.z + x0.w * d0.w
                 + x1.x * d1.x + x1.y * d1.y + x1.z * d1.z + x1.w * d1.w;
        sa += __shfl_xor_sync(0xFFFFFFFFu, sa, 1);
        sa += __shfl_xor_sync(0xFFFFFFFFu, sa, 2);
        float mn = fmaxf(m, sa);
        float sc = __expf(m - mn);
        float w  = __expf(sa - mn);
        den = den * sc + w;
        a0.x = a0.x * sc + w * x0.x; a0.y = a0.y * sc + w * x0.y;
        a0.z = a0.z * sc + w * x0.z; a0.w = a0.w * sc + w * x0.w;
        a1.x = a1.x * sc + w * x1.x; a1.y = a1.y * sc + w * x1.y;
        a1.z = a1.z * sc + w * x1.z; a1.w = a1.w * sc + w * x1.w;
        m = mn;
    }

    float inv = 1.0f / den;
    float v[8];
    v[0] = a0.x * inv; v[1] = a0.y * inv; v[2] = a0.z * inv; v[3] = a0.w * inv;
    v[4] = a1.x * inv; v[5] = a1.y * inv; v[6] = a1.z * inv; v[7] = a1.w * inv;
    bf16 hi[8], lo[8];
#pragma unroll
    for (int i = 0; i < 8; i++) {
        v[i] = (v[i] > 0.0f) ? v[i] : expm1f(v[i]);  // ELU(alpha=1)
        split_bf16(v[i], hi[i], lo[i]);
    }
    size_t ob = (size_t)gw * 256 + off;
    *(uint4*)(g_hh + ob) = make_uint4(pk2(hi[0], hi[1]), pk2(hi[2], hi[3]),
                                      pk2(hi[4], hi[5]), pk2(hi[6], hi[7]));
    *(uint4*)(g_hl + ob) = make_uint4(pk2(lo[0], lo[1]), pk2(lo[2], lo[3]),
                                      pk2(lo[4], lo[5]), pk2(lo[6], lo[7]));
}

// ---------------- layernorm: warp per row, lane owns 8 contiguous cols ----------------
__global__ void ln_kernel(const float* __restrict__ x,
                          const float* __restrict__ gam,
                          const float* __restrict__ bet) {
    int row = (blockIdx.x * blockDim.x + threadIdx.x) >> 5;
    if (row >= NS) return;
    int lane = threadIdx.x & 31;
    const float* xp = x + (size_t)row * 256 + lane * 8;
    float4 va = *(const float4*)xp;
    float4 vb = *(const float4*)(xp + 4);
    float v[8] = {va.x, va.y, va.z, va.w, vb.x, vb.y, vb.z, vb.w};
    float s = 0.0f, s2 = 0.0f;
#pragma unroll
    for (int r = 0; r < 8; r++) { s += v[r]; s2 += v[r] * v[r]; }
#pragma unroll
    for (int o = 16; o > 0; o >>= 1) {
        s  += __shfl_xor_sync(0xFFFFFFFFu, s, o);
        s2 += __shfl_xor_sync(0xFFFFFFFFu, s2, o);
    }
    float mean = s * (1.0f / 256.0f);
    float var = s2 * (1.0f / 256.0f) - mean * mean;
    float inv = rsqrtf(var + 1e-6f);
    float4 ga = *(const float4*)(gam + lane * 8);
    float4 gb = *(const float4*)(gam + lane * 8 + 4);
    float4 ba = *(const float4*)(bet + lane * 8);
    float4 bb = *(const float4*)(bet + lane * 8 + 4);
    float g[8] = {ga.x, ga.y, ga.z, ga.w, gb.x, gb.y, gb.z, gb.w};
    float bt[8] = {ba.x, ba.y, ba.z, ba.w, bb.x, bb.y, bb.z, bb.w};
    bf16 hi[8], lo[8];
#pragma unroll
    for (int r = 0; r < 8; r++) {
        float y = (v[r] - mean) * inv * g[r] + bt[r];
        split_bf16(y, hi[r], lo[r]);
    }
    size_t ob = (size_t)row * 256 + lane * 8;
    *(uint4*)(g_xnh + ob) = make_uint4(pk2(hi[0], hi[1]), pk2(hi[2], hi[3]),
                                       pk2(hi[4], hi[5]), pk2(hi[6], hi[7]));
    *(uint4*)(g_xnl + ob) = make_uint4(pk2(lo[0], lo[1]), pk2(lo[2], lo[3]),
                                       pk2(lo[4], lo[5]), pk2(lo[6], lo[7]));
}

// ---------------- launch ----------------
extern "C" void kernel_launch(void* const* d_in, const int* in_sizes, int n_in,
                              void* d_out, int out_size) {
    const float* s_in      = (const float*)d_in[0];
    const float* e_in      = (const float*)d_in[1];
    const float* dst_feat  = (const float*)d_in[2];
    const float* fc_w      = (const float*)d_in[3];
    const float* dstfeat_w = (const float*)d_in[4];
    const float* proj_w    = (const float*)d_in[5];
    const float* proj_b    = (const float*)d_in[6];
    const float* ln_g      = (const float*)d_in[7];
    const float* ln_b      = (const float*)d_in[8];
    const float* w1        = (const float*)d_in[9];
    const float* b1        = (const float*)d_in[10];
    const float* w2        = (const float*)d_in[11];
    const float* b2        = (const float*)d_in[12];
    const int*   edge_src  = (const int*)d_in[13];
    const int*   edge_dst  = (const int*)d_in[14];
    float* out = (float*)d_out;

    float *zp, *dfp, *xp;
    cudaGetSymbolAddress((void**)&zp,  g_z);
    cudaGetSymbolAddress((void**)&dfp, g_df);
    cudaGetSymbolAddress((void**)&xp,  g_x);
    bf16 *eh, *el, *fh, *fl, *sh, *sl, *hh, *hl, *xnh, *xnl, *th, *tl;
    cudaGetSymbolAddress((void**)&eh,  g_eh);  cudaGetSymbolAddress((void**)&el,  g_el);
    cudaGetSymbolAddress((void**)&fh,  g_fh);  cudaGetSymbolAddress((void**)&fl,  g_fl);
    cudaGetSymbolAddress((void**)&sh,  g_sh);  cudaGetSymbolAddress((void**)&sl,  g_sl);
    cudaGetSymbolAddress((void**)&hh,  g_hh);  cudaGetSymbolAddress((void**)&hl,  g_hl);
    cudaGetSymbolAddress((void**)&xnh, g_xnh); cudaGetSymbolAddress((void**)&xnl, g_xnl);
    cudaGetSymbolAddress((void**)&th,  g_th);  cudaGetSymbolAddress((void**)&tl,  g_tl);
    bf16 *wzh, *wzl, *wdh, *wdl, *pwh, *pwl, *w1h, *w1l, *w2h, *w2l;
    cudaGetSymbolAddress((void**)&wzh, g_wzh); cudaGetSymbolAddress((void**)&wzl, g_wzl);
    cudaGetSymbolAddress((void**)&wdh, g_wdh); cudaGetSymbolAddress((void**)&wdl, g_wdl);
    cudaGetSymbolAddress((void**)&pwh, g_pwh); cudaGetSymbolAddress((void**)&pwl, g_pwl);
    cudaGetSymbolAddress((void**)&w1h, g_w1h); cudaGetSymbolAddress((void**)&w1l, g_w1l);
    cudaGetSymbolAddress((void**)&w2h, g_w2h); cudaGetSymbolAddress((void**)&w2l, g_w2l);

    // opt-in to large dynamic smem (host-side, idempotent, capture-safe)
    cudaFuncSetAttribute(mma_gemm<0, false, false, false>, cudaFuncAttributeMaxDynamicSharedMemorySize, GEMM_SMEM);
    cudaFuncSetAttribute(mma_gemm<0, true,  false, false>, cudaFuncAttributeMaxDynamicSharedMemorySize, GEMM_SMEM);
    cudaFuncSetAttribute(mma_gemm<1, true,  false, true >, cudaFuncAttributeMaxDynamicSharedMemorySize, GEMM_SMEM);
    cudaFuncSetAttribute(mma_gemm<0, true,  true,  false>, cudaFuncAttributeMaxDynamicSharedMemorySize, GEMM_SMEM);

    const int TB = 256;
    const int MB = (NS + 127) / 128;  // 782

    // 1) input conversions
    act_split<<<(NE * D / 4 + TB - 1) / TB, TB>>>(e_in, eh, el, NE * D);
    act_split<<<(NS * FEAT / 4 + TB - 1) / TB, TB>>>(dst_feat, fh, fl, NS * FEAT);
    act_split<<<(NS * D / 4 + TB - 1) / TB, TB>>>(s_in, sh, sl, NS * D);
    repack_split<<<(256 * 256 + TB - 1) / TB, TB>>>(fc_w, wzh, wzl, 256);
    repack_split<<<(64 * 256 + TB - 1) / TB, TB>>>(dstfeat_w, wdh, wdl, 64);
    wsplit_t<<<(512 * 256 + TB - 1) / TB, TB>>>(proj_w, pwh, pwl, 512, 256);
    wsplit_t<<<(256 * 512 + TB - 1) / TB, TB>>>(w1, w1h, w1l, 256, 512);
    wsplit_t<<<(512 * 256 + TB - 1) / TB, TB>>>(w2, w2h, w2l, 512, 256);

    // 2) z = e @ Wz  [NE,256]
    mma_gemm<0, false, false, false><<<dim3(2, MB), TB, GEMM_SMEM>>>(
        eh, el, 256, eh, el, 256, D, wzh, wzl, 256,
        nullptr, nullptr, 0, zp, nullptr, nullptr, 256, NE, 256);

    // 3) df = dst_feat @ Wd  [NS,256]
    mma_gemm<0, false, false, false><<<dim3(2, MB), TB, GEMM_SMEM>>>(
        fh, fl, 64, fh, fl, 64, FEAT, wdh, wdl, 64,
        nullptr, nullptr, 0, dfp, nullptr, nullptr, 256, NS, 64);

    // 4) CSR build by dst (parallel decoupled scan)
    zero_counts<<<(NS + TB - 1) / TB, TB>>>();
    hist_kernel<<<(EDG + TB - 1) / TB, TB>>>(edge_dst);
    scan_pass1<<<NBLK, SCAN_B>>>();
    scan_pass2<<<1, 128>>>();
    scan_pass3<<<NBLK, SCAN_B>>>();
    scatter_kernel<<<(EDG + TB - 1) / TB, TB>>>(edge_src, edge_dst);

    // 5) attention + ELU -> h split bf16
    attn_kernel<<<(NS * 32 + TB - 1) / TB, TB>>>();

    // 6) proj: [h | s] @ proj_w + b -> g_x (fp32)
    mma_gemm<0, true, false, false><<<dim3(2, MB), TB, GEMM_SMEM>>>(
        hh, hl, 256, sh, sl, 256, 256, pwh, pwl, 512,
        proj_b, nullptr, 0, xp, nullptr, nullptr, 256, NS, 512);

    // 7) layernorm -> xn split bf16
    ln_kernel<<<(NS * 32 + TB - 1) / TB, TB>>>(xp, ln_g, ln_b);

    // 8) ffn1: gelu(xn @ w1 + b1) -> t split bf16
    mma_gemm<1, true, false, true><<<dim3(4, MB), TB, GEMM_SMEM>>>(
        xnh, xnl, 256, xnh, xnl, 256, 256, w1h, w1l, 256,
        b1, nullptr, 0, nullptr, th, tl, 512, NS, 256);

    // 9) ffn2: t @ w2 + b2 + g_x -> out (fp32)
    mma_gemm<0, true, true, false><<<dim3(2, MB), TB, GEMM_SMEM>>>(
        th, tl, 512, th, tl, 512, 512, w2h, w2l, 512,
        b2, xp, 256, out, nullptr, nullptr, 256, NS, 512);
}

// round 10
// speedup vs baseline: 1.5068x; 1.1832x over previous
#include <cuda_runtime.h>
#include <cuda_bf16.h>
#include <cuda_fp16.h>
#include <cstdint>
#include <math.h>

// Problem constants (fixed by the dataset)
#define NS 100000
#define NE 100000
#define EDG 1600000
#define D 256
#define H 8
#define HD 32
#define FEAT 64
#define DFF 512

#define SCAN_B 1024
#define NBLK ((NS + SCAN_B - 1) / SCAN_B)   // 98

// smem tile geometry: 32 elems of k per row, padded to 40 (80 B)
#define KP 40
#define ROWB 80
#define MATB (128 * ROWB)          // 10240 B per matrix
#define SMEM3 (2 * 4 * MATB)       // 81920 B (bf16 3-pass: Ah,Al,Bh,Bl x2)
#define SMEM2 (2 * 3 * MATB)       // 61440 B (fp16 2-pass: Ah,Al,Bh x2)

typedef __nv_bfloat16 bf16;
typedef __half f16;

// ---------------- device scratch (no allocations allowed) ----------------
__device__ float g_z[(size_t)NE * D];
__device__ float g_df[(size_t)NS * D];
__device__ float g_x[(size_t)NS * D];
// bf16 split (pre-softmax path)
__device__ bf16 g_eh[(size_t)NE * D],    g_el[(size_t)NE * D];
__device__ bf16 g_fh[(size_t)NS * FEAT], g_fl[(size_t)NS * FEAT];
__device__ bf16 g_wzh[256 * 256], g_wzl[256 * 256];
__device__ bf16 g_wdh[256 * 64],  g_wdl[256 * 64];
// fp16 split (post-softmax path)
__device__ f16 g_sh[(size_t)NS * D],   g_sl[(size_t)NS * D];
__device__ f16 g_hh[(size_t)NS * D],   g_hl[(size_t)NS * D];
__device__ f16 g_xnh[(size_t)NS * D],  g_xnl[(size_t)NS * D];
__device__ f16 g_th[(size_t)NS * DFF], g_tl[(size_t)NS * DFF];
// fp16 plain transposed weights Wt[n][k]
__device__ f16 g_pw[256 * 512];
__device__ f16 g_w1[512 * 256];
__device__ f16 g_w2[256 * 512];
// CSR
__device__ int g_counts[NS];
__device__ int g_offsets[NS + 1];
__device__ int g_cursor[NS];
__device__ int g_csr_src[EDG];
__device__ int g_bsum[NBLK];

// ---------------- small helpers ----------------
__device__ __forceinline__ float gelu_fast(float x) {
    const float c = 0.7978845608028654f;
    float u = c * (x + 0.044715f * x * x * x);
    float e = __expf(2.0f * u);
    float th = 1.0f - 2.0f / (e + 1.0f);
    return 0.5f * x * (1.0f + th);
}
__device__ __forceinline__ uint32_t smem_u32(const void* p) {
    uint32_t a;
    asm("{ .reg .u64 t; cvta.to.shared.u64 t, %1; cvt.u32.u64 %0, t; }" : "=r"(a) : "l"(p));
    return a;
}
__device__ __forceinline__ void ldm_x4(uint32_t* r, uint32_t addr) {
    asm volatile("ldmatrix.sync.aligned.m8n8.x4.shared.b16 {%0,%1,%2,%3}, [%4];"
                 : "=r"(r[0]), "=r"(r[1]), "=r"(r[2]), "=r"(r[3]) : "r"(addr));
}
// packing / splitting (overloaded per type)
__device__ __forceinline__ uint32_t pk2(bf16 a, bf16 b) {
    __nv_bfloat162 t(a, b); return *(uint32_t*)&t;
}
__device__ __forceinline__ uint32_t pk2(f16 a, f16 b) {
    __half2 t(a, b); return *(uint32_t*)&t;
}
__device__ __forceinline__ void split2(float x, bf16& hi, bf16& lo) {
    hi = __float2bfloat16_rn(x);
    lo = __float2bfloat16_rn(x - __bfloat162float(hi));
}
__device__ __forceinline__ void split2(float x, f16& hi, f16& lo) {
    hi = __float2half_rn(x);
    lo = __float2half_rn(x - __half2float(hi));
}
// mma per type
template <typename T>
__device__ __forceinline__ void mma_t(float* c, const uint32_t* a, const uint32_t* b);
template <>
__device__ __forceinline__ void mma_t<bf16>(float* c, const uint32_t* a, const uint32_t* b) {
    asm volatile(
        "mma.sync.aligned.m16n8k16.row.col.f32.bf16.bf16.f32 "
        "{%0,%1,%2,%3}, {%4,%5,%6,%7}, {%8,%9}, {%0,%1,%2,%3};"
        : "+f"(c[0]), "+f"(c[1]), "+f"(c[2]), "+f"(c[3])
        : "r"(a[0]), "r"(a[1]), "r"(a[2]), "r"(a[3]), "r"(b[0]), "r"(b[1]));
}
template <>
__device__ __forceinline__ void mma_t<f16>(float* c, const uint32_t* a, const uint32_t* b) {
    asm volatile(
        "mma.sync.aligned.m16n8k16.row.col.f32.f16.f16.f32 "
        "{%0,%1,%2,%3}, {%4,%5,%6,%7}, {%8,%9}, {%0,%1,%2,%3};"
        : "+f"(c[0]), "+f"(c[1]), "+f"(c[2]), "+f"(c[3])
        : "r"(a[0]), "r"(a[1]), "r"(a[2]), "r"(a[3]), "r"(b[0]), "r"(b[1]));
}
__device__ __forceinline__ void cpa16(uint32_t dst, const void* src, bool pred) {
    int sz = pred ? 16 : 0;
    asm volatile("cp.async.cg.shared.global [%0], [%1], 16, %2;"
                 :: "r"(dst), "l"(src), "r"(sz) : "memory");
}

// ---------------- conversion kernels ----------------
template <typename T>
__global__ void act_split(const float* __restrict__ in, T* __restrict__ hi,
                          T* __restrict__ lo, int n) {
    int i = 4 * (blockIdx.x * blockDim.x + threadIdx.x);
    if (i >= n) return;
    float4 v = *(const float4*)(in + i);
    T h0, l0, h1, l1, h2, l2, h3, l3;
    split2(v.x, h0, l0); split2(v.y, h1, l1);
    split2(v.z, h2, l2); split2(v.w, h3, l3);
    *(uint2*)(hi + i) = make_uint2(pk2(h0, h1), pk2(h2, h3));
    *(uint2*)(lo + i) = make_uint2(pk2(l0, l1), pk2(l2, l3));
}
// W[K][N] row-major -> fp16 Wt[N][K] (rn, no split)
__global__ void wsplit_t16(const float* __restrict__ w, f16* __restrict__ o, int K, int N) {
    int idx = blockIdx.x * blockDim.x + threadIdx.x;
    if (idx >= K * N) return;
    int k = idx / N, n = idx % N;
    o[(size_t)n * K + k] = __float2half_rn(w[idx]);
}
// per-head weight (H, K, HD) -> bf16 split Wt[256][K]
__global__ void repack_split(const float* __restrict__ w, bf16* __restrict__ hi,
                             bf16* __restrict__ lo, int K) {
    int idx = blockIdx.x * blockDim.x + threadIdx.x;
    if (idx >= K * 256) return;
    int n = idx / K, k = idx % K;
    bf16 h, l;
    split2(w[(n >> 5) * (K * 32) + k * 32 + (n & 31)], h, l);
    hi[idx] = h;
    lo[idx] = l;
}

// ================= cp.async double-buffered split GEMM =================
// PASSES==3 (bf16): Ah*Bh + Al*Bh + Ah*Bl.  PASSES==2 (fp16): Ah*B + Al*B.
template <typename T, int PASSES, int ACT, bool BIAS, bool RES, bool OSPLIT>
__global__ void __launch_bounds__(256, 2) mma_gemm(
    const T* __restrict__ Ah0, const T* __restrict__ Al0, int lda0,
    const T* __restrict__ Ah1, const T* __restrict__ Al1, int lda1, int ksplit,
    const T* __restrict__ Bh, const T* __restrict__ Bl, int ldbk,
    const float* __restrict__ bias,
    const float* __restrict__ res, int ldr,
    float* __restrict__ C, T* __restrict__ Ch, T* __restrict__ Cl, int ldc,
    int M, int K)
{
    constexpr int NMAT = (PASSES == 3) ? 4 : 3;
    constexpr int STB = NMAT * MATB;
    extern __shared__ char dsm[];
    uint32_t sb = smem_u32(dsm);

    int t = threadIdx.x;
    int lane = t & 31, wid = t >> 5;
    int m0 = blockIdx.y * 128;
    int n0 = blockIdx.x * 128;
    int wm = wid & 3;
    int wn = wid >> 2;

    float acc[2][8][4];
#pragma unroll
    for (int i = 0; i < 2; i++)
#pragma unroll
        for (int j = 0; j < 8; j++)
#pragma unroll
            for (int q = 0; q < 4; q++) acc[i][j][q] = 0.0f;

    uint32_t a_off = (uint32_t)(((wm * 32 + (lane & 15)) * KP + (lane >> 4) * 8) * 2);
    uint32_t b_off = (uint32_t)(((wn * 64 + (lane & 7) + (lane >> 4) * 8) * KP
                                 + ((lane >> 3) & 1) * 8) * 2);

    int p_row = t >> 1;
    int p_c0 = (t & 1) * 2;
    bool a_ok = (m0 + p_row) < M;
    const int KT = K >> 5;

    auto prefetch = [&](int stage, int k0) {
        const T *AhS, *AlS; int lda, koff;
        if (k0 < ksplit) { AhS = Ah0; AlS = Al0; lda = lda0; koff = k0; }
        else             { AhS = Ah1; AlS = Al1; lda = lda1; koff = k0 - ksplit; }
        const T* pah = AhS + (size_t)(m0 + p_row) * lda + koff;
        const T* pal = AlS + (size_t)(m0 + p_row) * lda + koff;
        const T* pbh = Bh + (size_t)(n0 + p_row) * ldbk + k0;
        uint32_t base = sb + stage * STB + p_row * ROWB;
#pragma unroll
        for (int ci = 0; ci < 2; ci++) {
            int c = p_c0 + ci;
            cpa16(base + c * 16,            pah + c * 8, a_ok);
            cpa16(base + MATB + c * 16,     pal + c * 8, a_ok);
            cpa16(base + 2 * MATB + c * 16, pbh + c * 8, true);
            if (PASSES == 3) {
                const T* pbl = Bl + (size_t)(n0 + p_row) * ldbk + k0;
                cpa16(base + 3 * MATB + c * 16, pbl + c * 8, true);
            }
        }
        asm volatile("cp.async.commit_group;" ::: "memory");
    };

    prefetch(0, 0);

    for (int kt = 0; kt < KT; kt++) {
        if (kt + 1 < KT) {
            prefetch((kt + 1) & 1, (kt + 1) * 32);
            asm volatile("cp.async.wait_group 1;" ::: "memory");
        } else {
            asm volatile("cp.async.wait_group 0;" ::: "memory");
        }
        __syncthreads();

        uint32_t s0 = sb + (kt & 1) * STB;
        uint32_t sAh = s0, sAl = s0 + MATB, sBh = s0 + 2 * MATB;

#pragma unroll
        for (int ks = 0; ks < 2; ks++) {
            uint32_t koffb = (uint32_t)(ks * 32);
            uint32_t a_hi[2][4], a_lo[2][4], b[4][4];
            ldm_x4(a_hi[0], sAh + a_off + koffb);
            ldm_x4(a_hi[1], sAh + a_off + koffb + 16 * KP * 2);
            ldm_x4(a_lo[0], sAl + a_off + koffb);
            ldm_x4(a_lo[1], sAl + a_off + koffb + 16 * KP * 2);
#pragma unroll
            for (int ni2 = 0; ni2 < 4; ni2++)
                ldm_x4(b[ni2], sBh + b_off + koffb + ni2 * 16 * KP * 2);
            // pass 1: Ah * Bh
#pragma unroll
            for (int mi = 0; mi < 2; mi++)
#pragma unroll
                for (int ni = 0; ni < 8; ni++)
                    mma_t<T>(acc[mi][ni], a_hi[mi], &b[ni >> 1][(ni & 1) * 2]);
            // pass 2: Al * Bh
#pragma unroll
            for (int mi = 0; mi < 2; mi++)
#pragma unroll
                for (int ni = 0; ni < 8; ni++)
                    mma_t<T>(acc[mi][ni], a_lo[mi], &b[ni >> 1][(ni & 1) * 2]);
            if (PASSES == 3) {
                uint32_t sBl = s0 + 3 * MATB;
#pragma unroll
                for (int ni2 = 0; ni2 < 4; ni2++)
                    ldm_x4(b[ni2], sBl + b_off + koffb + ni2 * 16 * KP * 2);
#pragma unroll
                for (int mi = 0; mi < 2; mi++)
#pragma unroll
                    for (int ni = 0; ni < 8; ni++)
                        mma_t<T>(acc[mi][ni], a_hi[mi], &b[ni >> 1][(ni & 1) * 2]);
            }
        }
        __syncthreads();
    }

    // ---- epilogue ----
#pragma unroll
    for (int mi = 0; mi < 2; mi++) {
#pragma unroll
        for (int ni = 0; ni < 8; ni++) {
            int cc = n0 + wn * 64 + ni * 8 + (lane & 3) * 2;
#pragma unroll
            for (int hh = 0; hh < 2; hh++) {
                int m = m0 + wm * 32 + mi * 16 + (lane >> 2) + hh * 8;
                if (m >= M) continue;
                float v0 = acc[mi][ni][hh * 2 + 0];
                float v1 = acc[mi][ni][hh * 2 + 1];
                if (BIAS) { v0 += bias[cc]; v1 += bias[cc + 1]; }
                if (ACT == 1) { v0 = gelu_fast(v0); v1 = gelu_fast(v1); }
                if (RES) {
                    const float* rp = res + (size_t)m * ldr + cc;
                    v0 += rp[0]; v1 += rp[1];
                }
                if (OSPLIT) {
                    T h0, l0, h1, l1;
                    split2(v0, h0, l0);
                    split2(v1, h1, l1);
                    *(uint32_t*)(Ch + (size_t)m * ldc + cc) = pk2(h0, h1);
                    *(uint32_t*)(Cl + (size_t)m * ldc + cc) = pk2(l0, l1);
                } else {
                    *(float2*)(C + (size_t)m * ldc + cc) = make_float2(v0, v1);
                }
            }
        }
    }
}

// ---------------- CSR build ----------------
__global__ void zero_counts() {
    int i = blockIdx.x * blockDim.x + threadIdx.x;
    if (i < NS) g_counts[i] = 0;
}
__global__ void hist_kernel(const int* __restrict__ edge_dst) {
    int i = blockIdx.x * blockDim.x + threadIdx.x;
    if (i < EDG) atomicAdd(&g_counts[edge_dst[i]], 1);
}
__global__ void __launch_bounds__(SCAN_B) scan_pass1() {
    __shared__ int ws[32];
    int b = blockIdx.x, t = threadIdx.x;
    int i = b * SCAN_B + t;
    int v = (i < NS) ? g_counts[i] : 0;
#pragma unroll
    for (int o = 16; o; o >>= 1) v += __shfl_xor_sync(0xFFFFFFFFu, v, o);
    if ((t & 31) == 0) ws[t >> 5] = v;
    __syncthreads();
    if (t < 32) {
        int x = ws[t];
#pragma unroll
        for (int o = 16; o; o >>= 1) x += __shfl_xor_sync(0xFFFFFFFFu, x, o);
        if (t == 0) g_bsum[b] = x;
    }
}
__global__ void scan_pass2() {
    __shared__ int sh[128];
    int t = threadIdx.x;
    int orig = (t < NBLK) ? g_bsum[t] : 0;
    sh[t] = orig;
    __syncthreads();
    for (int o = 1; o < 128; o <<= 1) {
        int v = (t >= o) ? sh[t - o] : 0;
        __syncthreads();
        sh[t] += v;
        __syncthreads();
    }
    if (t < NBLK) g_bsum[t] = sh[t] - orig;
}
__global__ void __launch_bounds__(SCAN_B) scan_pass3() {
    __shared__ int ws[32];
    int b = blockIdx.x, t = threadIdx.x;
    int lane = t & 31, w = t >> 5;
    int i = b * SCAN_B + t;
    int v = (i < NS) ? g_counts[i] : 0;
    int x = v;
#pragma unroll
    for (int o = 1; o < 32; o <<= 1) {
        int y = __shfl_up_sync(0xFFFFFFFFu, x, o);
        if (lane >= o) x += y;
    }
    if (lane == 31) ws[w] = x;
    __syncthreads();
    if (w == 0) {
        int sv = ws[lane];
#pragma unroll
        for (int o = 1; o < 32; o <<= 1) {
            int y = __shfl_up_sync(0xFFFFFFFFu, sv, o);
            if (lane >= o) sv += y;
        }
        ws[lane] = sv;
    }
    __syncthreads();
    int incl = x + (w > 0 ? ws[w - 1] : 0) + g_bsum[b];
    if (i < NS) {
        g_offsets[i + 1] = incl;
        g_cursor[i] = incl - v;
    }
    if (b == 0 && t == 0) g_offsets[0] = 0;
}
__global__ void scatter_kernel(const int* __restrict__ edge_src,
                               const int* __restrict__ edge_dst) {
    int i = blockIdx.x * blockDim.x + threadIdx.x;
    if (i >= EDG) return;
    int dst = edge_dst[i];
    int pos = atomicAdd(&g_cursor[dst], 1);
    g_csr_src[pos] = edge_src[i];
}

// ---------------- attention: warp per dst, lane = (head, quarter) ----------------
__global__ void __launch_bounds__(256) attn_kernel() {
    int gw = (blockIdx.x * blockDim.x + threadIdx.x) >> 5;
    if (gw >= NS) return;
    int lane = threadIdx.x & 31;
    int off = (lane >> 2) * 32 + (lane & 3) * 8;

    int beg = g_offsets[gw];
    int end = g_offsets[gw + 1];

    const float* dfp = g_df + (size_t)gw * 256 + off;
    float4 d0 = *(const float4*)(dfp);
    float4 d1 = *(const float4*)(dfp + 4);

    float m = -1e30f, den = 0.0f;
    float4 a0 = make_float4(0.f, 0.f, 0.f, 0.f);
    float4 a1 = make_float4(0.f, 0.f, 0.f, 0.f);

    int e = beg;
    for (; e + 2 <= end; e += 2) {
        int s0 = __ldg(&g_csr_src[e]);
        int s1 = __ldg(&g_csr_src[e + 1]);
        const float* zp0 = g_z + (size_t)s0 * 256 + off;
        const float* zp1 = g_z + (size_t)s1 * 256 + off;
        float4 x0 = __ldg((const float4*)zp0);
        float4 x1 = __ldg((const float4*)(zp0 + 4));
        float4 y0 = __ldg((const float4*)zp1);
        float4 y1 = __ldg((const float4*)(zp1 + 4));

        float sa = x0.x * d0.x + x0.y * d0.y + x0.z * d0.z + x0.w * d0.w
                 + x1.x * d1.x + x1.y * d1.y + x1.z * d1.z + x1.w * d1.w;
        float sb = y0.x * d0.x + y0.y * d0.y + y0.z * d0.z + y0.w * d0.w
                 + y1.x * d1.x + y1.y * d1.y + y1.z * d1.z + y1.w * d1.w;
        sa += __shfl_xor_sync(0xFFFFFFFFu, sa, 1);
        sb += __shfl_xor_sync(0xFFFFFFFFu, sb, 1);
        sa += __shfl_xor_sync(0xFFFFFFFFu, sa, 2);
        sb += __shfl_xor_sync(0xFFFFFFFFu, sb, 2);

        {
            float mn = fmaxf(m, sa);
            float sc = __expf(m - mn);
            float w  = __expf(sa - mn);
            den = den * sc + w;
            a0.x = a0.x * sc + w * x0.x; a0.y = a0.y * sc + w * x0.y;
            a0.z = a0.z * sc + w * x0.z; a0.w = a0.w * sc + w * x0.w;
            a1.x = a1.x * sc + w * x1.x; a1.y = a1.y * sc + w * x1.y;
            a1.z = a1.z * sc + w * x1.z; a1.w = a1.w * sc + w * x1.w;
            m = mn;
        }
        {
            float mn = fmaxf(m, sb);
            float sc = __expf(m - mn);
            float w  = __expf(sb - mn);
            den = den * sc + w;
            a0.x = a0.x * sc + w * y0.x; a0.y = a0.y * sc + w * y0.y;
            a0.z = a0.z * sc + w * y0.z; a0.w = a0.w * sc + w * y0.w;
            a1.x = a1.x * sc + w * y1.x; a1.y = a1.y * sc + w * y1.y;
            a1.z = a1.z * sc + w * y1.z; a1.w = a1.w * sc + w * y1.w;
            m = mn;
        }
    }
    for (; e < end; e++) {
        int s0 = __ldg(&g_csr_src[e]);
        const float* zp0 = g_z + (size_t)s0 * 256 + off;
        float4 x0 = __ldg((const float4*)zp0);
        float4 x1 = __ldg((const float4*)(zp0 + 4));
        float sa = x0.x * d0.x + x0.y * d0.y + x0.z * d0.z + x0.w * d0.w
                 + x1.x * d1.x + x1.y * d1.y + x1.z * d1.z + x1.w * d1.w;
        sa += __shfl_xor_sync(0xFFFFFFFFu, sa, 1);
        sa += __shfl_xor_sync(0xFFFFFFFFu, sa, 2);
        float mn = fmaxf(m, sa);
        float sc = __expf(m - mn);
        float w  = __expf(sa - mn);
        den = den * sc + w;
        a0.x = a0.x * sc + w * x0.x; a0.y = a0.y * sc + w * x0.y;
        a0.z = a0.z * sc + w * x0.z; a0.w = a0.w * sc + w * x0.w;
        a1.x = a1.x * sc + w * x1.x; a1.y = a1.y * sc + w * x1.y;
        a1.z = a1.z * sc + w * x1.z; a1.w = a1.w * sc + w * x1.w;
        m = mn;
    }

    float inv = 1.0f / den;
    float v[8];
    v[0] = a0.x * inv; v[1] = a0.y * inv; v[2] = a0.z * inv; v[3] = a0.w * inv;
    v[4] = a1.x * inv; v[5] = a1.y * inv; v[6] = a1.z * inv; v[7] = a1.w * inv;
    f16 hi[8], lo[8];
#pragma unroll
    for (int i = 0; i < 8; i++) {
        v[i] = (v[i] > 0.0f) ? v[i] : expm1f(v[i]);  // ELU(alpha=1)
        split2(v[i], hi[i], lo[i]);
    }
    size_t ob = (size_t)gw * 256 + off;
    *(uint4*)(g_hh + ob) = make_uint4(pk2(hi[0], hi[1]), pk2(hi[2], hi[3]),
                                      pk2(hi[4], hi[5]), pk2(hi[6], hi[7]));
    *(uint4*)(g_hl + ob) = make_uint4(pk2(lo[0], lo[1]), pk2(lo[2], lo[3]),
                                      pk2(lo[4], lo[5]), pk2(lo[6], lo[7]));
}

// ---------------- layernorm: warp per row, lane owns 8 contiguous cols ----------------
__global__ void ln_kernel(const float* __restrict__ x,
                          const float* __restrict__ gam,
                          const float* __restrict__ bet) {
    int row = (blockIdx.x * blockDim.x + threadIdx.x) >> 5;
    if (row >= NS) return;
    int lane = threadIdx.x & 31;
    const float* xp = x + (size_t)row * 256 + lane * 8;
    float4 va = *(const float4*)xp;
    float4 vb = *(const float4*)(xp + 4);
    float v[8] = {va.x, va.y, va.z, va.w, vb.x, vb.y, vb.z, vb.w};
    float s = 0.0f, s2 = 0.0f;
#pragma unroll
    for (int r = 0; r < 8; r++) { s += v[r]; s2 += v[r] * v[r]; }
#pragma unroll
    for (int o = 16; o > 0; o >>= 1) {
        s  += __shfl_xor_sync(0xFFFFFFFFu, s, o);
        s2 += __shfl_xor_sync(0xFFFFFFFFu, s2, o);
    }
    float mean = s * (1.0f / 256.0f);
    float var = s2 * (1.0f / 256.0f) - mean * mean;
    float inv = rsqrtf(var + 1e-6f);
    float4 ga = *(const float4*)(gam + lane * 8);
    float4 gb = *(const float4*)(gam + lane * 8 + 4);
    float4 ba = *(const float4*)(bet + lane * 8);
    float4 bb = *(const float4*)(bet + lane * 8 + 4);
    float g[8] = {ga.x, ga.y, ga.z, ga.w, gb.x, gb.y, gb.z, gb.w};
    float bt[8] = {ba.x, ba.y, ba.z, ba.w, bb.x, bb.y, bb.z, bb.w};
    f16 hi[8], lo[8];
#pragma unroll
    for (int r = 0; r < 8; r++) {
        float y = (v[r] - mean) * inv * g[r] + bt[r];
        split2(y, hi[r], lo[r]);
    }
    size_t ob = (size_t)row * 256 + lane * 8;
    *(uint4*)(g_xnh + ob) = make_uint4(pk2(hi[0], hi[1]), pk2(hi[2], hi[3]),
                                       pk2(hi[4], hi[5]), pk2(hi[6], hi[7]));
    *(uint4*)(g_xnl + ob) = make_uint4(pk2(lo[0], lo[1]), pk2(lo[2], lo[3]),
                                       pk2(lo[4], lo[5]), pk2(lo[6], lo[7]));
}

// ---------------- launch ----------------
extern "C" void kernel_launch(void* const* d_in, const int* in_sizes, int n_in,
                              void* d_out, int out_size) {
    const float* s_in      = (const float*)d_in[0];
    const float* e_in      = (const float*)d_in[1];
    const float* dst_feat  = (const float*)d_in[2];
    const float* fc_w      = (const float*)d_in[3];
    const float* dstfeat_w = (const float*)d_in[4];
    const float* proj_w    = (const float*)d_in[5];
    const float* proj_b    = (const float*)d_in[6];
    const float* ln_g      = (const float*)d_in[7];
    const float* ln_b      = (const float*)d_in[8];
    const float* w1        = (const float*)d_in[9];
    const float* b1        = (const float*)d_in[10];
    const float* w2        = (const float*)d_in[11];
    const float* b2        = (const float*)d_in[12];
    const int*   edge_src  = (const int*)d_in[13];
    const int*   edge_dst  = (const int*)d_in[14];
    float* out = (float*)d_out;

    float *zp, *dfp, *xp;
    cudaGetSymbolAddress((void**)&zp,  g_z);
    cudaGetSymbolAddress((void**)&dfp, g_df);
    cudaGetSymbolAddress((void**)&xp,  g_x);
    bf16 *eh, *el, *fh, *fl, *wzh, *wzl, *wdh, *wdl;
    cudaGetSymbolAddress((void**)&eh,  g_eh);  cudaGetSymbolAddress((void**)&el,  g_el);
    cudaGetSymbolAddress((void**)&fh,  g_fh);  cudaGetSymbolAddress((void**)&fl,  g_fl);
    cudaGetSymbolAddress((void**)&wzh, g_wzh); cudaGetSymbolAddress((void**)&wzl, g_wzl);
    cudaGetSymbolAddress((void**)&wdh, g_wdh); cudaGetSymbolAddress((void**)&wdl, g_wdl);
    f16 *sh, *sl, *hh, *hl, *xnh, *xnl, *th, *tl, *pw, *w1p, *w2p;
    cudaGetSymbolAddress((void**)&sh,  g_sh);  cudaGetSymbolAddress((void**)&sl,  g_sl);
    cudaGetSymbolAddress((void**)&hh,  g_hh);  cudaGetSymbolAddress((void**)&hl,  g_hl);
    cudaGetSymbolAddress((void**)&xnh, g_xnh); cudaGetSymbolAddress((void**)&xnl, g_xnl);
    cudaGetSymbolAddress((void**)&th,  g_th);  cudaGetSymbolAddress((void**)&tl,  g_tl);
    cudaGetSymbolAddress((void**)&pw,  g_pw);
    cudaGetSymbolAddress((void**)&w1p, g_w1);
    cudaGetSymbolAddress((void**)&w2p, g_w2);

    cudaFuncSetAttribute(mma_gemm<bf16, 3, 0, false, false, false>,
                         cudaFuncAttributeMaxDynamicSharedMemorySize, SMEM3);
    cudaFuncSetAttribute(mma_gemm<f16, 2, 0, true, false, false>,
                         cudaFuncAttributeMaxDynamicSharedMemorySize, SMEM2);
    cudaFuncSetAttribute(mma_gemm<f16, 2, 1, true, false, true>,
                         cudaFuncAttributeMaxDynamicSharedMemorySize, SMEM2);
    cudaFuncSetAttribute(mma_gemm<f16, 2, 0, true, true, false>,
                         cudaFuncAttributeMaxDynamicSharedMemorySize, SMEM2);

    const int TB = 256;
    const int MB = (NS + 127) / 128;  // 782

    // launch order puts z-GEMM at index 3 (the launch ncu captures)
    act_split<bf16><<<(NE * D / 4 + TB - 1) / TB, TB>>>(e_in, eh, el, NE * D);         // 0
    repack_split<<<(256 * 256 + TB - 1) / TB, TB>>>(fc_w, wzh, wzl, 256);              // 1
    act_split<bf16><<<(NS * FEAT / 4 + TB - 1) / TB, TB>>>(dst_feat, fh, fl, NS * FEAT); // 2
    // 3: z = e @ Wz  [NE,256]  (bf16 3-pass)
    mma_gemm<bf16, 3, 0, false, false, false><<<dim3(2, MB), TB, SMEM3>>>(
        eh, el, 256, eh, el, 256, D, wzh, wzl, 256,
        nullptr, nullptr, 0, zp, nullptr, nullptr, 256, NE, 256);
    repack_split<<<(64 * 256 + TB - 1) / TB, TB>>>(dstfeat_w, wdh, wdl, 64);           // 4
    // 5: df = dst_feat @ Wd  [NS,256]  (bf16 3-pass)
    mma_gemm<bf16, 3, 0, false, false, false><<<dim3(2, MB), TB, SMEM3>>>(
        fh, fl, 64, fh, fl, 64, FEAT, wdh, wdl, 64,
        nullptr, nullptr, 0, dfp, nullptr, nullptr, 256, NS, 64);

    // remaining conversions
    act_split<f16><<<(NS * D / 4 + TB - 1) / TB, TB>>>(s_in, sh, sl, NS * D);
    wsplit_t16<<<(512 * 256 + TB - 1) / TB, TB>>>(proj_w, pw, 512, 256);
    wsplit_t16<<<(256 * 512 + TB - 1) / TB, TB>>>(w1, w1p, 256, 512);
    wsplit_t16<<<(512 * 256 + TB - 1) / TB, TB>>>(w2, w2p, 512, 256);

    // CSR build by dst (parallel decoupled scan)
    zero_counts<<<(NS + TB - 1) / TB, TB>>>();
    hist_kernel<<<(EDG + TB - 1) / TB, TB>>>(edge_dst);
    scan_pass1<<<NBLK, SCAN_B>>>();
    scan_pass2<<<1, 128>>>();
    scan_pass3<<<NBLK, SCAN_B>>>();
    scatter_kernel<<<(EDG + TB - 1) / TB, TB>>>(edge_src, edge_dst);

    // attention + ELU -> h split fp16
    attn_kernel<<<(NS * 32 + TB - 1) / TB, TB>>>();

    // proj: [h | s] @ proj_w + b -> g_x (fp32)  (fp16 2-pass)
    mma_gemm<f16, 2, 0, true, false, false><<<dim3(2, MB), TB, SMEM2>>>(
        hh, hl, 256, sh, sl, 256, 256, pw, nullptr, 512,
        proj_b, nullptr, 0, xp, nullptr, nullptr, 256, NS, 512);

    // layernorm -> xn split fp16
    ln_kernel<<<(NS * 32 + TB - 1) / TB, TB>>>(xp, ln_g, ln_b);

    // ffn1: gelu(xn @ w1 + b1) -> t split fp16  (fp16 2-pass)
    mma_gemm<f16, 2, 1, true, false, true><<<dim3(4, MB), TB, SMEM2>>>(
        xnh, xnl, 256, xnh, xnl, 256, 256, w1p, nullptr, 256,
        b1, nullptr, 0, nullptr, th, tl, 512, NS, 256);

    // ffn2: t @ w2 + b2 + g_x -> out (fp32)  (fp16 2-pass)
    mma_gemm<f16, 2, 0, true, true, false><<<dim3(2, MB), TB, SMEM2>>>(
        th, tl, 512, th, tl, 512, 512, w2p, nullptr, 512,
        b2, xp, 256, out, nullptr, nullptr, 256, NS, 512);
}

// round 11
// speedup vs baseline: 1.5109x; 1.0028x over previous
#include <cuda_runtime.h>
#include <cuda_bf16.h>
#include <cuda_fp16.h>
#include <cstdint>
#include <math.h>

// Problem constants (fixed by the dataset)
#define NS 100000
#define NE 100000
#define EDG 1600000
#define D 256
#define H 8
#define HD 32
#define FEAT 64
#define DFF 512

#define SCAN_B 1024
#define NBLK ((NS + SCAN_B - 1) / SCAN_B)   // 98

// smem tile geometry: 32 elems of k per row, padded to 40 (80 B)
#define KP 40
#define ROWB 80
#define MATB (128 * ROWB)          // 10240 B per matrix
#define SMEM_BF3 (2 * 4 * MATB)    // 81920 B: bf16 3-pass, 2 stages (Ah,Al,Bh,Bl)
#define SMEM_FP2 (3 * 3 * MATB)    // 92160 B: fp16 2-pass, 3 stages (Ah,Al,Bh)

typedef __nv_bfloat16 bf16;
typedef __half f16;

// ---------------- device scratch (no allocations allowed) ----------------
__device__ float g_z[(size_t)NE * D];
__device__ float g_df[(size_t)NS * D];
__device__ float g_x[(size_t)NS * D];
// bf16 split (pre-softmax path)
__device__ bf16 g_eh[(size_t)NE * D],    g_el[(size_t)NE * D];
__device__ bf16 g_fh[(size_t)NS * FEAT], g_fl[(size_t)NS * FEAT];
__device__ bf16 g_wzh[256 * 256], g_wzl[256 * 256];
__device__ bf16 g_wdh[256 * 64],  g_wdl[256 * 64];
// fp16 split (post-softmax path)
__device__ f16 g_sh[(size_t)NS * D],   g_sl[(size_t)NS * D];
__device__ f16 g_hh[(size_t)NS * D],   g_hl[(size_t)NS * D];
__device__ f16 g_xnh[(size_t)NS * D],  g_xnl[(size_t)NS * D];
__device__ f16 g_th[(size_t)NS * DFF], g_tl[(size_t)NS * DFF];
// fp16 plain transposed weights Wt[n][k]
__device__ f16 g_pw[256 * 512];
__device__ f16 g_w1[512 * 256];
__device__ f16 g_w2[256 * 512];
// CSR
__device__ int g_counts[NS];
__device__ int g_offsets[NS + 1];
__device__ int g_cursor[NS];
__device__ int g_csr_src[EDG];
__device__ int g_bsum[NBLK];

// ---------------- small helpers ----------------
__device__ __forceinline__ float gelu_fast(float x) {
    const float c = 0.7978845608028654f;
    float u = c * (x + 0.044715f * x * x * x);
    float e = __expf(2.0f * u);
    float th = 1.0f - 2.0f / (e + 1.0f);
    return 0.5f * x * (1.0f + th);
}
__device__ __forceinline__ uint32_t smem_u32(const void* p) {
    uint32_t a;
    asm("{ .reg .u64 t; cvta.to.shared.u64 t, %1; cvt.u32.u64 %0, t; }" : "=r"(a) : "l"(p));
    return a;
}
__device__ __forceinline__ void ldm_x4(uint32_t* r, uint32_t addr) {
    asm volatile("ldmatrix.sync.aligned.m8n8.x4.shared.b16 {%0,%1,%2,%3}, [%4];"
                 : "=r"(r[0]), "=r"(r[1]), "=r"(r[2]), "=r"(r[3]) : "r"(addr));
}
__device__ __forceinline__ uint32_t pk2(bf16 a, bf16 b) {
    __nv_bfloat162 t(a, b); return *(uint32_t*)&t;
}
__device__ __forceinline__ uint32_t pk2(f16 a, f16 b) {
    __half2 t(a, b); return *(uint32_t*)&t;
}
__device__ __forceinline__ void split2(float x, bf16& hi, bf16& lo) {
    hi = __float2bfloat16_rn(x);
    lo = __float2bfloat16_rn(x - __bfloat162float(hi));
}
__device__ __forceinline__ void split2(float x, f16& hi, f16& lo) {
    hi = __float2half_rn(x);
    lo = __float2half_rn(x - __half2float(hi));
}
template <typename T>
__device__ __forceinline__ void mma_t(float* c, const uint32_t* a, const uint32_t* b);
template <>
__device__ __forceinline__ void mma_t<bf16>(float* c, const uint32_t* a, const uint32_t* b) {
    asm volatile(
        "mma.sync.aligned.m16n8k16.row.col.f32.bf16.bf16.f32 "
        "{%0,%1,%2,%3}, {%4,%5,%6,%7}, {%8,%9}, {%0,%1,%2,%3};"
        : "+f"(c[0]), "+f"(c[1]), "+f"(c[2]), "+f"(c[3])
        : "r"(a[0]), "r"(a[1]), "r"(a[2]), "r"(a[3]), "r"(b[0]), "r"(b[1]));
}
template <>
__device__ __forceinline__ void mma_t<f16>(float* c, const uint32_t* a, const uint32_t* b) {
    asm volatile(
        "mma.sync.aligned.m16n8k16.row.col.f32.f16.f16.f32 "
        "{%0,%1,%2,%3}, {%4,%5,%6,%7}, {%8,%9}, {%0,%1,%2,%3};"
        : "+f"(c[0]), "+f"(c[1]), "+f"(c[2]), "+f"(c[3])
        : "r"(a[0]), "r"(a[1]), "r"(a[2]), "r"(a[3]), "r"(b[0]), "r"(b[1]));
}
__device__ __forceinline__ void cpa16(uint32_t dst, const void* src, bool pred) {
    int sz = pred ? 16 : 0;
    asm volatile("cp.async.cg.shared.global [%0], [%1], 16, %2;"
                 :: "r"(dst), "l"(src), "r"(sz) : "memory");
}

// ---------------- conversion kernels ----------------
template <typename T>
__global__ void act_split(const float* __restrict__ in, T* __restrict__ hi,
                          T* __restrict__ lo, int n) {
    int i = 4 * (blockIdx.x * blockDim.x + threadIdx.x);
    if (i >= n) return;
    float4 v = *(const float4*)(in + i);
    T h0, l0, h1, l1, h2, l2, h3, l3;
    split2(v.x, h0, l0); split2(v.y, h1, l1);
    split2(v.z, h2, l2); split2(v.w, h3, l3);
    *(uint2*)(hi + i) = make_uint2(pk2(h0, h1), pk2(h2, h3));
    *(uint2*)(lo + i) = make_uint2(pk2(l0, l1), pk2(l2, l3));
}
__global__ void wsplit_t16(const float* __restrict__ w, f16* __restrict__ o, int K, int N) {
    int idx = blockIdx.x * blockDim.x + threadIdx.x;
    if (idx >= K * N) return;
    int k = idx / N, n = idx % N;
    o[(size_t)n * K + k] = __float2half_rn(w[idx]);
}
__global__ void repack_split(const float* __restrict__ w, bf16* __restrict__ hi,
                             bf16* __restrict__ lo, int K) {
    int idx = blockIdx.x * blockDim.x + threadIdx.x;
    if (idx >= K * 256) return;
    int n = idx / K, k = idx % K;
    bf16 h, l;
    split2(w[(n >> 5) * (K * 32) + k * 32 + (n & 31)], h, l);
    hi[idx] = h;
    lo[idx] = l;
}

// ================= multistage cp.async split GEMM =================
// PASSES==3 (bf16): Ah*Bh + Al*Bh + Ah*Bl.  PASSES==2 (fp16): Ah*B + Al*B.
// NSTAGE-deep pipeline, ONE __syncthreads per k-tile, uniform commit groups.
template <typename T, int PASSES, int NSTAGE, int ACT, bool BIAS, bool RES, bool OSPLIT>
__global__ void __launch_bounds__(256, 2) mma_gemm(
    const T* __restrict__ Ah0, const T* __restrict__ Al0, int lda0,
    const T* __restrict__ Ah1, const T* __restrict__ Al1, int lda1, int ksplit,
    const T* __restrict__ Bh, const T* __restrict__ Bl, int ldbk,
    const float* __restrict__ bias,
    const float* __restrict__ res, int ldr,
    float* __restrict__ C, T* __restrict__ Ch, T* __restrict__ Cl, int ldc,
    int M, int K)
{
    constexpr int NMAT = (PASSES == 3) ? 4 : 3;
    constexpr int STB = NMAT * MATB;
    extern __shared__ char dsm[];
    uint32_t sb = smem_u32(dsm);

    int t = threadIdx.x;
    int lane = t & 31, wid = t >> 5;
    int m0 = blockIdx.y * 128;
    int n0 = blockIdx.x * 128;
    int wm = wid & 3;
    int wn = wid >> 2;

    float acc[2][8][4];
#pragma unroll
    for (int i = 0; i < 2; i++)
#pragma unroll
        for (int j = 0; j < 8; j++)
#pragma unroll
            for (int q = 0; q < 4; q++) acc[i][j][q] = 0.0f;

    uint32_t a_off = (uint32_t)(((wm * 32 + (lane & 15)) * KP + (lane >> 4) * 8) * 2);
    uint32_t b_off = (uint32_t)(((wn * 64 + (lane & 7) + (lane >> 4) * 8) * KP
                                 + ((lane >> 3) & 1) * 8) * 2);

    int p_row = t >> 1;
    int p_c0 = (t & 1) * 2;
    bool a_ok = (m0 + p_row) < M;
    const int KT = K >> 5;

    // issue copies for k-tile index kt into stage slot; always commits a group
    auto prefetch = [&](int kt) {
        if (kt < KT) {
            int k0 = kt * 32;
            int stage = kt % NSTAGE;
            const T *AhS, *AlS; int lda, koff;
            if (k0 < ksplit) { AhS = Ah0; AlS = Al0; lda = lda0; koff = k0; }
            else             { AhS = Ah1; AlS = Al1; lda = lda1; koff = k0 - ksplit; }
            const T* pah = AhS + (size_t)(m0 + p_row) * lda + koff;
            const T* pal = AlS + (size_t)(m0 + p_row) * lda + koff;
            const T* pbh = Bh + (size_t)(n0 + p_row) * ldbk + k0;
            uint32_t base = sb + stage * STB + p_row * ROWB;
#pragma unroll
            for (int ci = 0; ci < 2; ci++) {
                int c = p_c0 + ci;
                cpa16(base + c * 16,            pah + c * 8, a_ok);
                cpa16(base + MATB + c * 16,     pal + c * 8, a_ok);
                cpa16(base + 2 * MATB + c * 16, pbh + c * 8, true);
                if (PASSES == 3) {
                    const T* pbl = Bl + (size_t)(n0 + p_row) * ldbk + k0;
                    cpa16(base + 3 * MATB + c * 16, pbl + c * 8, true);
                }
            }
        }
        asm volatile("cp.async.commit_group;" ::: "memory");
    };

    // prologue: stages 0 .. NSTAGE-2
#pragma unroll
    for (int s = 0; s < NSTAGE - 1; s++) prefetch(s);

    for (int kt = 0; kt < KT; kt++) {
        // wait for stage kt (NSTAGE-2 groups may remain pending)
        if (NSTAGE == 2) asm volatile("cp.async.wait_group 0;" ::: "memory");
        else             asm volatile("cp.async.wait_group 1;" ::: "memory");
        __syncthreads();  // also proves all warps done reading the slot we refill next

        prefetch(kt + NSTAGE - 1);

        uint32_t s0 = sb + (kt % NSTAGE) * STB;
        uint32_t sAh = s0, sAl = s0 + MATB, sBh = s0 + 2 * MATB;

#pragma unroll
        for (int ks = 0; ks < 2; ks++) {
            uint32_t koffb = (uint32_t)(ks * 32);
            uint32_t a_hi[2][4], a_lo[2][4], b[4][4];
            ldm_x4(a_hi[0], sAh + a_off + koffb);
            ldm_x4(a_hi[1], sAh + a_off + koffb + 16 * KP * 2);
            ldm_x4(a_lo[0], sAl + a_off + koffb);
            ldm_x4(a_lo[1], sAl + a_off + koffb + 16 * KP * 2);
#pragma unroll
            for (int ni2 = 0; ni2 < 4; ni2++)
                ldm_x4(b[ni2], sBh + b_off + koffb + ni2 * 16 * KP * 2);
            // pass 1: Ah * Bh
#pragma unroll
            for (int mi = 0; mi < 2; mi++)
#pragma unroll
                for (int ni = 0; ni < 8; ni++)
                    mma_t<T>(acc[mi][ni], a_hi[mi], &b[ni >> 1][(ni & 1) * 2]);
            // pass 2: Al * Bh
#pragma unroll
            for (int mi = 0; mi < 2; mi++)
#pragma unroll
                for (int ni = 0; ni < 8; ni++)
                    mma_t<T>(acc[mi][ni], a_lo[mi], &b[ni >> 1][(ni & 1) * 2]);
            if (PASSES == 3) {
                uint32_t sBl = s0 + 3 * MATB;
#pragma unroll
                for (int ni2 = 0; ni2 < 4; ni2++)
                    ldm_x4(b[ni2], sBl + b_off + koffb + ni2 * 16 * KP * 2);
#pragma unroll
                for (int mi = 0; mi < 2; mi++)
#pragma unroll
                    for (int ni = 0; ni < 8; ni++)
                        mma_t<T>(acc[mi][ni], a_hi[mi], &b[ni >> 1][(ni & 1) * 2]);
            }
        }
    }

    // ---- epilogue ----
#pragma unroll
    for (int mi = 0; mi < 2; mi++) {
#pragma unroll
        for (int ni = 0; ni < 8; ni++) {
            int cc = n0 + wn * 64 + ni * 8 + (lane & 3) * 2;
#pragma unroll
            for (int hh = 0; hh < 2; hh++) {
                int m = m0 + wm * 32 + mi * 16 + (lane >> 2) + hh * 8;
                if (m >= M) continue;
                float v0 = acc[mi][ni][hh * 2 + 0];
                float v1 = acc[mi][ni][hh * 2 + 1];
                if (BIAS) { v0 += bias[cc]; v1 += bias[cc + 1]; }
                if (ACT == 1) { v0 = gelu_fast(v0); v1 = gelu_fast(v1); }
                if (RES) {
                    const float* rp = res + (size_t)m * ldr + cc;
                    v0 += rp[0]; v1 += rp[1];
                }
                if (OSPLIT) {
                    T h0, l0, h1, l1;
                    split2(v0, h0, l0);
                    split2(v1, h1, l1);
                    *(uint32_t*)(Ch + (size_t)m * ldc + cc) = pk2(h0, h1);
                    *(uint32_t*)(Cl + (size_t)m * ldc + cc) = pk2(l0, l1);
                } else {
                    *(float2*)(C + (size_t)m * ldc + cc) = make_float2(v0, v1);
                }
            }
        }
    }
}

// ---------------- CSR build ----------------
__global__ void zero_counts() {
    int i = blockIdx.x * blockDim.x + threadIdx.x;
    if (i < NS) g_counts[i] = 0;
}
__global__ void hist_kernel(const int* __restrict__ edge_dst) {
    int i = blockIdx.x * blockDim.x + threadIdx.x;
    if (i < EDG) atomicAdd(&g_counts[edge_dst[i]], 1);
}
__global__ void __launch_bounds__(SCAN_B) scan_pass1() {
    __shared__ int ws[32];
    int b = blockIdx.x, t = threadIdx.x;
    int i = b * SCAN_B + t;
    int v = (i < NS) ? g_counts[i] : 0;
#pragma unroll
    for (int o = 16; o; o >>= 1) v += __shfl_xor_sync(0xFFFFFFFFu, v, o);
    if ((t & 31) == 0) ws[t >> 5] = v;
    __syncthreads();
    if (t < 32) {
        int x = ws[t];
#pragma unroll
        for (int o = 16; o; o >>= 1) x += __shfl_xor_sync(0xFFFFFFFFu, x, o);
        if (t == 0) g_bsum[b] = x;
    }
}
__global__ void scan_pass2() {
    __shared__ int sh[128];
    int t = threadIdx.x;
    int orig = (t < NBLK) ? g_bsum[t] : 0;
    sh[t] = orig;
    __syncthreads();
    for (int o = 1; o < 128; o <<= 1) {
        int v = (t >= o) ? sh[t - o] : 0;
        __syncthreads();
        sh[t] += v;
        __syncthreads();
    }
    if (t < NBLK) g_bsum[t] = sh[t] - orig;
}
__global__ void __launch_bounds__(SCAN_B) scan_pass3() {
    __shared__ int ws[32];
    int b = blockIdx.x, t = threadIdx.x;
    int lane = t & 31, w = t >> 5;
    int i = b * SCAN_B + t;
    int v = (i < NS) ? g_counts[i] : 0;
    int x = v;
#pragma unroll
    for (int o = 1; o < 32; o <<= 1) {
        int y = __shfl_up_sync(0xFFFFFFFFu, x, o);
        if (lane >= o) x += y;
    }
    if (lane == 31) ws[w] = x;
    __syncthreads();
    if (w == 0) {
        int sv = ws[lane];
#pragma unroll
        for (int o = 1; o < 32; o <<= 1) {
            int y = __shfl_up_sync(0xFFFFFFFFu, sv, o);
            if (lane >= o) sv += y;
        }
        ws[lane] = sv;
    }
    __syncthreads();
    int incl = x + (w > 0 ? ws[w - 1] : 0) + g_bsum[b];
    if (i < NS) {
        g_offsets[i + 1] = incl;
        g_cursor[i] = incl - v;
    }
    if (b == 0 && t == 0) g_offsets[0] = 0;
}
__global__ void scatter_kernel(const int* __restrict__ edge_src,
                               const int* __restrict__ edge_dst) {
    int i = blockIdx.x * blockDim.x + threadIdx.x;
    if (i >= EDG) return;
    int dst = edge_dst[i];
    int pos = atomicAdd(&g_cursor[dst], 1);
    g_csr_src[pos] = edge_src[i];
}

// ---------------- attention: warp per dst, lane = (head, quarter) ----------------
__global__ void __launch_bounds__(256) attn_kernel() {
    int gw = (blockIdx.x * blockDim.x + threadIdx.x) >> 5;
    if (gw >= NS) return;
    int lane = threadIdx.x & 31;
    int off = (lane >> 2) * 32 + (lane & 3) * 8;

    int beg = g_offsets[gw];
    int end = g_offsets[gw + 1];

    const float* dfp = g_df + (size_t)gw * 256 + off;
    float4 d0 = *(const float4*)(dfp);
    float4 d1 = *(const float4*)(dfp + 4);

    float m = -1e30f, den = 0.0f;
    float4 a0 = make_float4(0.f, 0.f, 0.f, 0.f);
    float4 a1 = make_float4(0.f, 0.f, 0.f, 0.f);

    int e = beg;
    for (; e + 2 <= end; e += 2) {
        int s0 = __ldg(&g_csr_src[e]);
        int s1 = __ldg(&g_csr_src[e + 1]);
        const float* zp0 = g_z + (size_t)s0 * 256 + off;
        const float* zp1 = g_z + (size_t)s1 * 256 + off;
        float4 x0 = __ldg((const float4*)zp0);
        float4 x1 = __ldg((const float4*)(zp0 + 4));
        float4 y0 = __ldg((const float4*)zp1);
        float4 y1 = __ldg((const float4*)(zp1 + 4));

        float sa = x0.x * d0.x + x0.y * d0.y + x0.z * d0.z + x0.w * d0.w
                 + x1.x * d1.x + x1.y * d1.y + x1.z * d1.z + x1.w * d1.w;
        float sb = y0.x * d0.x + y0.y * d0.y + y0.z * d0.z + y0.w * d0.w
                 + y1.x * d1.x + y1.y * d1.y + y1.z * d1.z + y1.w * d1.w;
        sa += __shfl_xor_sync(0xFFFFFFFFu, sa, 1);
        sb += __shfl_xor_sync(0xFFFFFFFFu, sb, 1);
        sa += __shfl_xor_sync(0xFFFFFFFFu, sa, 2);
        sb += __shfl_xor_sync(0xFFFFFFFFu, sb, 2);

        {
            float mn = fmaxf(m, sa);
            float sc = __expf(m - mn);
            float w  = __expf(sa - mn);
            den = den * sc + w;
            a0.x = a0.x * sc + w * x0.x; a0.y = a0.y * sc + w * x0.y;
            a0.z = a0.z * sc + w * x0.z; a0.w = a0.w * sc + w * x0.w;
            a1.x = a1.x * sc + w * x1.x; a1.y = a1.y * sc + w * x1.y;
            a1.z = a1.z * sc + w * x1.z; a1.w = a1.w * sc + w * x1.w;
            m = mn;
        }
        {
            float mn = fmaxf(m, sb);
            float sc = __expf(m - mn);
            float w  = __expf(sb - mn);
            den = den * sc + w;
            a0.x = a0.x * sc + w * y0.x; a0.y = a0.y * sc + w * y0.y;
            a0.z = a0.z * sc + w * y0.z; a0.w = a0.w * sc + w * y0.w;
            a1.x = a1.x * sc + w * y1.x; a1.y = a1.y * sc + w * y1.y;
            a1.z = a1.z * sc + w * y1.z; a1.w = a1.w * sc + w * y1.w;
            m = mn;
        }
    }
    for (; e < end; e++) {
        int s0 = __ldg(&g_csr_src[e]);
        const float* zp0 = g_z + (size_t)s0 * 256 + off;
        float4 x0 = __ldg((const float4*)zp0);
        float4 x1 = __ldg((const float4*)(zp0 + 4));
        float sa = x0.x * d0.x + x0.y * d0.y + x0.z * d0.z + x0.w * d0.w
                 + x1.x * d1.x + x1.y * d1.y + x1.z * d1.z + x1.w * d1.w;
        sa += __shfl_xor_sync(0xFFFFFFFFu, sa, 1);
        sa += __shfl_xor_sync(0xFFFFFFFFu, sa, 2);
        float mn = fmaxf(m, sa);
        float sc = __expf(m - mn);
        float w  = __expf(sa - mn);
        den = den * sc + w;
        a0.x = a0.x * sc + w * x0.x; a0.y = a0.y * sc + w * x0.y;
        a0.z = a0.z * sc + w * x0.z; a0.w = a0.w * sc + w * x0.w;
        a1.x = a1.x * sc + w * x1.x; a1.y = a1.y * sc + w * x1.y;
        a1.z = a1.z * sc + w * x1.z; a1.w = a1.w * sc + w * x1.w;
        m = mn;
    }

    float inv = 1.0f / den;
    float v[8];
    v[0] = a0.x * inv; v[1] = a0.y * inv; v[2] = a0.z * inv; v[3] = a0.w * inv;
    v[4] = a1.x * inv; v[5] = a1.y * inv; v[6] = a1.z * inv; v[7] = a1.w * inv;
    f16 hi[8], lo[8];
#pragma unroll
    for (int i = 0; i < 8; i++) {
        v[i] = (v[i] > 0.0f) ? v[i] : expm1f(v[i]);  // ELU(alpha=1)
        split2(v[i], hi[i], lo[i]);
    }
    size_t ob = (size_t)gw * 256 + off;
    *(uint4*)(g_hh + ob) = make_uint4(pk2(hi[0], hi[1]), pk2(hi[2], hi[3]),
                                      pk2(hi[4], hi[5]), pk2(hi[6], hi[7]));
    *(uint4*)(g_hl + ob) = make_uint4(pk2(lo[0], lo[1]), pk2(lo[2], lo[3]),
                                      pk2(lo[4], lo[5]), pk2(lo[6], lo[7]));
}

// ---------------- layernorm: warp per row, lane owns 8 contiguous cols ----------------
__global__ void ln_kernel(const float* __restrict__ x,
                          const float* __restrict__ gam,
                          const float* __restrict__ bet) {
    int row = (blockIdx.x * blockDim.x + threadIdx.x) >> 5;
    if (row >= NS) return;
    int lane = threadIdx.x & 31;
    const float* xp = x + (size_t)row * 256 + lane * 8;
    float4 va = *(const float4*)xp;
    float4 vb = *(const float4*)(xp + 4);
    float v[8] = {va.x, va.y, va.z, va.w, vb.x, vb.y, vb.z, vb.w};
    float s = 0.0f, s2 = 0.0f;
#pragma unroll
    for (int r = 0; r < 8; r++) { s += v[r]; s2 += v[r] * v[r]; }
#pragma unroll
    for (int o = 16; o > 0; o >>= 1) {
        s  += __shfl_xor_sync(0xFFFFFFFFu, s, o);
        s2 += __shfl_xor_sync(0xFFFFFFFFu, s2, o);
    }
    float mean = s * (1.0f / 256.0f);
    float var = s2 * (1.0f / 256.0f) - mean * mean;
    float inv = rsqrtf(var + 1e-6f);
    float4 ga = *(const float4*)(gam + lane * 8);
    float4 gb = *(const float4*)(gam + lane * 8 + 4);
    float4 ba = *(const float4*)(bet + lane * 8);
    float4 bb = *(const float4*)(bet + lane * 8 + 4);
    float g[8] = {ga.x, ga.y, ga.z, ga.w, gb.x, gb.y, gb.z, gb.w};
    float bt[8] = {ba.x, ba.y, ba.z, ba.w, bb.x, bb.y, bb.z, bb.w};
    f16 hi[8], lo[8];
#pragma unroll
    for (int r = 0; r < 8; r++) {
        float y = (v[r] - mean) * inv * g[r] + bt[r];
        split2(y, hi[r], lo[r]);
    }
    size_t ob = (size_t)row * 256 + lane * 8;
    *(uint4*)(g_xnh + ob) = make_uint4(pk2(hi[0], hi[1]), pk2(hi[2], hi[3]),
                                       pk2(hi[4], hi[5]), pk2(hi[6], hi[7]));
    *(uint4*)(g_xnl + ob) = make_uint4(pk2(lo[0], lo[1]), pk2(lo[2], lo[3]),
                                       pk2(lo[4], lo[5]), pk2(lo[6], lo[7]));
}

// ---------------- launch ----------------
extern "C" void kernel_launch(void* const* d_in, const int* in_sizes, int n_in,
                              void* d_out, int out_size) {
    const float* s_in      = (const float*)d_in[0];
    const float* e_in      = (const float*)d_in[1];
    const float* dst_feat  = (const float*)d_in[2];
    const float* fc_w      = (const float*)d_in[3];
    const float* dstfeat_w = (const float*)d_in[4];
    const float* proj_w    = (const float*)d_in[5];
    const float* proj_b    = (const float*)d_in[6];
    const float* ln_g      = (const float*)d_in[7];
    const float* ln_b      = (const float*)d_in[8];
    const float* w1        = (const float*)d_in[9];
    const float* b1        = (const float*)d_in[10];
    const float* w2        = (const float*)d_in[11];
    const float* b2        = (const float*)d_in[12];
    const int*   edge_src  = (const int*)d_in[13];
    const int*   edge_dst  = (const int*)d_in[14];
    float* out = (float*)d_out;

    float *zp, *dfp, *xp;
    cudaGetSymbolAddress((void**)&zp,  g_z);
    cudaGetSymbolAddress((void**)&dfp, g_df);
    cudaGetSymbolAddress((void**)&xp,  g_x);
    bf16 *eh, *el, *fh, *fl, *wzh, *wzl, *wdh, *wdl;
    cudaGetSymbolAddress((void**)&eh,  g_eh);  cudaGetSymbolAddress((void**)&el,  g_el);
    cudaGetSymbolAddress((void**)&fh,  g_fh);  cudaGetSymbolAddress((void**)&fl,  g_fl);
    cudaGetSymbolAddress((void**)&wzh, g_wzh); cudaGetSymbolAddress((void**)&wzl, g_wzl);
    cudaGetSymbolAddress((void**)&wdh, g_wdh); cudaGetSymbolAddress((void**)&wdl, g_wdl);
    f16 *sh, *sl, *hh, *hl, *xnh, *xnl, *th, *tl, *pw, *w1p, *w2p;
    cudaGetSymbolAddress((void**)&sh,  g_sh);  cudaGetSymbolAddress((void**)&sl,  g_sl);
    cudaGetSymbolAddress((void**)&hh,  g_hh);  cudaGetSymbolAddress((void**)&hl,  g_hl);
    cudaGetSymbolAddress((void**)&xnh, g_xnh); cudaGetSymbolAddress((void**)&xnl, g_xnl);
    cudaGetSymbolAddress((void**)&th,  g_th);  cudaGetSymbolAddress((void**)&tl,  g_tl);
    cudaGetSymbolAddress((void**)&pw,  g_pw);
    cudaGetSymbolAddress((void**)&w1p, g_w1);
    cudaGetSymbolAddress((void**)&w2p, g_w2);

    cudaFuncSetAttribute(mma_gemm<bf16, 3, 2, 0, false, false, false>,
                         cudaFuncAttributeMaxDynamicSharedMemorySize, SMEM_BF3);
    cudaFuncSetAttribute(mma_gemm<f16, 2, 3, 0, true, false, false>,
                         cudaFuncAttributeMaxDynamicSharedMemorySize, SMEM_FP2);
    cudaFuncSetAttribute(mma_gemm<f16, 2, 3, 1, true, false, true>,
                         cudaFuncAttributeMaxDynamicSharedMemorySize, SMEM_FP2);
    cudaFuncSetAttribute(mma_gemm<f16, 2, 3, 0, true, true, false>,
                         cudaFuncAttributeMaxDynamicSharedMemorySize, SMEM_FP2);

    const int TB = 256;
    const int MB = (NS + 127) / 128;  // 782

    // launch order puts z-GEMM at index 3 (the launch ncu captures)
    act_split<bf16><<<(NE * D / 4 + TB - 1) / TB, TB>>>(e_in, eh, el, NE * D);           // 0
    repack_split<<<(256 * 256 + TB - 1) / TB, TB>>>(fc_w, wzh, wzl, 256);                // 1
    act_split<bf16><<<(NS * FEAT / 4 + TB - 1) / TB, TB>>>(dst_feat, fh, fl, NS * FEAT); // 2
    // 3: z = e @ Wz  [NE,256]  (bf16 3-pass, 2-stage)
    mma_gemm<bf16, 3, 2, 0, false, false, false><<<dim3(2, MB), TB, SMEM_BF3>>>(
        eh, el, 256, eh, el, 256, D, wzh, wzl, 256,
        nullptr, nullptr, 0, zp, nullptr, nullptr, 256, NE, 256);
    repack_split<<<(64 * 256 + TB - 1) / TB, TB>>>(dstfeat_w, wdh, wdl, 64);             // 4
    // 5: df = dst_feat @ Wd  [NS,256]  (bf16 3-pass, 2-stage)
    mma_gemm<bf16, 3, 2, 0, false, false, false><<<dim3(2, MB), TB, SMEM_BF3>>>(
        fh, fl, 64, fh, fl, 64, FEAT, wdh, wdl, 64,
        nullptr, nullptr, 0, dfp, nullptr, nullptr, 256, NS, 64);

    // remaining conversions
    act_split<f16><<<(NS * D / 4 + TB - 1) / TB, TB>>>(s_in, sh, sl, NS * D);
    wsplit_t16<<<(512 * 256 + TB - 1) / TB, TB>>>(proj_w, pw, 512, 256);
    wsplit_t16<<<(256 * 512 + TB - 1) / TB, TB>>>(w1, w1p, 256, 512);
    wsplit_t16<<<(512 * 256 + TB - 1) / TB, TB>>>(w2, w2p, 512, 256);

    // CSR build by dst (parallel decoupled scan)
    zero_counts<<<(NS + TB - 1) / TB, TB>>>();
    hist_kernel<<<(EDG + TB - 1) / TB, TB>>>(edge_dst);
    scan_pass1<<<NBLK, SCAN_B>>>();
    scan_pass2<<<1, 128>>>();
    scan_pass3<<<NBLK, SCAN_B>>>();
    scatter_kernel<<<(EDG + TB - 1) / TB, TB>>>(edge_src, edge_dst);

    // attention + ELU -> h split fp16
    attn_kernel<<<(NS * 32 + TB - 1) / TB, TB>>>();

    // proj: [h | s] @ proj_w + b -> g_x (fp32)  (fp16 2-pass, 3-stage)
    mma_gemm<f16, 2, 3, 0, true, false, false><<<dim3(2, MB), TB, SMEM_FP2>>>(
        hh, hl, 256, sh, sl, 256, 256, pw, nullptr, 512,
        proj_b, nullptr, 0, xp, nullptr, nullptr, 256, NS, 512);

    // layernorm -> xn split fp16
    ln_kernel<<<(NS * 32 + TB - 1) / TB, TB>>>(xp, ln_g, ln_b);

    // ffn1: gelu(xn @ w1 + b1) -> t split fp16  (fp16 2-pass, 3-stage)
    mma_gemm<f16, 2, 3, 1, true, false, true><<<dim3(4, MB), TB, SMEM_FP2>>>(
        xnh, xnl, 256, xnh, xnl, 256, 256, w1p, nullptr, 256,
        b1, nullptr, 0, nullptr, th, tl, 512, NS, 256);

    // ffn2: t @ w2 + b2 + g_x -> out (fp32)  (fp16 2-pass, 3-stage)
    mma_gemm<f16, 2, 3, 0, true, true, false><<<dim3(2, MB), TB, SMEM_FP2>>>(
        th, tl, 512, th, tl, 512, 512, w2p, nullptr, 512,
        b2, xp, 256, out, nullptr, nullptr, 256, NS, 512);
}

// round 12
// speedup vs baseline: 1.5432x; 1.0214x over previous
#include <cuda_runtime.h>
#include <cuda_bf16.h>
#include <cuda_fp16.h>
#include <cstdint>
#include <math.h>

// Problem constants (fixed by the dataset)
#define NS 100000
#define NE 100000
#define EDG 1600000
#define D 256
#define H 8
#define HD 32
#define FEAT 64
#define DFF 512

#define SCAN_B 1024
#define NBLK ((NS + SCAN_B - 1) / SCAN_B)   // 98

// smem tile geometry: 32 elems of k per row, padded to 40 (80 B)
#define KP 40
#define ROWB 80
#define MATB (128 * ROWB)          // 10240 B per matrix
#define SMEM_BF3 (2 * 4 * MATB)    // 81920 B: bf16 3-pass, 2 stages (Ah,Al,Bh,Bl)
#define SMEM_FP2 (3 * 3 * MATB)    // 92160 B: fp16 2-pass, 3 stages (Ah,Al,Bh)

typedef __nv_bfloat16 bf16;
typedef __half f16;

// ---------------- device scratch (no allocations allowed) ----------------
__device__ float g_z[(size_t)NE * D];
__device__ float g_df[(size_t)NS * D];
__device__ float g_x[(size_t)NS * D];
// bf16 split (pre-softmax path)
__device__ bf16 g_eh[(size_t)NE * D],    g_el[(size_t)NE * D];
__device__ bf16 g_fh[(size_t)NS * FEAT], g_fl[(size_t)NS * FEAT];
__device__ bf16 g_wzh[256 * 256], g_wzl[256 * 256];
__device__ bf16 g_wdh[256 * 64],  g_wdl[256 * 64];
// fp16 split (post-softmax path)
__device__ f16 g_sh[(size_t)NS * D],   g_sl[(size_t)NS * D];
__device__ f16 g_hh[(size_t)NS * D],   g_hl[(size_t)NS * D];
__device__ f16 g_xnh[(size_t)NS * D],  g_xnl[(size_t)NS * D];
__device__ f16 g_th[(size_t)NS * DFF], g_tl[(size_t)NS * DFF];
// fp16 plain transposed weights Wt[n][k]
__device__ f16 g_pw[256 * 512];
__device__ f16 g_w1[512 * 256];
__device__ f16 g_w2[256 * 512];
// CSR
__device__ int g_counts[NS];
__device__ int g_offsets[NS + 1];
__device__ int g_cursor[NS];
__device__ int g_csr_src[EDG];
__device__ int g_bsum[NBLK];

// ---------------- small helpers ----------------
__device__ __forceinline__ float gelu_fast(float x) {
    const float c = 0.7978845608028654f;
    float u = c * (x + 0.044715f * x * x * x);
    float e = __expf(2.0f * u);
    float th = 1.0f - 2.0f / (e + 1.0f);
    return 0.5f * x * (1.0f + th);
}
__device__ __forceinline__ uint32_t smem_u32(const void* p) {
    uint32_t a;
    asm("{ .reg .u64 t; cvta.to.shared.u64 t, %1; cvt.u32.u64 %0, t; }" : "=r"(a) : "l"(p));
    return a;
}
__device__ __forceinline__ void ldm_x4(uint32_t* r, uint32_t addr) {
    asm volatile("ldmatrix.sync.aligned.m8n8.x4.shared.b16 {%0,%1,%2,%3}, [%4];"
                 : "=r"(r[0]), "=r"(r[1]), "=r"(r[2]), "=r"(r[3]) : "r"(addr));
}
__device__ __forceinline__ uint32_t pk2(bf16 a, bf16 b) {
    __nv_bfloat162 t(a, b); return *(uint32_t*)&t;
}
__device__ __forceinline__ uint32_t pk2(f16 a, f16 b) {
    __half2 t(a, b); return *(uint32_t*)&t;
}
__device__ __forceinline__ void split2(float x, bf16& hi, bf16& lo) {
    hi = __float2bfloat16_rn(x);
    lo = __float2bfloat16_rn(x - __bfloat162float(hi));
}
__device__ __forceinline__ void split2(float x, f16& hi, f16& lo) {
    hi = __float2half_rn(x);
    lo = __float2half_rn(x - __half2float(hi));
}
template <typename T>
__device__ __forceinline__ void mma_t(float* c, const uint32_t* a, const uint32_t* b);
template <>
__device__ __forceinline__ void mma_t<bf16>(float* c, const uint32_t* a, const uint32_t* b) {
    asm volatile(
        "mma.sync.aligned.m16n8k16.row.col.f32.bf16.bf16.f32 "
        "{%0,%1,%2,%3}, {%4,%5,%6,%7}, {%8,%9}, {%0,%1,%2,%3};"
        : "+f"(c[0]), "+f"(c[1]), "+f"(c[2]), "+f"(c[3])
        : "r"(a[0]), "r"(a[1]), "r"(a[2]), "r"(a[3]), "r"(b[0]), "r"(b[1]));
}
template <>
__device__ __forceinline__ void mma_t<f16>(float* c, const uint32_t* a, const uint32_t* b) {
    asm volatile(
        "mma.sync.aligned.m16n8k16.row.col.f32.f16.f16.f32 "
        "{%0,%1,%2,%3}, {%4,%5,%6,%7}, {%8,%9}, {%0,%1,%2,%3};"
        : "+f"(c[0]), "+f"(c[1]), "+f"(c[2]), "+f"(c[3])
        : "r"(a[0]), "r"(a[1]), "r"(a[2]), "r"(a[3]), "r"(b[0]), "r"(b[1]));
}
__device__ __forceinline__ void cpa16(uint32_t dst, const void* src, bool pred) {
    int sz = pred ? 16 : 0;
    asm volatile("cp.async.cg.shared.global [%0], [%1], 16, %2;"
                 :: "r"(dst), "l"(src), "r"(sz) : "memory");
}

// ---------------- conversion kernels ----------------
template <typename T>
__global__ void act_split(const float* __restrict__ in, T* __restrict__ hi,
                          T* __restrict__ lo, int n) {
    int i = 4 * (blockIdx.x * blockDim.x + threadIdx.x);
    if (i >= n) return;
    float4 v = *(const float4*)(in + i);
    T h0, l0, h1, l1, h2, l2, h3, l3;
    split2(v.x, h0, l0); split2(v.y, h1, l1);
    split2(v.z, h2, l2); split2(v.w, h3, l3);
    *(uint2*)(hi + i) = make_uint2(pk2(h0, h1), pk2(h2, h3));
    *(uint2*)(lo + i) = make_uint2(pk2(l0, l1), pk2(l2, l3));
}
__global__ void wsplit_t16(const float* __restrict__ w, f16* __restrict__ o, int K, int N) {
    int idx = blockIdx.x * blockDim.x + threadIdx.x;
    if (idx >= K * N) return;
    int k = idx / N, n = idx % N;
    o[(size_t)n * K + k] = __float2half_rn(w[idx]);
}
__global__ void repack_split(const float* __restrict__ w, bf16* __restrict__ hi,
                             bf16* __restrict__ lo, int K) {
    int idx = blockIdx.x * blockDim.x + threadIdx.x;
    if (idx >= K * 256) return;
    int n = idx / K, k = idx % K;
    bf16 h, l;
    split2(w[(n >> 5) * (K * 32) + k * 32 + (n & 31)], h, l);
    hi[idx] = h;
    lo[idx] = l;
}

// ================= multistage cp.async split GEMM =================
// PASSES==3 (bf16): Ah*Bh + Al*Bh + Ah*Bl.  PASSES==2 (fp16): Ah*B + Al*B.
template <typename T, int PASSES, int NSTAGE, int ACT, bool BIAS, bool RES, bool OSPLIT>
__global__ void __launch_bounds__(256, 2) mma_gemm(
    const T* __restrict__ Ah0, const T* __restrict__ Al0, int lda0,
    const T* __restrict__ Ah1, const T* __restrict__ Al1, int lda1, int ksplit,
    const T* __restrict__ Bh, const T* __restrict__ Bl, int ldbk,
    const float* __restrict__ bias,
    const float* __restrict__ res, int ldr,
    float* __restrict__ C, T* __restrict__ Ch, T* __restrict__ Cl, int ldc,
    int M, int K)
{
    constexpr int NMAT = (PASSES == 3) ? 4 : 3;
    constexpr int STB = NMAT * MATB;
    extern __shared__ char dsm[];
    uint32_t sb = smem_u32(dsm);

    int t = threadIdx.x;
    int lane = t & 31, wid = t >> 5;
    int m0 = blockIdx.y * 128;
    int n0 = blockIdx.x * 128;
    int wm = wid & 3;
    int wn = wid >> 2;

    float acc[2][8][4];
#pragma unroll
    for (int i = 0; i < 2; i++)
#pragma unroll
        for (int j = 0; j < 8; j++)
#pragma unroll
            for (int q = 0; q < 4; q++) acc[i][j][q] = 0.0f;

    uint32_t a_off = (uint32_t)(((wm * 32 + (lane & 15)) * KP + (lane >> 4) * 8) * 2);
    uint32_t b_off = (uint32_t)(((wn * 64 + (lane & 7) + (lane >> 4) * 8) * KP
                                 + ((lane >> 3) & 1) * 8) * 2);

    int p_row = t >> 1;
    int p_c0 = (t & 1) * 2;
    bool a_ok = (m0 + p_row) < M;
    const int KT = K >> 5;

    auto prefetch = [&](int kt) {
        if (kt < KT) {
            int k0 = kt * 32;
            int stage = kt % NSTAGE;
            const T *AhS, *AlS; int lda, koff;
            if (k0 < ksplit) { AhS = Ah0; AlS = Al0; lda = lda0; koff = k0; }
            else             { AhS = Ah1; AlS = Al1; lda = lda1; koff = k0 - ksplit; }
            const T* pah = AhS + (size_t)(m0 + p_row) * lda + koff;
            const T* pal = AlS + (size_t)(m0 + p_row) * lda + koff;
            const T* pbh = Bh + (size_t)(n0 + p_row) * ldbk + k0;
            uint32_t base = sb + stage * STB + p_row * ROWB;
#pragma unroll
            for (int ci = 0; ci < 2; ci++) {
                int c = p_c0 + ci;
                cpa16(base + c * 16,            pah + c * 8, a_ok);
                cpa16(base + MATB + c * 16,     pal + c * 8, a_ok);
                cpa16(base + 2 * MATB + c * 16, pbh + c * 8, true);
                if (PASSES == 3) {
                    const T* pbl = Bl + (size_t)(n0 + p_row) * ldbk + k0;
                    cpa16(base + 3 * MATB + c * 16, pbl + c * 8, true);
                }
            }
        }
        asm volatile("cp.async.commit_group;" ::: "memory");
    };

#pragma unroll
    for (int s = 0; s < NSTAGE - 1; s++) prefetch(s);

    for (int kt = 0; kt < KT; kt++) {
        if (NSTAGE == 2) asm volatile("cp.async.wait_group 0;" ::: "memory");
        else             asm volatile("cp.async.wait_group 1;" ::: "memory");
        __syncthreads();

        prefetch(kt + NSTAGE - 1);

        uint32_t s0 = sb + (kt % NSTAGE) * STB;
        uint32_t sAh = s0, sAl = s0 + MATB, sBh = s0 + 2 * MATB;

#pragma unroll
        for (int ks = 0; ks < 2; ks++) {
            uint32_t koffb = (uint32_t)(ks * 32);
            uint32_t a_hi[2][4], a_lo[2][4], b[4][4];
            ldm_x4(a_hi[0], sAh + a_off + koffb);
            ldm_x4(a_hi[1], sAh + a_off + koffb + 16 * KP * 2);
            ldm_x4(a_lo[0], sAl + a_off + koffb);
            ldm_x4(a_lo[1], sAl + a_off + koffb + 16 * KP * 2);
#pragma unroll
            for (int ni2 = 0; ni2 < 4; ni2++)
                ldm_x4(b[ni2], sBh + b_off + koffb + ni2 * 16 * KP * 2);
#pragma unroll
            for (int mi = 0; mi < 2; mi++)
#pragma unroll
                for (int ni = 0; ni < 8; ni++)
                    mma_t<T>(acc[mi][ni], a_hi[mi], &b[ni >> 1][(ni & 1) * 2]);
#pragma unroll
            for (int mi = 0; mi < 2; mi++)
#pragma unroll
                for (int ni = 0; ni < 8; ni++)
                    mma_t<T>(acc[mi][ni], a_lo[mi], &b[ni >> 1][(ni & 1) * 2]);
            if (PASSES == 3) {
                uint32_t sBl = s0 + 3 * MATB;
#pragma unroll
                for (int ni2 = 0; ni2 < 4; ni2++)
                    ldm_x4(b[ni2], sBl + b_off + koffb + ni2 * 16 * KP * 2);
#pragma unroll
                for (int mi = 0; mi < 2; mi++)
#pragma unroll
                    for (int ni = 0; ni < 8; ni++)
                        mma_t<T>(acc[mi][ni], a_hi[mi], &b[ni >> 1][(ni & 1) * 2]);
            }
        }
    }

    // ---- epilogue ----
#pragma unroll
    for (int mi = 0; mi < 2; mi++) {
#pragma unroll
        for (int ni = 0; ni < 8; ni++) {
            int cc = n0 + wn * 64 + ni * 8 + (lane & 3) * 2;
#pragma unroll
            for (int hh = 0; hh < 2; hh++) {
                int m = m0 + wm * 32 + mi * 16 + (lane >> 2) + hh * 8;
                if (m >= M) continue;
                float v0 = acc[mi][ni][hh * 2 + 0];
                float v1 = acc[mi][ni][hh * 2 + 1];
                if (BIAS) { v0 += bias[cc]; v1 += bias[cc + 1]; }
                if (ACT == 1) { v0 = gelu_fast(v0); v1 = gelu_fast(v1); }
                if (RES) {
                    const float* rp = res + (size_t)m * ldr + cc;
                    v0 += rp[0]; v1 += rp[1];
                }
                if (OSPLIT) {
                    T h0, l0, h1, l1;
                    split2(v0, h0, l0);
                    split2(v1, h1, l1);
                    *(uint32_t*)(Ch + (size_t)m * ldc + cc) = pk2(h0, h1);
                    *(uint32_t*)(Cl + (size_t)m * ldc + cc) = pk2(l0, l1);
                } else {
                    *(float2*)(C + (size_t)m * ldc + cc) = make_float2(v0, v1);
                }
            }
        }
    }
}

// ---------------- CSR build ----------------
__global__ void zero_counts() {
    int i = blockIdx.x * blockDim.x + threadIdx.x;
    if (i < NS) g_counts[i] = 0;
}
__global__ void hist_kernel(const int* __restrict__ edge_dst) {
    int i = blockIdx.x * blockDim.x + threadIdx.x;
    if (i < EDG) atomicAdd(&g_counts[edge_dst[i]], 1);
}
__global__ void __launch_bounds__(SCAN_B) scan_pass1() {
    __shared__ int ws[32];
    int b = blockIdx.x, t = threadIdx.x;
    int i = b * SCAN_B + t;
    int v = (i < NS) ? g_counts[i] : 0;
#pragma unroll
    for (int o = 16; o; o >>= 1) v += __shfl_xor_sync(0xFFFFFFFFu, v, o);
    if ((t & 31) == 0) ws[t >> 5] = v;
    __syncthreads();
    if (t < 32) {
        int x = ws[t];
#pragma unroll
        for (int o = 16; o; o >>= 1) x += __shfl_xor_sync(0xFFFFFFFFu, x, o);
        if (t == 0) g_bsum[b] = x;
    }
}
__global__ void scan_pass2() {
    __shared__ int sh[128];
    int t = threadIdx.x;
    int orig = (t < NBLK) ? g_bsum[t] : 0;
    sh[t] = orig;
    __syncthreads();
    for (int o = 1; o < 128; o <<= 1) {
        int v = (t >= o) ? sh[t - o] : 0;
        __syncthreads();
        sh[t] += v;
        __syncthreads();
    }
    if (t < NBLK) g_bsum[t] = sh[t] - orig;
}
__global__ void __launch_bounds__(SCAN_B) scan_pass3() {
    __shared__ int ws[32];
    int b = blockIdx.x, t = threadIdx.x;
    int lane = t & 31, w = t >> 5;
    int i = b * SCAN_B + t;
    int v = (i < NS) ? g_counts[i] : 0;
    int x = v;
#pragma unroll
    for (int o = 1; o < 32; o <<= 1) {
        int y = __shfl_up_sync(0xFFFFFFFFu, x, o);
        if (lane >= o) x += y;
    }
    if (lane == 31) ws[w] = x;
    __syncthreads();
    if (w == 0) {
        int sv = ws[lane];
#pragma unroll
        for (int o = 1; o < 32; o <<= 1) {
            int y = __shfl_up_sync(0xFFFFFFFFu, sv, o);
            if (lane >= o) sv += y;
        }
        ws[lane] = sv;
    }
    __syncthreads();
    int incl = x + (w > 0 ? ws[w - 1] : 0) + g_bsum[b];
    if (i < NS) {
        g_offsets[i + 1] = incl;
        g_cursor[i] = incl - v;
    }
    if (b == 0 && t == 0) g_offsets[0] = 0;
}
__global__ void scatter_kernel(const int* __restrict__ edge_src,
                               const int* __restrict__ edge_dst) {
    int i = blockIdx.x * blockDim.x + threadIdx.x;
    if (i >= EDG) return;
    int dst = edge_dst[i];
    int pos = atomicAdd(&g_cursor[dst], 1);
    g_csr_src[pos] = edge_src[i];
}

// ---------------- attention: warp per dst, lane = (head, quarter) ----------------
__global__ void __launch_bounds__(256) attn_kernel() {
    int gw = (blockIdx.x * blockDim.x + threadIdx.x) >> 5;
    if (gw >= NS) return;
    int lane = threadIdx.x & 31;
    int off = (lane >> 2) * 32 + (lane & 3) * 8;

    int beg = g_offsets[gw];
    int end = g_offsets[gw + 1];

    const float* dfp = g_df + (size_t)gw * 256 + off;
    float4 d0 = *(const float4*)(dfp);
    float4 d1 = *(const float4*)(dfp + 4);

    float m = -1e30f, den = 0.0f;
    float4 a0 = make_float4(0.f, 0.f, 0.f, 0.f);
    float4 a1 = make_float4(0.f, 0.f, 0.f, 0.f);

    int e = beg;
    for (; e + 2 <= end; e += 2) {
        int s0 = __ldg(&g_csr_src[e]);
        int s1 = __ldg(&g_csr_src[e + 1]);
        const float* zp0 = g_z + (size_t)s0 * 256 + off;
        const float* zp1 = g_z + (size_t)s1 * 256 + off;
        float4 x0 = __ldg((const float4*)zp0);
        float4 x1 = __ldg((const float4*)(zp0 + 4));
        float4 y0 = __ldg((const float4*)zp1);
        float4 y1 = __ldg((const float4*)(zp1 + 4));

        float sa = x0.x * d0.x + x0.y * d0.y + x0.z * d0.z + x0.w * d0.w
                 + x1.x * d1.x + x1.y * d1.y + x1.z * d1.z + x1.w * d1.w;
        float sb = y0.x * d0.x + y0.y * d0.y + y0.z * d0.z + y0.w * d0.w
                 + y1.x * d1.x + y1.y * d1.y + y1.z * d1.z + y1.w * d1.w;
        sa += __shfl_xor_sync(0xFFFFFFFFu, sa, 1);
        sb += __shfl_xor_sync(0xFFFFFFFFu, sb, 1);
        sa += __shfl_xor_sync(0xFFFFFFFFu, sa, 2);
        sb += __shfl_xor_sync(0xFFFFFFFFu, sb, 2);

        {
            float mn = fmaxf(m, sa);
            float sc = __expf(m - mn);
            float w  = __expf(sa - mn);
            den = den * sc + w;
            a0.x = a0.x * sc + w * x0.x; a0.y = a0.y * sc + w * x0.y;
            a0.z = a0.z * sc + w * x0.z; a0.w = a0.w * sc + w * x0.w;
            a1.x = a1.x * sc + w * x1.x; a1.y = a1.y * sc + w * x1.y;
            a1.z = a1.z * sc + w * x1.z; a1.w = a1.w * sc + w * x1.w;
            m = mn;
        }
        {
            float mn = fmaxf(m, sb);
            float sc = __expf(m - mn);
            float w  = __expf(sb - mn);
            den = den * sc + w;
            a0.x = a0.x * sc + w * y0.x; a0.y = a0.y * sc + w * y0.y;
            a0.z = a0.z * sc + w * y0.z; a0.w = a0.w * sc + w * y0.w;
            a1.x = a1.x * sc + w * y1.x; a1.y = a1.y * sc + w * y1.y;
            a1.z = a1.z * sc + w * y1.z; a1.w = a1.w * sc + w * y1.w;
            m = mn;
        }
    }
    for (; e < end; e++) {
        int s0 = __ldg(&g_csr_src[e]);
        const float* zp0 = g_z + (size_t)s0 * 256 + off;
        float4 x0 = __ldg((const float4*)zp0);
        float4 x1 = __ldg((const float4*)(zp0 + 4));
        float sa = x0.x * d0.x + x0.y * d0.y + x0.z * d0.z + x0.w * d0.w
                 + x1.x * d1.x + x1.y * d1.y + x1.z * d1.z + x1.w * d1.w;
        sa += __shfl_xor_sync(0xFFFFFFFFu, sa, 1);
        sa += __shfl_xor_sync(0xFFFFFFFFu, sa, 2);
        float mn = fmaxf(m, sa);
        float sc = __expf(m - mn);
        float w  = __expf(sa - mn);
        den = den * sc + w;
        a0.x = a0.x * sc + w * x0.x; a0.y = a0.y * sc + w * x0.y;
        a0.z = a0.z * sc + w * x0.z; a0.w = a0.w * sc + w * x0.w;
        a1.x = a1.x * sc + w * x1.x; a1.y = a1.y * sc + w * x1.y;
        a1.z = a1.z * sc + w * x1.z; a1.w = a1.w * sc + w * x1.w;
        m = mn;
    }

    float inv = 1.0f / den;
    float v[8];
    v[0] = a0.x * inv; v[1] = a0.y * inv; v[2] = a0.z * inv; v[3] = a0.w * inv;
    v[4] = a1.x * inv; v[5] = a1.y * inv; v[6] = a1.z * inv; v[7] = a1.w * inv;
    f16 hi[8], lo[8];
#pragma unroll
    for (int i = 0; i < 8; i++) {
        v[i] = (v[i] > 0.0f) ? v[i] : expm1f(v[i]);  // ELU(alpha=1)
        split2(v[i], hi[i], lo[i]);
    }
    size_t ob = (size_t)gw * 256 + off;
    *(uint4*)(g_hh + ob) = make_uint4(pk2(hi[0], hi[1]), pk2(hi[2], hi[3]),
                                      pk2(hi[4], hi[5]), pk2(hi[6], hi[7]));
    *(uint4*)(g_hl + ob) = make_uint4(pk2(lo[0], lo[1]), pk2(lo[2], lo[3]),
                                      pk2(lo[4], lo[5]), pk2(lo[6], lo[7]));
}

// ---------------- layernorm: warp per row, lane owns 8 contiguous cols ----------------
__global__ void ln_kernel(const float* __restrict__ x,
                          const float* __restrict__ gam,
                          const float* __restrict__ bet) {
    int row = (blockIdx.x * blockDim.x + threadIdx.x) >> 5;
    if (row >= NS) return;
    int lane = threadIdx.x & 31;
    const float* xp = x + (size_t)row * 256 + lane * 8;
    float4 va = *(const float4*)xp;
    float4 vb = *(const float4*)(xp + 4);
    float v[8] = {va.x, va.y, va.z, va.w, vb.x, vb.y, vb.z, vb.w};
    float s = 0.0f, s2 = 0.0f;
#pragma unroll
    for (int r = 0; r < 8; r++) { s += v[r]; s2 += v[r] * v[r]; }
#pragma unroll
    for (int o = 16; o > 0; o >>= 1) {
        s  += __shfl_xor_sync(0xFFFFFFFFu, s, o);
        s2 += __shfl_xor_sync(0xFFFFFFFFu, s2, o);
    }
    float mean = s * (1.0f / 256.0f);
    float var = s2 * (1.0f / 256.0f) - mean * mean;
    float inv = rsqrtf(var + 1e-6f);
    float4 ga = *(const float4*)(gam + lane * 8);
    float4 gb = *(const float4*)(gam + lane * 8 + 4);
    float4 ba = *(const float4*)(bet + lane * 8);
    float4 bb = *(const float4*)(bet + lane * 8 + 4);
    float g[8] = {ga.x, ga.y, ga.z, ga.w, gb.x, gb.y, gb.z, gb.w};
    float bt[8] = {ba.x, ba.y, ba.z, ba.w, bb.x, bb.y, bb.z, bb.w};
    f16 hi[8], lo[8];
#pragma unroll
    for (int r = 0; r < 8; r++) {
        float y = (v[r] - mean) * inv * g[r] + bt[r];
        split2(y, hi[r], lo[r]);
    }
    size_t ob = (size_t)row * 256 + lane * 8;
    *(uint4*)(g_xnh + ob) = make_uint4(pk2(hi[0], hi[1]), pk2(hi[2], hi[3]),
                                       pk2(hi[4], hi[5]), pk2(hi[6], hi[7]));
    *(uint4*)(g_xnl + ob) = make_uint4(pk2(lo[0], lo[1]), pk2(lo[2], lo[3]),
                                       pk2(lo[4], lo[5]), pk2(lo[6], lo[7]));
}

// ---------------- launch ----------------
extern "C" void kernel_launch(void* const* d_in, const int* in_sizes, int n_in,
                              void* d_out, int out_size) {
    const float* s_in      = (const float*)d_in[0];
    const float* e_in      = (const float*)d_in[1];
    const float* dst_feat  = (const float*)d_in[2];
    const float* fc_w      = (const float*)d_in[3];
    const float* dstfeat_w = (const float*)d_in[4];
    const float* proj_w    = (const float*)d_in[5];
    const float* proj_b    = (const float*)d_in[6];
    const float* ln_g      = (const float*)d_in[7];
    const float* ln_b      = (const float*)d_in[8];
    const float* w1        = (const float*)d_in[9];
    const float* b1        = (const float*)d_in[10];
    const float* w2        = (const float*)d_in[11];
    const float* b2        = (const float*)d_in[12];
    const int*   edge_src  = (const int*)d_in[13];
    const int*   edge_dst  = (const int*)d_in[14];
    float* out = (float*)d_out;

    float *zp, *dfp, *xp;
    cudaGetSymbolAddress((void**)&zp,  g_z);
    cudaGetSymbolAddress((void**)&dfp, g_df);
    cudaGetSymbolAddress((void**)&xp,  g_x);
    bf16 *eh, *el, *fh, *fl, *wzh, *wzl, *wdh, *wdl;
    cudaGetSymbolAddress((void**)&eh,  g_eh);  cudaGetSymbolAddress((void**)&el,  g_el);
    cudaGetSymbolAddress((void**)&fh,  g_fh);  cudaGetSymbolAddress((void**)&fl,  g_fl);
    cudaGetSymbolAddress((void**)&wzh, g_wzh); cudaGetSymbolAddress((void**)&wzl, g_wzl);
    cudaGetSymbolAddress((void**)&wdh, g_wdh); cudaGetSymbolAddress((void**)&wdl, g_wdl);
    f16 *sh, *sl, *hh, *hl, *xnh, *xnl, *th, *tl, *pw, *w1p, *w2p;
    cudaGetSymbolAddress((void**)&sh,  g_sh);  cudaGetSymbolAddress((void**)&sl,  g_sl);
    cudaGetSymbolAddress((void**)&hh,  g_hh);  cudaGetSymbolAddress((void**)&hl,  g_hl);
    cudaGetSymbolAddress((void**)&xnh, g_xnh); cudaGetSymbolAddress((void**)&xnl, g_xnl);
    cudaGetSymbolAddress((void**)&th,  g_th);  cudaGetSymbolAddress((void**)&tl,  g_tl);
    cudaGetSymbolAddress((void**)&pw,  g_pw);
    cudaGetSymbolAddress((void**)&w1p, g_w1);
    cudaGetSymbolAddress((void**)&w2p, g_w2);

    cudaFuncSetAttribute(mma_gemm<bf16, 3, 2, 0, false, false, false>,
                         cudaFuncAttributeMaxDynamicSharedMemorySize, SMEM_BF3);
    cudaFuncSetAttribute(mma_gemm<f16, 2, 3, 0, true, false, false>,
                         cudaFuncAttributeMaxDynamicSharedMemorySize, SMEM_FP2);
    cudaFuncSetAttribute(mma_gemm<f16, 2, 3, 1, true, false, true>,
                         cudaFuncAttributeMaxDynamicSharedMemorySize, SMEM_FP2);
    cudaFuncSetAttribute(mma_gemm<f16, 2, 3, 0, true, true, false>,
                         cudaFuncAttributeMaxDynamicSharedMemorySize, SMEM_FP2);

    const int TB = 256;
    const int MB = (NS + 127) / 128;  // 782

    // ---- side stream for the independent CSR + conversion chain ----
    cudaStream_t s1;
    cudaStreamCreateWithFlags(&s1, cudaStreamNonBlocking);
    cudaEvent_t evFork, evJoin;
    cudaEventCreateWithFlags(&evFork, cudaEventDisableTiming);
    cudaEventCreateWithFlags(&evJoin, cudaEventDisableTiming);

    // fork point at the very start of the main stream
    cudaEventRecord(evFork, 0);
    cudaStreamWaitEvent(s1, evFork, 0);

    // ---- main stream: conversions needed by z/df, then the two bf16 GEMMs ----
    act_split<bf16><<<(NE * D / 4 + TB - 1) / TB, TB>>>(e_in, eh, el, NE * D);           // 0
    repack_split<<<(256 * 256 + TB - 1) / TB, TB>>>(fc_w, wzh, wzl, 256);                // 1
    act_split<bf16><<<(NS * FEAT / 4 + TB - 1) / TB, TB>>>(dst_feat, fh, fl, NS * FEAT); // 2
    // 3: z = e @ Wz  [NE,256]  (bf16 3-pass, 2-stage) — ncu capture slot
    mma_gemm<bf16, 3, 2, 0, false, false, false><<<dim3(2, MB), TB, SMEM_BF3>>>(
        eh, el, 256, eh, el, 256, D, wzh, wzl, 256,
        nullptr, nullptr, 0, zp, nullptr, nullptr, 256, NE, 256);
    repack_split<<<(64 * 256 + TB - 1) / TB, TB>>>(dstfeat_w, wdh, wdl, 64);             // 4
    // 5: df = dst_feat @ Wd  [NS,256]  (bf16 3-pass, 2-stage)
    mma_gemm<bf16, 3, 2, 0, false, false, false><<<dim3(2, MB), TB, SMEM_BF3>>>(
        fh, fl, 64, fh, fl, 64, FEAT, wdh, wdl, 64,
        nullptr, nullptr, 0, dfp, nullptr, nullptr, 256, NS, 64);

    // ---- side stream: CSR build + post-softmax-path conversions (independent) ----
    zero_counts<<<(NS + TB - 1) / TB, TB, 0, s1>>>();
    hist_kernel<<<(EDG + TB - 1) / TB, TB, 0, s1>>>(edge_dst);
    scan_pass1<<<NBLK, SCAN_B, 0, s1>>>();
    scan_pass2<<<1, 128, 0, s1>>>();
    scan_pass3<<<NBLK, SCAN_B, 0, s1>>>();
    scatter_kernel<<<(EDG + TB - 1) / TB, TB, 0, s1>>>(edge_src, edge_dst);
    act_split<f16><<<(NS * D / 4 + TB - 1) / TB, TB, 0, s1>>>(s_in, sh, sl, NS * D);
    wsplit_t16<<<(512 * 256 + TB - 1) / TB, TB, 0, s1>>>(proj_w, pw, 512, 256);
    wsplit_t16<<<(256 * 512 + TB - 1) / TB, TB, 0, s1>>>(w1, w1p, 256, 512);
    wsplit_t16<<<(512 * 256 + TB - 1) / TB, TB, 0, s1>>>(w2, w2p, 512, 256);
    cudaEventRecord(evJoin, s1);

    // join: attention needs z, df (main) and CSR (s1)
    cudaStreamWaitEvent(0, evJoin, 0);

    // attention + ELU -> h split fp16
    attn_kernel<<<(NS * 32 + TB - 1) / TB, TB>>>();

    // proj: [h | s] @ proj_w + b -> g_x (fp32)  (fp16 2-pass, 3-stage)
    mma_gemm<f16, 2, 3, 0, true, false, false><<<dim3(2, MB), TB, SMEM_FP2>>>(
        hh, hl, 256, sh, sl, 256, 256, pw, nullptr, 512,
        proj_b, nullptr, 0, xp, nullptr, nullptr, 256, NS, 512);

    // layernorm -> xn split fp16
    ln_kernel<<<(NS * 32 + TB - 1) / TB, TB>>>(xp, ln_g, ln_b);

    // ffn1: gelu(xn @ w1 + b1) -> t split fp16  (fp16 2-pass, 3-stage)
    mma_gemm<f16, 2, 3, 1, true, false, true><<<dim3(4, MB), TB, SMEM_FP2>>>(
        xnh, xnl, 256, xnh, xnl, 256, 256, w1p, nullptr, 256,
        b1, nullptr, 0, nullptr, th, tl, 512, NS, 256);

    // ffn2: t @ w2 + b2 + g_x -> out (fp32)  (fp16 2-pass, 3-stage)
    mma_gemm<f16, 2, 3, 0, true, true, false><<<dim3(2, MB), TB, SMEM_FP2>>>(
        th, tl, 512, th, tl, 512, 512, w2p, nullptr, 512,
        b2, xp, 256, out, nullptr, nullptr, 256, NS, 512);
}

// round 13
// speedup vs baseline: 1.9356x; 1.2543x over previous
#include <cuda_runtime.h>
#include <cuda_bf16.h>
#include <cuda_fp16.h>
#include <cstdint>
#include <math.h>

// Problem constants (fixed by the dataset)
#define NS 100000
#define NE 100000
#define EDG 1600000
#define D 256
#define H 8
#define HD 32
#define FEAT 64
#define DFF 512

#define SCAN_B 1024
#define NBLK ((NS + SCAN_B - 1) / SCAN_B)   // 98

// smem tile geometry: 32 elems of k per row, padded to 40 (80 B)
#define KP 40
#define ROWB 80
#define MATB (128 * ROWB)          // 10240 B per matrix
#define SMEM_BF3 (2 * 4 * MATB)    // 81920 B: bf16 3-pass, 2 stages (Ah,Al,Bh,Bl)
#define SMEM_FP1 (3 * 2 * MATB)    // 61440 B: fp16 1-pass, 3 stages (A,B)

typedef __nv_bfloat16 bf16;
typedef __half f16;

// ---------------- device scratch (no allocations allowed) ----------------
__device__ float g_z[(size_t)NE * D];
__device__ float g_df[(size_t)NS * D];
__device__ float g_x[(size_t)NS * D];
// bf16 split (pre-softmax path)
__device__ bf16 g_eh[(size_t)NE * D],    g_el[(size_t)NE * D];
__device__ bf16 g_fh[(size_t)NS * FEAT], g_fl[(size_t)NS * FEAT];
__device__ bf16 g_wzh[256 * 256], g_wzl[256 * 256];
__device__ bf16 g_wdh[256 * 64],  g_wdl[256 * 64];
// fp16 rn (post-softmax path)
__device__ f16 g_sf[(size_t)NS * D];
__device__ f16 g_hf[(size_t)NS * D];
__device__ f16 g_xnf[(size_t)NS * D];
__device__ f16 g_tf[(size_t)NS * DFF];
// fp16 plain transposed weights Wt[n][k]
__device__ f16 g_pw[256 * 512];
__device__ f16 g_w1[512 * 256];
__device__ f16 g_w2[256 * 512];
// CSR
__device__ int g_counts[NS];
__device__ int g_offsets[NS + 1];
__device__ int g_cursor[NS];
__device__ int g_csr_src[EDG];
__device__ int g_bsum[NBLK];

// ---------------- small helpers ----------------
__device__ __forceinline__ float gelu_fast(float x) {
    const float c = 0.7978845608028654f;
    float u = c * (x + 0.044715f * x * x * x);
    float e = __expf(2.0f * u);
    float th = 1.0f - 2.0f / (e + 1.0f);
    return 0.5f * x * (1.0f + th);
}
__device__ __forceinline__ uint32_t smem_u32(const void* p) {
    uint32_t a;
    asm("{ .reg .u64 t; cvta.to.shared.u64 t, %1; cvt.u32.u64 %0, t; }" : "=r"(a) : "l"(p));
    return a;
}
__device__ __forceinline__ void ldm_x4(uint32_t* r, uint32_t addr) {
    asm volatile("ldmatrix.sync.aligned.m8n8.x4.shared.b16 {%0,%1,%2,%3}, [%4];"
                 : "=r"(r[0]), "=r"(r[1]), "=r"(r[2]), "=r"(r[3]) : "r"(addr));
}
__device__ __forceinline__ uint32_t pk2(bf16 a, bf16 b) {
    __nv_bfloat162 t(a, b); return *(uint32_t*)&t;
}
__device__ __forceinline__ uint32_t pk2(f16 a, f16 b) {
    __half2 t(a, b); return *(uint32_t*)&t;
}
__device__ __forceinline__ void split2(float x, bf16& hi, bf16& lo) {
    hi = __float2bfloat16_rn(x);
    lo = __float2bfloat16_rn(x - __bfloat162float(hi));
}
template <typename T>
__device__ __forceinline__ void mma_t(float* c, const uint32_t* a, const uint32_t* b);
template <>
__device__ __forceinline__ void mma_t<bf16>(float* c, const uint32_t* a, const uint32_t* b) {
    asm volatile(
        "mma.sync.aligned.m16n8k16.row.col.f32.bf16.bf16.f32 "
        "{%0,%1,%2,%3}, {%4,%5,%6,%7}, {%8,%9}, {%0,%1,%2,%3};"
        : "+f"(c[0]), "+f"(c[1]), "+f"(c[2]), "+f"(c[3])
        : "r"(a[0]), "r"(a[1]), "r"(a[2]), "r"(a[3]), "r"(b[0]), "r"(b[1]));
}
template <>
__device__ __forceinline__ void mma_t<f16>(float* c, const uint32_t* a, const uint32_t* b) {
    asm volatile(
        "mma.sync.aligned.m16n8k16.row.col.f32.f16.f16.f32 "
        "{%0,%1,%2,%3}, {%4,%5,%6,%7}, {%8,%9}, {%0,%1,%2,%3};"
        : "+f"(c[0]), "+f"(c[1]), "+f"(c[2]), "+f"(c[3])
        : "r"(a[0]), "r"(a[1]), "r"(a[2]), "r"(a[3]), "r"(b[0]), "r"(b[1]));
}
__device__ __forceinline__ void cpa16(uint32_t dst, const void* src, bool pred) {
    int sz = pred ? 16 : 0;
    asm volatile("cp.async.cg.shared.global [%0], [%1], 16, %2;"
                 :: "r"(dst), "l"(src), "r"(sz) : "memory");
}

// ---------------- conversion kernels ----------------
__global__ void act_split_bf(const float* __restrict__ in, bf16* __restrict__ hi,
                             bf16* __restrict__ lo, int n) {
    int i = 4 * (blockIdx.x * blockDim.x + threadIdx.x);
    if (i >= n) return;
    float4 v = *(const float4*)(in + i);
    bf16 h0, l0, h1, l1, h2, l2, h3, l3;
    split2(v.x, h0, l0); split2(v.y, h1, l1);
    split2(v.z, h2, l2); split2(v.w, h3, l3);
    *(uint2*)(hi + i) = make_uint2(pk2(h0, h1), pk2(h2, h3));
    *(uint2*)(lo + i) = make_uint2(pk2(l0, l1), pk2(l2, l3));
}
__global__ void act_rn16(const float* __restrict__ in, f16* __restrict__ o, int n) {
    int i = 4 * (blockIdx.x * blockDim.x + threadIdx.x);
    if (i >= n) return;
    float4 v = *(const float4*)(in + i);
    *(uint2*)(o + i) = make_uint2(pk2(__float2half_rn(v.x), __float2half_rn(v.y)),
                                  pk2(__float2half_rn(v.z), __float2half_rn(v.w)));
}
__global__ void wsplit_t16(const float* __restrict__ w, f16* __restrict__ o, int K, int N) {
    int idx = blockIdx.x * blockDim.x + threadIdx.x;
    if (idx >= K * N) return;
    int k = idx / N, n = idx % N;
    o[(size_t)n * K + k] = __float2half_rn(w[idx]);
}
__global__ void repack_split(const float* __restrict__ w, bf16* __restrict__ hi,
                             bf16* __restrict__ lo, int K) {
    int idx = blockIdx.x * blockDim.x + threadIdx.x;
    if (idx >= K * 256) return;
    int n = idx / K, k = idx % K;
    bf16 h, l;
    split2(w[(n >> 5) * (K * 32) + k * 32 + (n & 31)], h, l);
    hi[idx] = h;
    lo[idx] = l;
}

// ================= multistage cp.async GEMM =================
// PASSES==3 (bf16): Ah*Bh + Al*Bh + Ah*Bl (split operands).
// PASSES==1 (fp16): A*B plain rn.
template <typename T, int PASSES, int NSTAGE, int ACT, bool BIAS, bool RES, bool OHALF>
__global__ void __launch_bounds__(256, 2) mma_gemm(
    const T* __restrict__ Ah0, const T* __restrict__ Al0, int lda0,
    const T* __restrict__ Ah1, const T* __restrict__ Al1, int lda1, int ksplit,
    const T* __restrict__ Bh, const T* __restrict__ Bl, int ldbk,
    const float* __restrict__ bias,
    const float* __restrict__ res, int ldr,
    float* __restrict__ C, f16* __restrict__ Cf, int ldc,
    int M, int K)
{
    constexpr int NMAT = (PASSES == 3) ? 4 : 2;
    constexpr int STB = NMAT * MATB;
    constexpr int BOFF = (PASSES == 3) ? 2 * MATB : MATB;
    extern __shared__ char dsm[];
    uint32_t sb = smem_u32(dsm);

    int t = threadIdx.x;
    int lane = t & 31, wid = t >> 5;
    int m0 = blockIdx.y * 128;
    int n0 = blockIdx.x * 128;
    int wm = wid & 3;
    int wn = wid >> 2;

    float acc[2][8][4];
#pragma unroll
    for (int i = 0; i < 2; i++)
#pragma unroll
        for (int j = 0; j < 8; j++)
#pragma unroll
            for (int q = 0; q < 4; q++) acc[i][j][q] = 0.0f;

    uint32_t a_off = (uint32_t)(((wm * 32 + (lane & 15)) * KP + (lane >> 4) * 8) * 2);
    uint32_t b_off = (uint32_t)(((wn * 64 + (lane & 7) + (lane >> 4) * 8) * KP
                                 + ((lane >> 3) & 1) * 8) * 2);

    int p_row = t >> 1;
    int p_c0 = (t & 1) * 2;
    bool a_ok = (m0 + p_row) < M;
    const int KT = K >> 5;

    auto prefetch = [&](int kt) {
        if (kt < KT) {
            int k0 = kt * 32;
            int stage = kt % NSTAGE;
            const T *AhS, *AlS; int lda, koff;
            if (k0 < ksplit) { AhS = Ah0; AlS = Al0; lda = lda0; koff = k0; }
            else             { AhS = Ah1; AlS = Al1; lda = lda1; koff = k0 - ksplit; }
            const T* pah = AhS + (size_t)(m0 + p_row) * lda + koff;
            const T* pbh = Bh + (size_t)(n0 + p_row) * ldbk + k0;
            uint32_t base = sb + stage * STB + p_row * ROWB;
#pragma unroll
            for (int ci = 0; ci < 2; ci++) {
                int c = p_c0 + ci;
                cpa16(base + c * 16,        pah + c * 8, a_ok);
                cpa16(base + BOFF + c * 16, pbh + c * 8, true);
                if (PASSES == 3) {
                    const T* pal = AlS + (size_t)(m0 + p_row) * lda + koff;
                    const T* pbl = Bl + (size_t)(n0 + p_row) * ldbk + k0;
                    cpa16(base + MATB + c * 16,     pal + c * 8, a_ok);
                    cpa16(base + 3 * MATB + c * 16, pbl + c * 8, true);
                }
            }
        }
        asm volatile("cp.async.commit_group;" ::: "memory");
    };

#pragma unroll
    for (int s = 0; s < NSTAGE - 1; s++) prefetch(s);

    for (int kt = 0; kt < KT; kt++) {
        if (NSTAGE == 2) asm volatile("cp.async.wait_group 0;" ::: "memory");
        else             asm volatile("cp.async.wait_group 1;" ::: "memory");
        __syncthreads();

        prefetch(kt + NSTAGE - 1);

        uint32_t s0 = sb + (kt % NSTAGE) * STB;
        uint32_t sAh = s0, sBh = s0 + BOFF;

#pragma unroll
        for (int ks = 0; ks < 2; ks++) {
            uint32_t koffb = (uint32_t)(ks * 32);
            uint32_t a_hi[2][4], b[4][4];
            ldm_x4(a_hi[0], sAh + a_off + koffb);
            ldm_x4(a_hi[1], sAh + a_off + koffb + 16 * KP * 2);
#pragma unroll
            for (int ni2 = 0; ni2 < 4; ni2++)
                ldm_x4(b[ni2], sBh + b_off + koffb + ni2 * 16 * KP * 2);
            // pass 1: Ah * Bh
#pragma unroll
            for (int mi = 0; mi < 2; mi++)
#pragma unroll
                for (int ni = 0; ni < 8; ni++)
                    mma_t<T>(acc[mi][ni], a_hi[mi], &b[ni >> 1][(ni & 1) * 2]);
            if (PASSES == 3) {
                uint32_t sAl = s0 + MATB, sBl = s0 + 3 * MATB;
                uint32_t a_lo[2][4];
                ldm_x4(a_lo[0], sAl + a_off + koffb);
                ldm_x4(a_lo[1], sAl + a_off + koffb + 16 * KP * 2);
                // pass 2: Al * Bh
#pragma unroll
                for (int mi = 0; mi < 2; mi++)
#pragma unroll
                    for (int ni = 0; ni < 8; ni++)
                        mma_t<T>(acc[mi][ni], a_lo[mi], &b[ni >> 1][(ni & 1) * 2]);
                // pass 3: Ah * Bl
#pragma unroll
                for (int ni2 = 0; ni2 < 4; ni2++)
                    ldm_x4(b[ni2], sBl + b_off + koffb + ni2 * 16 * KP * 2);
#pragma unroll
                for (int mi = 0; mi < 2; mi++)
#pragma unroll
                    for (int ni = 0; ni < 8; ni++)
                        mma_t<T>(acc[mi][ni], a_hi[mi], &b[ni >> 1][(ni & 1) * 2]);
            }
        }
    }

    // ---- epilogue ----
#pragma unroll
    for (int mi = 0; mi < 2; mi++) {
#pragma unroll
        for (int ni = 0; ni < 8; ni++) {
            int cc = n0 + wn * 64 + ni * 8 + (lane & 3) * 2;
#pragma unroll
            for (int hh = 0; hh < 2; hh++) {
                int m = m0 + wm * 32 + mi * 16 + (lane >> 2) + hh * 8;
                if (m >= M) continue;
                float v0 = acc[mi][ni][hh * 2 + 0];
                float v1 = acc[mi][ni][hh * 2 + 1];
                if (BIAS) { v0 += bias[cc]; v1 += bias[cc + 1]; }
                if (ACT == 1) { v0 = gelu_fast(v0); v1 = gelu_fast(v1); }
                if (RES) {
                    const float* rp = res + (size_t)m * ldr + cc;
                    v0 += rp[0]; v1 += rp[1];
                }
                if (OHALF) {
                    *(uint32_t*)(Cf + (size_t)m * ldc + cc) =
                        pk2(__float2half_rn(v0), __float2half_rn(v1));
                } else {
                    *(float2*)(C + (size_t)m * ldc + cc) = make_float2(v0, v1);
                }
            }
        }
    }
}

// ---------------- CSR build ----------------
__global__ void zero_counts() {
    int i = blockIdx.x * blockDim.x + threadIdx.x;
    if (i < NS) g_counts[i] = 0;
}
__global__ void hist_kernel(const int* __restrict__ edge_dst) {
    int i = blockIdx.x * blockDim.x + threadIdx.x;
    if (i < EDG) atomicAdd(&g_counts[edge_dst[i]], 1);
}
__global__ void __launch_bounds__(SCAN_B) scan_pass1() {
    __shared__ int ws[32];
    int b = blockIdx.x, t = threadIdx.x;
    int i = b * SCAN_B + t;
    int v = (i < NS) ? g_counts[i] : 0;
#pragma unroll
    for (int o = 16; o; o >>= 1) v += __shfl_xor_sync(0xFFFFFFFFu, v, o);
    if ((t & 31) == 0) ws[t >> 5] = v;
    __syncthreads();
    if (t < 32) {
        int x = ws[t];
#pragma unroll
        for (int o = 16; o; o >>= 1) x += __shfl_xor_sync(0xFFFFFFFFu, x, o);
        if (t == 0) g_bsum[b] = x;
    }
}
__global__ void scan_pass2() {
    __shared__ int sh[128];
    int t = threadIdx.x;
    int orig = (t < NBLK) ? g_bsum[t] : 0;
    sh[t] = orig;
    __syncthreads();
    for (int o = 1; o < 128; o <<= 1) {
        int v = (t >= o) ? sh[t - o] : 0;
        __syncthreads();
        sh[t] += v;
        __syncthreads();
    }
    if (t < NBLK) g_bsum[t] = sh[t] - orig;
}
__global__ void __launch_bounds__(SCAN_B) scan_pass3() {
    __shared__ int ws[32];
    int b = blockIdx.x, t = threadIdx.x;
    int lane = t & 31, w = t >> 5;
    int i = b * SCAN_B + t;
    int v = (i < NS) ? g_counts[i] : 0;
    int x = v;
#pragma unroll
    for (int o = 1; o < 32; o <<= 1) {
        int y = __shfl_up_sync(0xFFFFFFFFu, x, o);
        if (lane >= o) x += y;
    }
    if (lane == 31) ws[w] = x;
    __syncthreads();
    if (w == 0) {
        int sv = ws[lane];
#pragma unroll
        for (int o = 1; o < 32; o <<= 1) {
            int y = __shfl_up_sync(0xFFFFFFFFu, sv, o);
            if (lane >= o) sv += y;
        }
        ws[lane] = sv;
    }
    __syncthreads();
    int incl = x + (w > 0 ? ws[w - 1] : 0) + g_bsum[b];
    if (i < NS) {
        g_offsets[i + 1] = incl;
        g_cursor[i] = incl - v;
    }
    if (b == 0 && t == 0) g_offsets[0] = 0;
}
__global__ void scatter_kernel(const int* __restrict__ edge_src,
                               const int* __restrict__ edge_dst) {
    int i = blockIdx.x * blockDim.x + threadIdx.x;
    if (i >= EDG) return;
    int dst = edge_dst[i];
    int pos = atomicAdd(&g_cursor[dst], 1);
    g_csr_src[pos] = edge_src[i];
}

// ---------------- attention: warp per dst, lane = (head, quarter) ----------------
__global__ void __launch_bounds__(256) attn_kernel() {
    int gw = (blockIdx.x * blockDim.x + threadIdx.x) >> 5;
    if (gw >= NS) return;
    int lane = threadIdx.x & 31;
    int off = (lane >> 2) * 32 + (lane & 3) * 8;

    int beg = g_offsets[gw];
    int end = g_offsets[gw + 1];

    const float* dfp = g_df + (size_t)gw * 256 + off;
    float4 d0 = *(const float4*)(dfp);
    float4 d1 = *(const float4*)(dfp + 4);

    float m = -1e30f, den = 0.0f;
    float4 a0 = make_float4(0.f, 0.f, 0.f, 0.f);
    float4 a1 = make_float4(0.f, 0.f, 0.f, 0.f);

    int e = beg;
    for (; e + 2 <= end; e += 2) {
        int s0 = __ldg(&g_csr_src[e]);
        int s1 = __ldg(&g_csr_src[e + 1]);
        const float* zp0 = g_z + (size_t)s0 * 256 + off;
        const float* zp1 = g_z + (size_t)s1 * 256 + off;
        float4 x0 = __ldg((const float4*)zp0);
        float4 x1 = __ldg((const float4*)(zp0 + 4));
        float4 y0 = __ldg((const float4*)zp1);
        float4 y1 = __ldg((const float4*)(zp1 + 4));

        float sa = x0.x * d0.x + x0.y * d0.y + x0.z * d0.z + x0.w * d0.w
                 + x1.x * d1.x + x1.y * d1.y + x1.z * d1.z + x1.w * d1.w;
        float sb = y0.x * d0.x + y0.y * d0.y + y0.z * d0.z + y0.w * d0.w
                 + y1.x * d1.x + y1.y * d1.y + y1.z * d1.z + y1.w * d1.w;
        sa += __shfl_xor_sync(0xFFFFFFFFu, sa, 1);
        sb += __shfl_xor_sync(0xFFFFFFFFu, sb, 1);
        sa += __shfl_xor_sync(0xFFFFFFFFu, sa, 2);
        sb += __shfl_xor_sync(0xFFFFFFFFu, sb, 2);

        {
            float mn = fmaxf(m, sa);
            float sc = __expf(m - mn);
            float w  = __expf(sa - mn);
            den = den * sc + w;
            a0.x = a0.x * sc + w * x0.x; a0.y = a0.y * sc + w * x0.y;
            a0.z = a0.z * sc + w * x0.z; a0.w = a0.w * sc + w * x0.w;
            a1.x = a1.x * sc + w * x1.x; a1.y = a1.y * sc + w * x1.y;
            a1.z = a1.z * sc + w * x1.z; a1.w = a1.w * sc + w * x1.w;
            m = mn;
        }
        {
            float mn = fmaxf(m, sb);
            float sc = __expf(m - mn);
            float w  = __expf(sb - mn);
            den = den * sc + w;
            a0.x = a0.x * sc + w * y0.x; a0.y = a0.y * sc + w * y0.y;
            a0.z = a0.z * sc + w * y0.z; a0.w = a0.w * sc + w * y0.w;
            a1.x = a1.x * sc + w * y1.x; a1.y = a1.y * sc + w * y1.y;
            a1.z = a1.z * sc + w * y1.z; a1.w = a1.w * sc + w * y1.w;
            m = mn;
        }
    }
    for (; e < end; e++) {
        int s0 = __ldg(&g_csr_src[e]);
        const float* zp0 = g_z + (size_t)s0 * 256 + off;
        float4 x0 = __ldg((const float4*)zp0);
        float4 x1 = __ldg((const float4*)(zp0 + 4));
        float sa = x0.x * d0.x + x0.y * d0.y + x0.z * d0.z + x0.w * d0.w
                 + x1.x * d1.x + x1.y * d1.y + x1.z * d1.z + x1.w * d1.w;
        sa += __shfl_xor_sync(0xFFFFFFFFu, sa, 1);
        sa += __shfl_xor_sync(0xFFFFFFFFu, sa, 2);
        float mn = fmaxf(m, sa);
        float sc = __expf(m - mn);
        float w  = __expf(sa - mn);
        den = den * sc + w;
        a0.x = a0.x * sc + w * x0.x; a0.y = a0.y * sc + w * x0.y;
        a0.z = a0.z * sc + w * x0.z; a0.w = a0.w * sc + w * x0.w;
        a1.x = a1.x * sc + w * x1.x; a1.y = a1.y * sc + w * x1.y;
        a1.z = a1.z * sc + w * x1.z; a1.w = a1.w * sc + w * x1.w;
        m = mn;
    }

    float inv = 1.0f / den;
    float v[8];
    v[0] = a0.x * inv; v[1] = a0.y * inv; v[2] = a0.z * inv; v[3] = a0.w * inv;
    v[4] = a1.x * inv; v[5] = a1.y * inv; v[6] = a1.z * inv; v[7] = a1.w * inv;
    f16 hv[8];
#pragma unroll
    for (int i = 0; i < 8; i++) {
        v[i] = (v[i] > 0.0f) ? v[i] : expm1f(v[i]);  // ELU(alpha=1)
        hv[i] = __float2half_rn(v[i]);
    }
    size_t ob = (size_t)gw * 256 + off;
    *(uint4*)(g_hf + ob) = make_uint4(pk2(hv[0], hv[1]), pk2(hv[2], hv[3]),
                                      pk2(hv[4], hv[5]), pk2(hv[6], hv[7]));
}

// ---------------- layernorm: warp per row, lane owns 8 contiguous cols ----------------
__global__ void ln_kernel(const float* __restrict__ x,
                          const float* __restrict__ gam,
                          const float* __restrict__ bet) {
    int row = (blockIdx.x * blockDim.x + threadIdx.x) >> 5;
    if (row >= NS) return;
    int lane = threadIdx.x & 31;
    const float* xp = x + (size_t)row * 256 + lane * 8;
    float4 va = *(const float4*)xp;
    float4 vb = *(const float4*)(xp + 4);
    float v[8] = {va.x, va.y, va.z, va.w, vb.x, vb.y, vb.z, vb.w};
    float s = 0.0f, s2 = 0.0f;
#pragma unroll
    for (int r = 0; r < 8; r++) { s += v[r]; s2 += v[r] * v[r]; }
#pragma unroll
    for (int o = 16; o > 0; o >>= 1) {
        s  += __shfl_xor_sync(0xFFFFFFFFu, s, o);
        s2 += __shfl_xor_sync(0xFFFFFFFFu, s2, o);
    }
    float mean = s * (1.0f / 256.0f);
    float var = s2 * (1.0f / 256.0f) - mean * mean;
    float inv = rsqrtf(var + 1e-6f);
    float4 ga = *(const float4*)(gam + lane * 8);
    float4 gb = *(const float4*)(gam + lane * 8 + 4);
    float4 ba = *(const float4*)(bet + lane * 8);
    float4 bb = *(const float4*)(bet + lane * 8 + 4);
    float g[8] = {ga.x, ga.y, ga.z, ga.w, gb.x, gb.y, gb.z, gb.w};
    float bt[8] = {ba.x, ba.y, ba.z, ba.w, bb.x, bb.y, bb.z, bb.w};
    f16 hv[8];
#pragma unroll
    for (int r = 0; r < 8; r++) {
        float y = (v[r] - mean) * inv * g[r] + bt[r];
        hv[r] = __float2half_rn(y);
    }
    size_t ob = (size_t)row * 256 + lane * 8;
    *(uint4*)(g_xnf + ob) = make_uint4(pk2(hv[0], hv[1]), pk2(hv[2], hv[3]),
                                       pk2(hv[4], hv[5]), pk2(hv[6], hv[7]));
}

// ---------------- launch ----------------
extern "C" void kernel_launch(void* const* d_in, const int* in_sizes, int n_in,
                              void* d_out, int out_size) {
    const float* s_in      = (const float*)d_in[0];
    const float* e_in      = (const float*)d_in[1];
    const float* dst_feat  = (const float*)d_in[2];
    const float* fc_w      = (const float*)d_in[3];
    const float* dstfeat_w = (const float*)d_in[4];
    const float* proj_w    = (const float*)d_in[5];
    const float* proj_b    = (const float*)d_in[6];
    const float* ln_g      = (const float*)d_in[7];
    const float* ln_b      = (const float*)d_in[8];
    const float* w1        = (const float*)d_in[9];
    const float* b1        = (const float*)d_in[10];
    const float* w2        = (const float*)d_in[11];
    const float* b2        = (const float*)d_in[12];
    const int*   edge_src  = (const int*)d_in[13];
    const int*   edge_dst  = (const int*)d_in[14];
    float* out = (float*)d_out;

    float *zp, *dfp, *xp;
    cudaGetSymbolAddress((void**)&zp,  g_z);
    cudaGetSymbolAddress((void**)&dfp, g_df);
    cudaGetSymbolAddress((void**)&xp,  g_x);
    bf16 *eh, *el, *fh, *fl, *wzh, *wzl, *wdh, *wdl;
    cudaGetSymbolAddress((void**)&eh,  g_eh);  cudaGetSymbolAddress((void**)&el,  g_el);
    cudaGetSymbolAddress((void**)&fh,  g_fh);  cudaGetSymbolAddress((void**)&fl,  g_fl);
    cudaGetSymbolAddress((void**)&wzh, g_wzh); cudaGetSymbolAddress((void**)&wzl, g_wzl);
    cudaGetSymbolAddress((void**)&wdh, g_wdh); cudaGetSymbolAddress((void**)&wdl, g_wdl);
    f16 *sf, *hf, *xnf, *tf, *pw, *w1p, *w2p;
    cudaGetSymbolAddress((void**)&sf,  g_sf);
    cudaGetSymbolAddress((void**)&hf,  g_hf);
    cudaGetSymbolAddress((void**)&xnf, g_xnf);
    cudaGetSymbolAddress((void**)&tf,  g_tf);
    cudaGetSymbolAddress((void**)&pw,  g_pw);
    cudaGetSymbolAddress((void**)&w1p, g_w1);
    cudaGetSymbolAddress((void**)&w2p, g_w2);

    cudaFuncSetAttribute(mma_gemm<bf16, 3, 2, 0, false, false, false>,
                         cudaFuncAttributeMaxDynamicSharedMemorySize, SMEM_BF3);
    cudaFuncSetAttribute(mma_gemm<f16, 1, 3, 0, true, false, false>,
                         cudaFuncAttributeMaxDynamicSharedMemorySize, SMEM_FP1);
    cudaFuncSetAttribute(mma_gemm<f16, 1, 3, 1, true, false, true>,
                         cudaFuncAttributeMaxDynamicSharedMemorySize, SMEM_FP1);
    cudaFuncSetAttribute(mma_gemm<f16, 1, 3, 0, true, true, false>,
                         cudaFuncAttributeMaxDynamicSharedMemorySize, SMEM_FP1);

    const int TB = 256;
    const int MB = (NS + 127) / 128;  // 782

    // ---- side stream for the independent CSR + conversion chain ----
    cudaStream_t s1;
    cudaStreamCreateWithFlags(&s1, cudaStreamNonBlocking);
    cudaEvent_t evFork, evJoin;
    cudaEventCreateWithFlags(&evFork, cudaEventDisableTiming);
    cudaEventCreateWithFlags(&evJoin, cudaEventDisableTiming);

    cudaEventRecord(evFork, 0);
    cudaStreamWaitEvent(s1, evFork, 0);

    // ---- main stream: conversions needed by z/df, then the two bf16 GEMMs ----
    act_split_bf<<<(NE * D / 4 + TB - 1) / TB, TB>>>(e_in, eh, el, NE * D);           // 0
    repack_split<<<(256 * 256 + TB - 1) / TB, TB>>>(fc_w, wzh, wzl, 256);             // 1
    act_split_bf<<<(NS * FEAT / 4 + TB - 1) / TB, TB>>>(dst_feat, fh, fl, NS * FEAT); // 2
    // 3: z = e @ Wz  [NE,256]  (bf16 3-pass, 2-stage) — ncu capture slot
    mma_gemm<bf16, 3, 2, 0, false, false, false><<<dim3(2, MB), TB, SMEM_BF3>>>(
        eh, el, 256, eh, el, 256, D, wzh, wzl, 256,
        nullptr, nullptr, 0, zp, nullptr, 256, NE, 256);
    repack_split<<<(64 * 256 + TB - 1) / TB, TB>>>(dstfeat_w, wdh, wdl, 64);          // 4
    // 5: df = dst_feat @ Wd  [NS,256]  (bf16 3-pass, 2-stage)
    mma_gemm<bf16, 3, 2, 0, false, false, false><<<dim3(2, MB), TB, SMEM_BF3>>>(
        fh, fl, 64, fh, fl, 64, FEAT, wdh, wdl, 64,
        nullptr, nullptr, 0, dfp, nullptr, 256, NS, 64);

    // ---- side stream: CSR build + post-softmax-path conversions (independent) ----
    zero_counts<<<(NS + TB - 1) / TB, TB, 0, s1>>>();
    hist_kernel<<<(EDG + TB - 1) / TB, TB, 0, s1>>>(edge_dst);
    scan_pass1<<<NBLK, SCAN_B, 0, s1>>>();
    scan_pass2<<<1, 128, 0, s1>>>();
    scan_pass3<<<NBLK, SCAN_B, 0, s1>>>();
    scatter_kernel<<<(EDG + TB - 1) / TB, TB, 0, s1>>>(edge_src, edge_dst);
    act_rn16<<<(NS * D / 4 + TB - 1) / TB, TB, 0, s1>>>(s_in, sf, NS * D);
    wsplit_t16<<<(512 * 256 + TB - 1) / TB, TB, 0, s1>>>(proj_w, pw, 512, 256);
    wsplit_t16<<<(256 * 512 + TB - 1) / TB, TB, 0, s1>>>(w1, w1p, 256, 512);
    wsplit_t16<<<(512 * 256 + TB - 1) / TB, TB, 0, s1>>>(w2, w2p, 512, 256);
    cudaEventRecord(evJoin, s1);

    cudaStreamWaitEvent(0, evJoin, 0);

    // attention + ELU -> h fp16 rn
    attn_kernel<<<(NS * 32 + TB - 1) / TB, TB>>>();

    // proj: [h | s] @ proj_w + b -> g_x (fp32)  (fp16 1-pass, 3-stage)
    mma_gemm<f16, 1, 3, 0, true, false, false><<<dim3(2, MB), TB, SMEM_FP1>>>(
        hf, nullptr, 256, sf, nullptr, 256, 256, pw, nullptr, 512,
        proj_b, nullptr, 0, xp, nullptr, 256, NS, 512);

    // layernorm -> xn fp16 rn
    ln_kernel<<<(NS * 32 + TB - 1) / TB, TB>>>(xp, ln_g, ln_b);

    // ffn1: gelu(xn @ w1 + b1) -> t fp16 rn  (fp16 1-pass, 3-stage)
    mma_gemm<f16, 1, 3, 1, true, false, true><<<dim3(4, MB), TB, SMEM_FP1>>>(
        xnf, nullptr, 256, xnf, nullptr, 256, 256, w1p, nullptr, 256,
        b1, nullptr, 0, nullptr, tf, 512, NS, 256);

    // ffn2: t @ w2 + b2 + g_x -> out (fp32)  (fp16 1-pass, 3-stage)
    mma_gemm<f16, 1, 3, 0, true, true, false><<<dim3(2, MB), TB, SMEM_FP1>>>(
        tf, nullptr, 512, tf, nullptr, 512, 512, w2p, nullptr, 512,
        b2, xp, 256, out, nullptr, 256, NS, 512);
}

// round 14
// speedup vs baseline: 1.9975x; 1.0320x over previous
#include <cuda_runtime.h>
#include <cuda_bf16.h>
#include <cuda_fp16.h>
#include <cstdint>
#include <math.h>

// Problem constants (fixed by the dataset)
#define NS 100000
#define NE 100000
#define EDG 1600000
#define D 256
#define H 8
#define HD 32
#define FEAT 64
#define DFF 512

#define SCAN_B 1024
#define NBLK ((NS + SCAN_B - 1) / SCAN_B)   // 98

// smem tile geometry: 32 elems of k per row, padded to 40 (80 B)
#define KP 40
#define ROWB 80
#define MATB (128 * ROWB)          // 10240 B per matrix
#define SMEM_BF3 (2 * 4 * MATB)    // 81920 B: bf16 3-pass, 2 stages (Ah,Al,Bh,Bl)
#define SMEM_FP1 (3 * 2 * MATB)    // 61440 B: fp16 1-pass, 3 stages (A,B)

typedef __nv_bfloat16 bf16;
typedef __half f16;

// ---------------- device scratch (no allocations allowed) ----------------
__device__ f16   g_zf[(size_t)NE * D];   // z in fp16 (gathered by attention)
__device__ float g_df[(size_t)NS * D];
__device__ float g_x[(size_t)NS * D];
// bf16 split (pre-softmax path)
__device__ bf16 g_eh[(size_t)NE * D],    g_el[(size_t)NE * D];
__device__ bf16 g_fh[(size_t)NS * FEAT], g_fl[(size_t)NS * FEAT];
__device__ bf16 g_wzh[256 * 256], g_wzl[256 * 256];
__device__ bf16 g_wdh[256 * 64],  g_wdl[256 * 64];
// fp16 rn (post-softmax path)
__device__ f16 g_sf[(size_t)NS * D];
__device__ f16 g_hf[(size_t)NS * D];
__device__ f16 g_xnf[(size_t)NS * D];
__device__ f16 g_tf[(size_t)NS * DFF];
// fp16 plain transposed weights Wt[n][k]
__device__ f16 g_pw[256 * 512];
__device__ f16 g_w1[512 * 256];
__device__ f16 g_w2[256 * 512];
// CSR
__device__ int g_counts[NS];
__device__ int g_offsets[NS + 1];
__device__ int g_cursor[NS];
__device__ int g_csr_src[EDG];
__device__ int g_bsum[NBLK];

// ---------------- small helpers ----------------
__device__ __forceinline__ float gelu_fast(float x) {
    const float c = 0.7978845608028654f;
    float u = c * (x + 0.044715f * x * x * x);
    float e = __expf(2.0f * u);
    float th = 1.0f - 2.0f / (e + 1.0f);
    return 0.5f * x * (1.0f + th);
}
__device__ __forceinline__ uint32_t smem_u32(const void* p) {
    uint32_t a;
    asm("{ .reg .u64 t; cvta.to.shared.u64 t, %1; cvt.u32.u64 %0, t; }" : "=r"(a) : "l"(p));
    return a;
}
__device__ __forceinline__ void ldm_x4(uint32_t* r, uint32_t addr) {
    asm volatile("ldmatrix.sync.aligned.m8n8.x4.shared.b16 {%0,%1,%2,%3}, [%4];"
                 : "=r"(r[0]), "=r"(r[1]), "=r"(r[2]), "=r"(r[3]) : "r"(addr));
}
__device__ __forceinline__ uint32_t pk2(bf16 a, bf16 b) {
    __nv_bfloat162 t(a, b); return *(uint32_t*)&t;
}
__device__ __forceinline__ uint32_t pk2(f16 a, f16 b) {
    __half2 t(a, b); return *(uint32_t*)&t;
}
__device__ __forceinline__ void split2(float x, bf16& hi, bf16& lo) {
    hi = __float2bfloat16_rn(x);
    lo = __float2bfloat16_rn(x - __bfloat162float(hi));
}
template <typename T>
__device__ __forceinline__ void mma_t(float* c, const uint32_t* a, const uint32_t* b);
template <>
__device__ __forceinline__ void mma_t<bf16>(float* c, const uint32_t* a, const uint32_t* b) {
    asm volatile(
        "mma.sync.aligned.m16n8k16.row.col.f32.bf16.bf16.f32 "
        "{%0,%1,%2,%3}, {%4,%5,%6,%7}, {%8,%9}, {%0,%1,%2,%3};"
        : "+f"(c[0]), "+f"(c[1]), "+f"(c[2]), "+f"(c[3])
        : "r"(a[0]), "r"(a[1]), "r"(a[2]), "r"(a[3]), "r"(b[0]), "r"(b[1]));
}
template <>
__device__ __forceinline__ void mma_t<f16>(float* c, const uint32_t* a, const uint32_t* b) {
    asm volatile(
        "mma.sync.aligned.m16n8k16.row.col.f32.f16.f16.f32 "
        "{%0,%1,%2,%3}, {%4,%5,%6,%7}, {%8,%9}, {%0,%1,%2,%3};"
        : "+f"(c[0]), "+f"(c[1]), "+f"(c[2]), "+f"(c[3])
        : "r"(a[0]), "r"(a[1]), "r"(a[2]), "r"(a[3]), "r"(b[0]), "r"(b[1]));
}
__device__ __forceinline__ void cpa16(uint32_t dst, const void* src, bool pred) {
    int sz = pred ? 16 : 0;
    asm volatile("cp.async.cg.shared.global [%0], [%1], 16, %2;"
                 :: "r"(dst), "l"(src), "r"(sz) : "memory");
}

// ---------------- conversion kernels ----------------
__global__ void act_split_bf(const float* __restrict__ in, bf16* __restrict__ hi,
                             bf16* __restrict__ lo, int n) {
    int i = 4 * (blockIdx.x * blockDim.x + threadIdx.x);
    if (i >= n) return;
    float4 v = *(const float4*)(in + i);
    bf16 h0, l0, h1, l1, h2, l2, h3, l3;
    split2(v.x, h0, l0); split2(v.y, h1, l1);
    split2(v.z, h2, l2); split2(v.w, h3, l3);
    *(uint2*)(hi + i) = make_uint2(pk2(h0, h1), pk2(h2, h3));
    *(uint2*)(lo + i) = make_uint2(pk2(l0, l1), pk2(l2, l3));
}
__global__ void act_rn16(const float* __restrict__ in, f16* __restrict__ o, int n) {
    int i = 4 * (blockIdx.x * blockDim.x + threadIdx.x);
    if (i >= n) return;
    float4 v = *(const float4*)(in + i);
    *(uint2*)(o + i) = make_uint2(pk2(__float2half_rn(v.x), __float2half_rn(v.y)),
                                  pk2(__float2half_rn(v.z), __float2half_rn(v.w)));
}
__global__ void wsplit_t16(const float* __restrict__ w, f16* __restrict__ o, int K, int N) {
    int idx = blockIdx.x * blockDim.x + threadIdx.x;
    if (idx >= K * N) return;
    int k = idx / N, n = idx % N;
    o[(size_t)n * K + k] = __float2half_rn(w[idx]);
}
__global__ void repack_split(const float* __restrict__ w, bf16* __restrict__ hi,
                             bf16* __restrict__ lo, int K) {
    int idx = blockIdx.x * blockDim.x + threadIdx.x;
    if (idx >= K * 256) return;
    int n = idx / K, k = idx % K;
    bf16 h, l;
    split2(w[(n >> 5) * (K * 32) + k * 32 + (n & 31)], h, l);
    hi[idx] = h;
    lo[idx] = l;
}

// ================= multistage cp.async GEMM =================
// PASSES==3 (bf16): Ah*Bh + Al*Bh + Ah*Bl (split operands).
// PASSES==1 (fp16): A*B plain rn.
template <typename T, int PASSES, int NSTAGE, int ACT, bool BIAS, bool RES, bool OHALF>
__global__ void __launch_bounds__(256, 2) mma_gemm(
    const T* __restrict__ Ah0, const T* __restrict__ Al0, int lda0,
    const T* __restrict__ Ah1, const T* __restrict__ Al1, int lda1, int ksplit,
    const T* __restrict__ Bh, const T* __restrict__ Bl, int ldbk,
    const float* __restrict__ bias,
    const float* __restrict__ res, int ldr,
    float* __restrict__ C, f16* __restrict__ Cf, int ldc,
    int M, int K)
{
    constexpr int NMAT = (PASSES == 3) ? 4 : 2;
    constexpr int STB = NMAT * MATB;
    constexpr int BOFF = (PASSES == 3) ? 2 * MATB : MATB;
    extern __shared__ char dsm[];
    uint32_t sb = smem_u32(dsm);

    int t = threadIdx.x;
    int lane = t & 31, wid = t >> 5;
    int m0 = blockIdx.y * 128;
    int n0 = blockIdx.x * 128;
    int wm = wid & 3;
    int wn = wid >> 2;

    float acc[2][8][4];
#pragma unroll
    for (int i = 0; i < 2; i++)
#pragma unroll
        for (int j = 0; j < 8; j++)
#pragma unroll
            for (int q = 0; q < 4; q++) acc[i][j][q] = 0.0f;

    uint32_t a_off = (uint32_t)(((wm * 32 + (lane & 15)) * KP + (lane >> 4) * 8) * 2);
    uint32_t b_off = (uint32_t)(((wn * 64 + (lane & 7) + (lane >> 4) * 8) * KP
                                 + ((lane >> 3) & 1) * 8) * 2);

    int p_row = t >> 1;
    int p_c0 = (t & 1) * 2;
    bool a_ok = (m0 + p_row) < M;
    const int KT = K >> 5;

    auto prefetch = [&](int kt) {
        if (kt < KT) {
            int k0 = kt * 32;
            int stage = kt % NSTAGE;
            const T *AhS, *AlS; int lda, koff;
            if (k0 < ksplit) { AhS = Ah0; AlS = Al0; lda = lda0; koff = k0; }
            else             { AhS = Ah1; AlS = Al1; lda = lda1; koff = k0 - ksplit; }
            const T* pah = AhS + (size_t)(m0 + p_row) * lda + koff;
            const T* pbh = Bh + (size_t)(n0 + p_row) * ldbk + k0;
            uint32_t base = sb + stage * STB + p_row * ROWB;
#pragma unroll
            for (int ci = 0; ci < 2; ci++) {
                int c = p_c0 + ci;
                cpa16(base + c * 16,        pah + c * 8, a_ok);
                cpa16(base + BOFF + c * 16, pbh + c * 8, true);
                if (PASSES == 3) {
                    const T* pal = AlS + (size_t)(m0 + p_row) * lda + koff;
                    const T* pbl = Bl + (size_t)(n0 + p_row) * ldbk + k0;
                    cpa16(base + MATB + c * 16,     pal + c * 8, a_ok);
                    cpa16(base + 3 * MATB + c * 16, pbl + c * 8, true);
                }
            }
        }
        asm volatile("cp.async.commit_group;" ::: "memory");
    };

#pragma unroll
    for (int s = 0; s < NSTAGE - 1; s++) prefetch(s);

    for (int kt = 0; kt < KT; kt++) {
        if (NSTAGE == 2) asm volatile("cp.async.wait_group 0;" ::: "memory");
        else             asm volatile("cp.async.wait_group 1;" ::: "memory");
        __syncthreads();

        prefetch(kt + NSTAGE - 1);

        uint32_t s0 = sb + (kt % NSTAGE) * STB;
        uint32_t sAh = s0, sBh = s0 + BOFF;

#pragma unroll
        for (int ks = 0; ks < 2; ks++) {
            uint32_t koffb = (uint32_t)(ks * 32);
            uint32_t a_hi[2][4], b[4][4];
            ldm_x4(a_hi[0], sAh + a_off + koffb);
            ldm_x4(a_hi[1], sAh + a_off + koffb + 16 * KP * 2);
#pragma unroll
            for (int ni2 = 0; ni2 < 4; ni2++)
                ldm_x4(b[ni2], sBh + b_off + koffb + ni2 * 16 * KP * 2);
            // pass 1: Ah * Bh
#pragma unroll
            for (int mi = 0; mi < 2; mi++)
#pragma unroll
                for (int ni = 0; ni < 8; ni++)
                    mma_t<T>(acc[mi][ni], a_hi[mi], &b[ni >> 1][(ni & 1) * 2]);
            if (PASSES == 3) {
                uint32_t sAl = s0 + MATB, sBl = s0 + 3 * MATB;
                uint32_t a_lo[2][4];
                ldm_x4(a_lo[0], sAl + a_off + koffb);
                ldm_x4(a_lo[1], sAl + a_off + koffb + 16 * KP * 2);
                // pass 2: Al * Bh
#pragma unroll
                for (int mi = 0; mi < 2; mi++)
#pragma unroll
                    for (int ni = 0; ni < 8; ni++)
                        mma_t<T>(acc[mi][ni], a_lo[mi], &b[ni >> 1][(ni & 1) * 2]);
                // pass 3: Ah * Bl
#pragma unroll
                for (int ni2 = 0; ni2 < 4; ni2++)
                    ldm_x4(b[ni2], sBl + b_off + koffb + ni2 * 16 * KP * 2);
#pragma unroll
                for (int mi = 0; mi < 2; mi++)
#pragma unroll
                    for (int ni = 0; ni < 8; ni++)
                        mma_t<T>(acc[mi][ni], a_hi[mi], &b[ni >> 1][(ni & 1) * 2]);
            }
        }
    }

    // ---- epilogue ----
#pragma unroll
    for (int mi = 0; mi < 2; mi++) {
#pragma unroll
        for (int ni = 0; ni < 8; ni++) {
            int cc = n0 + wn * 64 + ni * 8 + (lane & 3) * 2;
#pragma unroll
            for (int hh = 0; hh < 2; hh++) {
                int m = m0 + wm * 32 + mi * 16 + (lane >> 2) + hh * 8;
                if (m >= M) continue;
                float v0 = acc[mi][ni][hh * 2 + 0];
                float v1 = acc[mi][ni][hh * 2 + 1];
                if (BIAS) { v0 += bias[cc]; v1 += bias[cc + 1]; }
                if (ACT == 1) { v0 = gelu_fast(v0); v1 = gelu_fast(v1); }
                if (RES) {
                    const float* rp = res + (size_t)m * ldr + cc;
                    v0 += rp[0]; v1 += rp[1];
                }
                if (OHALF) {
                    *(uint32_t*)(Cf + (size_t)m * ldc + cc) =
                        pk2(__float2half_rn(v0), __float2half_rn(v1));
                } else {
                    *(float2*)(C + (size_t)m * ldc + cc) = make_float2(v0, v1);
                }
            }
        }
    }
}

// ---------------- CSR build ----------------
__global__ void zero_counts() {
    int i = blockIdx.x * blockDim.x + threadIdx.x;
    if (i < NS) g_counts[i] = 0;
}
__global__ void hist_kernel(const int* __restrict__ edge_dst) {
    int i = blockIdx.x * blockDim.x + threadIdx.x;
    if (i < EDG) atomicAdd(&g_counts[edge_dst[i]], 1);
}
__global__ void __launch_bounds__(SCAN_B) scan_pass1() {
    __shared__ int ws[32];
    int b = blockIdx.x, t = threadIdx.x;
    int i = b * SCAN_B + t;
    int v = (i < NS) ? g_counts[i] : 0;
#pragma unroll
    for (int o = 16; o; o >>= 1) v += __shfl_xor_sync(0xFFFFFFFFu, v, o);
    if ((t & 31) == 0) ws[t >> 5] = v;
    __syncthreads();
    if (t < 32) {
        int x = ws[t];
#pragma unroll
        for (int o = 16; o; o >>= 1) x += __shfl_xor_sync(0xFFFFFFFFu, x, o);
        if (t == 0) g_bsum[b] = x;
    }
}
__global__ void scan_pass2() {
    __shared__ int sh[128];
    int t = threadIdx.x;
    int orig = (t < NBLK) ? g_bsum[t] : 0;
    sh[t] = orig;
    __syncthreads();
    for (int o = 1; o < 128; o <<= 1) {
        int v = (t >= o) ? sh[t - o] : 0;
        __syncthreads();
        sh[t] += v;
        __syncthreads();
    }
    if (t < NBLK) g_bsum[t] = sh[t] - orig;
}
__global__ void __launch_bounds__(SCAN_B) scan_pass3() {
    __shared__ int ws[32];
    int b = blockIdx.x, t = threadIdx.x;
    int lane = t & 31, w = t >> 5;
    int i = b * SCAN_B + t;
    int v = (i < NS) ? g_counts[i] : 0;
    int x = v;
#pragma unroll
    for (int o = 1; o < 32; o <<= 1) {
        int y = __shfl_up_sync(0xFFFFFFFFu, x, o);
        if (lane >= o) x += y;
    }
    if (lane == 31) ws[w] = x;
    __syncthreads();
    if (w == 0) {
        int sv = ws[lane];
#pragma unroll
        for (int o = 1; o < 32; o <<= 1) {
            int y = __shfl_up_sync(0xFFFFFFFFu, sv, o);
            if (lane >= o) sv += y;
        }
        ws[lane] = sv;
    }
    __syncthreads();
    int incl = x + (w > 0 ? ws[w - 1] : 0) + g_bsum[b];
    if (i < NS) {
        g_offsets[i + 1] = incl;
        g_cursor[i] = incl - v;
    }
    if (b == 0 && t == 0) g_offsets[0] = 0;
}
__global__ void scatter_kernel(const int* __restrict__ edge_src,
                               const int* __restrict__ edge_dst) {
    int i = blockIdx.x * blockDim.x + threadIdx.x;
    if (i >= EDG) return;
    int dst = edge_dst[i];
    int pos = atomicAdd(&g_cursor[dst], 1);
    g_csr_src[pos] = edge_src[i];
}

// ---------------- attention: warp per dst, lane = (head, quarter) ----------------
// z gathered in fp16 (16B per lane per edge); scores/softmax/accumulate in fp32.
__global__ void __launch_bounds__(256) attn_kernel() {
    int gw = (blockIdx.x * blockDim.x + threadIdx.x) >> 5;
    if (gw >= NS) return;
    int lane = threadIdx.x & 31;
    int off = (lane >> 2) * 32 + (lane & 3) * 8;

    int beg = g_offsets[gw];
    int end = g_offsets[gw + 1];

    const float* dfp = g_df + (size_t)gw * 256 + off;
    float4 d0 = *(const float4*)(dfp);
    float4 d1 = *(const float4*)(dfp + 4);

    float m = -1e30f, den = 0.0f;
    float4 a0 = make_float4(0.f, 0.f, 0.f, 0.f);
    float4 a1 = make_float4(0.f, 0.f, 0.f, 0.f);

    int e = beg;
    for (; e + 2 <= end; e += 2) {
        int s0 = __ldg(&g_csr_src[e]);
        int s1 = __ldg(&g_csr_src[e + 1]);
        uint4 rx = __ldg((const uint4*)(g_zf + (size_t)s0 * 256 + off));
        uint4 ry = __ldg((const uint4*)(g_zf + (size_t)s1 * 256 + off));
        const __half2* hx = (const __half2*)&rx;
        const __half2* hy = (const __half2*)&ry;
        float2 xa = __half22float2(hx[0]), xb = __half22float2(hx[1]);
        float2 xc = __half22float2(hx[2]), xd = __half22float2(hx[3]);
        float2 ya = __half22float2(hy[0]), yb = __half22float2(hy[1]);
        float2 yc = __half22float2(hy[2]), yd = __half22float2(hy[3]);
        float4 x0 = make_float4(xa.x, xa.y, xb.x, xb.y);
        float4 x1 = make_float4(xc.x, xc.y, xd.x, xd.y);
        float4 y0 = make_float4(ya.x, ya.y, yb.x, yb.y);
        float4 y1 = make_float4(yc.x, yc.y, yd.x, yd.y);

        float sa = x0.x * d0.x + x0.y * d0.y + x0.z * d0.z + x0.w * d0.w
                 + x1.x * d1.x + x1.y * d1.y + x1.z * d1.z + x1.w * d1.w;
        float sb = y0.x * d0.x + y0.y * d0.y + y0.z * d0.z + y0.w * d0.w
                 + y1.x * d1.x + y1.y * d1.y + y1.z * d1.z + y1.w * d1.w;
        sa += __shfl_xor_sync(0xFFFFFFFFu, sa, 1);
        sb += __shfl_xor_sync(0xFFFFFFFFu, sb, 1);
        sa += __shfl_xor_sync(0xFFFFFFFFu, sa, 2);
        sb += __shfl_xor_sync(0xFFFFFFFFu, sb, 2);

        {
            float mn = fmaxf(m, sa);
            float sc = __expf(m - mn);
            float w  = __expf(sa - mn);
            den = den * sc + w;
            a0.x = a0.x * sc + w * x0.x; a0.y = a0.y * sc + w * x0.y;
            a0.z = a0.z * sc + w * x0.z; a0.w = a0.w * sc + w * x0.w;
            a1.x = a1.x * sc + w * x1.x; a1.y = a1.y * sc + w * x1.y;
            a1.z = a1.z * sc + w * x1.z; a1.w = a1.w * sc + w * x1.w;
            m = mn;
        }
        {
            float mn = fmaxf(m, sb);
            float sc = __expf(m - mn);
            float w  = __expf(sb - mn);
            den = den * sc + w;
            a0.x = a0.x * sc + w * y0.x; a0.y = a0.y * sc + w * y0.y;
            a0.z = a0.z * sc + w * y0.z; a0.w = a0.w * sc + w * y0.w;
            a1.x = a1.x * sc + w * y1.x; a1.y = a1.y * sc + w * y1.y;
            a1.z = a1.z * sc + w * y1.z; a1.w = a1.w * sc + w * y1.w;
            m = mn;
        }
    }
    for (; e < end; e++) {
        int s0 = __ldg(&g_csr_src[e]);
        uint4 rx = __ldg((const uint4*)(g_zf + (size_t)s0 * 256 + off));
        const __half2* hx = (const __half2*)&rx;
        float2 xa = __half22float2(hx[0]), xb = __half22float2(hx[1]);
        float2 xc = __half22float2(hx[2]), xd = __half22float2(hx[3]);
        float4 x0 = make_float4(xa.x, xa.y, xb.x, xb.y);
        float4 x1 = make_float4(xc.x, xc.y, xd.x, xd.y);
        float sa = x0.x * d0.x + x0.y * d0.y + x0.z * d0.z + x0.w * d0.w
                 + x1.x * d1.x + x1.y * d1.y + x1.z * d1.z + x1.w * d1.w;
        sa += __shfl_xor_sync(0xFFFFFFFFu, sa, 1);
        sa += __shfl_xor_sync(0xFFFFFFFFu, sa, 2);
        float mn = fmaxf(m, sa);
        float sc = __expf(m - mn);
        float w  = __expf(sa - mn);
        den = den * sc + w;
        a0.x = a0.x * sc + w * x0.x; a0.y = a0.y * sc + w * x0.y;
        a0.z = a0.z * sc + w * x0.z; a0.w = a0.w * sc + w * x0.w;
        a1.x = a1.x * sc + w * x1.x; a1.y = a1.y * sc + w * x1.y;
        a1.z = a1.z * sc + w * x1.z; a1.w = a1.w * sc + w * x1.w;
        m = mn;
    }

    float inv = 1.0f / den;
    float v[8];
    v[0] = a0.x * inv; v[1] = a0.y * inv; v[2] = a0.z * inv; v[3] = a0.w * inv;
    v[4] = a1.x * inv; v[5] = a1.y * inv; v[6] = a1.z * inv; v[7] = a1.w * inv;
    f16 hv[8];
#pragma unroll
    for (int i = 0; i < 8; i++) {
        v[i] = (v[i] > 0.0f) ? v[i] : expm1f(v[i]);  // ELU(alpha=1)
        hv[i] = __float2half_rn(v[i]);
    }
    size_t ob = (size_t)gw * 256 + off;
    *(uint4*)(g_hf + ob) = make_uint4(pk2(hv[0], hv[1]), pk2(hv[2], hv[3]),
                                      pk2(hv[4], hv[5]), pk2(hv[6], hv[7]));
}

// ---------------- layernorm: warp per row, lane owns 8 contiguous cols ----------------
__global__ void ln_kernel(const float* __restrict__ x,
                          const float* __restrict__ gam,
                          const float* __restrict__ bet) {
    int row = (blockIdx.x * blockDim.x + threadIdx.x) >> 5;
    if (row >= NS) return;
    int lane = threadIdx.x & 31;
    const float* xp = x + (size_t)row * 256 + lane * 8;
    float4 va = *(const float4*)xp;
    float4 vb = *(const float4*)(xp + 4);
    float v[8] = {va.x, va.y, va.z, va.w, vb.x, vb.y, vb.z, vb.w};
    float s = 0.0f, s2 = 0.0f;
#pragma unroll
    for (int r = 0; r < 8; r++) { s += v[r]; s2 += v[r] * v[r]; }
#pragma unroll
    for (int o = 16; o > 0; o >>= 1) {
        s  += __shfl_xor_sync(0xFFFFFFFFu, s, o);
        s2 += __shfl_xor_sync(0xFFFFFFFFu, s2, o);
    }
    float mean = s * (1.0f / 256.0f);
    float var = s2 * (1.0f / 256.0f) - mean * mean;
    float inv = rsqrtf(var + 1e-6f);
    float4 ga = *(const float4*)(gam + lane * 8);
    float4 gb = *(const float4*)(gam + lane * 8 + 4);
    float4 ba = *(const float4*)(bet + lane * 8);
    float4 bb = *(const float4*)(bet + lane * 8 + 4);
    float g[8] = {ga.x, ga.y, ga.z, ga.w, gb.x, gb.y, gb.z, gb.w};
    float bt[8] = {ba.x, ba.y, ba.z, ba.w, bb.x, bb.y, bb.z, bb.w};
    f16 hv[8];
#pragma unroll
    for (int r = 0; r < 8; r++) {
        float y = (v[r] - mean) * inv * g[r] + bt[r];
        hv[r] = __float2half_rn(y);
    }
    size_t ob = (size_t)row * 256 + lane * 8;
    *(uint4*)(g_xnf + ob) = make_uint4(pk2(hv[0], hv[1]), pk2(hv[2], hv[3]),
                                       pk2(hv[4], hv[5]), pk2(hv[6], hv[7]));
}

// ---------------- launch ----------------
extern "C" void kernel_launch(void* const* d_in, const int* in_sizes, int n_in,
                              void* d_out, int out_size) {
    const float* s_in      = (const float*)d_in[0];
    const float* e_in      = (const float*)d_in[1];
    const float* dst_feat  = (const float*)d_in[2];
    const float* fc_w      = (const float*)d_in[3];
    const float* dstfeat_w = (const float*)d_in[4];
    const float* proj_w    = (const float*)d_in[5];
    const float* proj_b    = (const float*)d_in[6];
    const float* ln_g      = (const float*)d_in[7];
    const float* ln_b      = (const float*)d_in[8];
    const float* w1        = (const float*)d_in[9];
    const float* b1        = (const float*)d_in[10];
    const float* w2        = (const float*)d_in[11];
    const float* b2        = (const float*)d_in[12];
    const int*   edge_src  = (const int*)d_in[13];
    const int*   edge_dst  = (const int*)d_in[14];
    float* out = (float*)d_out;

    float *dfp, *xp;
    cudaGetSymbolAddress((void**)&dfp, g_df);
    cudaGetSymbolAddress((void**)&xp,  g_x);
    bf16 *eh, *el, *fh, *fl, *wzh, *wzl, *wdh, *wdl;
    cudaGetSymbolAddress((void**)&eh,  g_eh);  cudaGetSymbolAddress((void**)&el,  g_el);
    cudaGetSymbolAddress((void**)&fh,  g_fh);  cudaGetSymbolAddress((void**)&fl,  g_fl);
    cudaGetSymbolAddress((void**)&wzh, g_wzh); cudaGetSymbolAddress((void**)&wzl, g_wzl);
    cudaGetSymbolAddress((void**)&wdh, g_wdh); cudaGetSymbolAddress((void**)&wdl, g_wdl);
    f16 *zf, *sf, *hf, *xnf, *tf, *pw, *w1p, *w2p;
    cudaGetSymbolAddress((void**)&zf,  g_zf);
    cudaGetSymbolAddress((void**)&sf,  g_sf);
    cudaGetSymbolAddress((void**)&hf,  g_hf);
    cudaGetSymbolAddress((void**)&xnf, g_xnf);
    cudaGetSymbolAddress((void**)&tf,  g_tf);
    cudaGetSymbolAddress((void**)&pw,  g_pw);
    cudaGetSymbolAddress((void**)&w1p, g_w1);
    cudaGetSymbolAddress((void**)&w2p, g_w2);

    cudaFuncSetAttribute(mma_gemm<bf16, 3, 2, 0, false, false, true>,
                         cudaFuncAttributeMaxDynamicSharedMemorySize, SMEM_BF3);
    cudaFuncSetAttribute(mma_gemm<bf16, 3, 2, 0, false, false, false>,
                         cudaFuncAttributeMaxDynamicSharedMemorySize, SMEM_BF3);
    cudaFuncSetAttribute(mma_gemm<f16, 1, 3, 0, true, false, false>,
                         cudaFuncAttributeMaxDynamicSharedMemorySize, SMEM_FP1);
    cudaFuncSetAttribute(mma_gemm<f16, 1, 3, 1, true, false, true>,
                         cudaFuncAttributeMaxDynamicSharedMemorySize, SMEM_FP1);
    cudaFuncSetAttribute(mma_gemm<f16, 1, 3, 0, true, true, false>,
                         cudaFuncAttributeMaxDynamicSharedMemorySize, SMEM_FP1);

    const int TB = 256;
    const int MB = (NS + 127) / 128;  // 782

    // ---- side stream for the independent CSR + conversion chain ----
    cudaStream_t s1;
    cudaStreamCreateWithFlags(&s1, cudaStreamNonBlocking);
    cudaEvent_t evFork, evJoin;
    cudaEventCreateWithFlags(&evFork, cudaEventDisableTiming);
    cudaEventCreateWithFlags(&evJoin, cudaEventDisableTiming);

    cudaEventRecord(evFork, 0);
    cudaStreamWaitEvent(s1, evFork, 0);

    // ---- main stream: conversions needed by z/df, then the two bf16 GEMMs ----
    act_split_bf<<<(NE * D / 4 + TB - 1) / TB, TB>>>(e_in, eh, el, NE * D);           // 0
    repack_split<<<(256 * 256 + TB - 1) / TB, TB>>>(fc_w, wzh, wzl, 256);             // 1
    act_split_bf<<<(NS * FEAT / 4 + TB - 1) / TB, TB>>>(dst_feat, fh, fl, NS * FEAT); // 2
    // 3: z = e @ Wz  [NE,256] -> fp16 (bf16 3-pass, 2-stage) — ncu capture slot
    mma_gemm<bf16, 3, 2, 0, false, false, true><<<dim3(2, MB), TB, SMEM_BF3>>>(
        eh, el, 256, eh, el, 256, D, wzh, wzl, 256,
        nullptr, nullptr, 0, nullptr, zf, 256, NE, 256);
    repack_split<<<(64 * 256 + TB - 1) / TB, TB>>>(dstfeat_w, wdh, wdl, 64);          // 4
    // 5: df = dst_feat @ Wd  [NS,256] (fp32; bf16 3-pass, 2-stage)
    mma_gemm<bf16, 3, 2, 0, false, false, false><<<dim3(2, MB), TB, SMEM_BF3>>>(
        fh, fl, 64, fh, fl, 64, FEAT, wdh, wdl, 64,
        nullptr, nullptr, 0, dfp, nullptr, 256, NS, 64);

    // ---- side stream: CSR build + post-softmax-path conversions (independent) ----
    zero_counts<<<(NS + TB - 1) / TB, TB, 0, s1>>>();
    hist_kernel<<<(EDG + TB - 1) / TB, TB, 0, s1>>>(edge_dst);
    scan_pass1<<<NBLK, SCAN_B, 0, s1>>>();
    scan_pass2<<<1, 128, 0, s1>>>();
    scan_pass3<<<NBLK, SCAN_B, 0, s1>>>();
    scatter_kernel<<<(EDG + TB - 1) / TB, TB, 0, s1>>>(edge_src, edge_dst);
    act_rn16<<<(NS * D / 4 + TB - 1) / TB, TB, 0, s1>>>(s_in, sf, NS * D);
    wsplit_t16<<<(512 * 256 + TB - 1) / TB, TB, 0, s1>>>(proj_w, pw, 512, 256);
    wsplit_t16<<<(256 * 512 + TB - 1) / TB, TB, 0, s1>>>(w1, w1p, 256, 512);
    wsplit_t16<<<(512 * 256 + TB - 1) / TB, TB, 0, s1>>>(w2, w2p, 512, 256);
    cudaEventRecord(evJoin, s1);

    cudaStreamWaitEvent(0, evJoin, 0);

    // attention + ELU -> h fp16 rn
    attn_kernel<<<(NS * 32 + TB - 1) / TB, TB>>>();

    // proj: [h | s] @ proj_w + b -> g_x (fp32)  (fp16 1-pass, 3-stage)
    mma_gemm<f16, 1, 3, 0, true, false, false><<<dim3(2, MB), TB, SMEM_FP1>>>(
        hf, nullptr, 256, sf, nullptr, 256, 256, pw, nullptr, 512,
        proj_b, nullptr, 0, xp, nullptr, 256, NS, 512);

    // layernorm -> xn fp16 rn
    ln_kernel<<<(NS * 32 + TB - 1) / TB, TB>>>(xp, ln_g, ln_b);

    // ffn1: gelu(xn @ w1 + b1) -> t fp16 rn  (fp16 1-pass, 3-stage)
    mma_gemm<f16, 1, 3, 1, true, false, true><<<dim3(4, MB), TB, SMEM_FP1>>>(
        xnf, nullptr, 256, xnf, nullptr, 256, 256, w1p, nullptr, 256,
        b1, nullptr, 0, nullptr, tf, 512, NS, 256);

    // ffn2: t @ w2 + b2 + g_x -> out (fp32)  (fp16 1-pass, 3-stage)
    mma_gemm<f16, 1, 3, 0, true, true, false><<<dim3(2, MB), TB, SMEM_FP1>>>(
        tf, nullptr, 512, tf, nullptr, 512, 512, w2p, nullptr, 512,
        b2, xp, 256, out, nullptr, 256, NS, 512);
}